// round 4
// baseline (speedup 1.0000x reference)
#include <cuda_runtime.h>
#include <math.h>
#include <stdint.h>

#define NQ 75
#define NS 25
#define NU 64
#define NALL 164
#define H1 84
#define H2 42
#define H3 21
#define PP 441
#define PPAD 512
#define KCLS 5
#define SHOT 5
#define MSUP (SHOT*PP)          // 2205
#define MAUG (MSUP + 10*PP)     // 6615
#define BCOLS 6656              // padded bank cols (52*128)
#define SELN 10
#define NEGINF -3.4e38f

__device__ float g_bufA[(size_t)NALL*64*H1*H1];
__device__ float g_bufC[(size_t)NALL*64*H2*H2];
__device__ float g_bufD[(size_t)NALL*64*H3*H3];
__device__ float g_bufE[(size_t)NALL*64*H3*H3];
__device__ float g_bufB[(size_t)NALL*64*H2*H2];
__device__ float g_rinv[(size_t)NALL*PP];
__device__ float g_ndescT[(size_t)NALL*64*PPAD];   // [img][k][p] padded, tail zero
__device__ float g_bankT[(size_t)KCLS*64*BCOLS];   // [cls][k][col]
__device__ float g_stats[3*64*2];
__device__ float g_partU[NU*KCLS*4];
__device__ float g_partQ[NQ*KCLS*4];
__device__ float g_simu[NU*KCLS];
__device__ int   g_selidx[KCLS*SELN];

__device__ __forceinline__ float* bufPtr(int s){
    switch(s){
        case 0: return g_bufA; case 1: return g_bufB; case 2: return g_bufC;
        case 3: return g_bufD; default: return g_bufE;
    }
}
__device__ __forceinline__ int groupOf(int n){ return (n < NQ) ? 0 : ((n < NQ+NS) ? 1 : 2); }

__device__ __forceinline__ void cpasync16(uint32_t dst, const void* src){
    asm volatile("cp.async.cg.shared.global [%0], [%1], 16;\n" :: "r"(dst), "l"(src));
}
#define CP_COMMIT() asm volatile("cp.async.commit_group;\n" ::: "memory")
#define CP_WAIT0()  asm volatile("cp.async.wait_group 0;\n" ::: "memory")

// ---------- conv1: 3->64, 84x84 SAME ----------
__global__ void conv1_kernel(const float* __restrict__ in1, const float* __restrict__ in2,
                             const float* __restrict__ in3, const float* __restrict__ w)
{
    __shared__ float sW[64*27];
    __shared__ float sIn[3*18*18];
    const int n = blockIdx.z;
    const int gx0 = blockIdx.x*16, gy0 = blockIdx.y*16;
    const int tx = threadIdx.x, ty = threadIdx.y;
    const int tid = ty*16 + tx;
    const float* img = (n < NQ)    ? (in1 + (size_t)n*3*H1*H1)
                     : (n < NQ+NS) ? (in2 + (size_t)(n-NQ)*3*H1*H1)
                                   : (in3 + (size_t)(n-NQ-NS)*3*H1*H1);
    for (int i = tid; i < 64*27; i += 256) sW[i] = w[i];
    for (int i = tid; i < 3*18*18; i += 256) {
        int c = i / 324, rem = i % 324, r = rem/18, cc = rem%18;
        int gy = gy0 - 1 + r, gx = gx0 - 1 + cc;
        sIn[i] = (gy>=0 && gy<H1 && gx>=0 && gx<H1) ? img[((size_t)c*H1+gy)*H1+gx] : 0.f;
    }
    __syncthreads();
    int ox = gx0+tx, oy = gy0+ty;
    if (ox >= H1 || oy >= H1) return;
    float v[27];
#pragma unroll
    for (int c=0;c<3;c++)
#pragma unroll
      for (int dy=0;dy<3;dy++)
#pragma unroll
        for (int dx=0;dx<3;dx++)
          v[c*9+dy*3+dx] = sIn[c*324 + (ty+dy)*18 + (tx+dx)];
#pragma unroll 4
    for (int oc=0; oc<64; oc++){
        float acc = 0.f;
        const float* wp = sW + oc*27;
#pragma unroll
        for (int j=0;j<27;j++) acc += wp[j]*v[j];
        g_bufA[(((size_t)n*64+oc)*H1+oy)*H1+ox] = acc;
    }
}

// ---------- conv 64->64 3x3 SAME ----------
template<int RPT>
__global__ void conv64_kernel(int inSel, int outSel, const float* __restrict__ wt, int H, int W)
{
    extern __shared__ float sm[];
    float* sW  = sm;
    float* sIn = sm + 36864;
    constexpr int TH   = 16*RPT;
    constexpr int HALO = (TH+2)*18;
    const int n   = blockIdx.z;
    const int gx0 = blockIdx.x*16;
    const int gy0 = blockIdx.y*TH;
    const int tx = threadIdx.x, ty = threadIdx.y;
    const int tid = ty*16 + tx;
    for (int i = tid; i < 64*64*9; i += 256) sW[i] = wt[i];
    const int oyb = gy0 + ty*RPT;
    const int ox  = gx0 + tx;
    const bool anyValid = (ox < W) && (oyb < H);
    const float* inN  = bufPtr(inSel)  + (size_t)n*64*H*W;
    float*       outN = bufPtr(outSel) + (size_t)n*64*H*W;

    for (int ocg = 0; ocg < 4; ++ocg) {
        float acc[16][RPT];
#pragma unroll
        for (int o=0;o<16;o++)
#pragma unroll
          for (int r=0;r<RPT;r++) acc[o][r]=0.f;
        for (int cc = 0; cc < 4; ++cc) {
            __syncthreads();
            for (int i = tid; i < 16*HALO; i += 256) {
                int c = i / HALO, rem = i % HALO, r = rem/18, col = rem%18;
                int gy = gy0-1+r, gx = gx0-1+col;
                float v = 0.f;
                if (gy>=0 && gy<H && gx>=0 && gx<W)
                    v = inN[((size_t)(cc*16+c)*H+gy)*W+gx];
                sIn[i] = v;
            }
            __syncthreads();
            if (anyValid) {
                for (int ic=0; ic<16; ++ic) {
                    float v[RPT+2][3];
                    const float* sp = sIn + ic*HALO + (ty*RPT)*18 + tx;
#pragma unroll
                    for (int r=0;r<RPT+2;r++)
#pragma unroll
                      for (int d=0;d<3;d++) v[r][d] = sp[r*18+d];
                    const float* wp = sW + (size_t)(ocg*16)*576 + (cc*16+ic)*9;
#pragma unroll
                    for (int o=0;o<16;o++){
                        const float* wo = wp + o*576;
                        float w0=wo[0],w1=wo[1],w2=wo[2],w3=wo[3],w4=wo[4];
                        float w5=wo[5],w6=wo[6],w7=wo[7],w8=wo[8];
#pragma unroll
                        for (int r=0;r<RPT;r++){
                            float a = acc[o][r];
                            a += w0*v[r  ][0]; a += w1*v[r  ][1]; a += w2*v[r  ][2];
                            a += w3*v[r+1][0]; a += w4*v[r+1][1]; a += w5*v[r+1][2];
                            a += w6*v[r+2][0]; a += w7*v[r+2][1]; a += w8*v[r+2][2];
                            acc[o][r] = a;
                        }
                    }
                }
            }
        }
        if (anyValid) {
#pragma unroll
            for (int o=0;o<16;o++){
                int oc = ocg*16+o;
#pragma unroll
                for (int r=0;r<RPT;r++){
                    int oy = oyb + r;
                    if (oy < H) outN[((size_t)oc*H+oy)*W+ox] = acc[o][r];
                }
            }
        }
    }
}

// ---------- BN stats ----------
__global__ void bn_stats_kernel(int sel, int HW)
{
    __shared__ double ssum[256], ssum2[256];
    const int ch = blockIdx.x, g = blockIdx.y;
    const int n0 = (g==0)?0:((g==1)?NQ:(NQ+NS));
    const int n1 = (g==0)?NQ:((g==1)?(NQ+NS):NALL);
    const int tid = threadIdx.x;
    const float* buf = bufPtr(sel);
    double s=0.0, s2=0.0;
    for (int n=n0; n<n1; ++n) {
        const float* p = buf + ((size_t)n*64+ch)*HW;
        for (int i=tid;i<HW;i+=256){ double x = (double)p[i]; s+=x; s2+=x*x; }
    }
    ssum[tid]=s; ssum2[tid]=s2; __syncthreads();
    for (int st=128; st>0; st>>=1){
        if (tid<st){ ssum[tid]+=ssum[tid+st]; ssum2[tid]+=ssum2[tid+st]; }
        __syncthreads();
    }
    if (tid==0){
        double cnt = (double)(n1-n0)*HW;
        double mean = ssum[0]/cnt;
        double var  = ssum2[0]/cnt - mean*mean;
        g_stats[(g*64+ch)*2+0] = (float)mean;
        g_stats[(g*64+ch)*2+1] = (float)(1.0/sqrt(var + 1e-5));
    }
}

// ---------- BN + LeakyReLU (+pool) ----------
__global__ void bn_pool_kernel(int inSel, int outSel, const float* __restrict__ gamma,
                               const float* __restrict__ beta, int H, int W, int doPool)
{
    const int oH = doPool ? H/2 : H, oW = doPool ? W/2 : W;
    const size_t total = (size_t)NALL*64*oH*oW;
    const float* in = bufPtr(inSel);
    float* out = bufPtr(outSel);
    for (size_t idx = (size_t)blockIdx.x*blockDim.x + threadIdx.x; idx < total;
         idx += (size_t)gridDim.x*blockDim.x) {
        int ox = (int)(idx % oW); size_t t = idx / oW;
        int oy = (int)(t % oH);   t /= oH;
        int c  = (int)(t % 64);   int n = (int)(t / 64);
        int g = groupOf(n);
        float mean = g_stats[(g*64+c)*2+0], rsig = g_stats[(g*64+c)*2+1];
        float sc = gamma[c]*rsig;
        float sh = beta[c] - mean*sc;
        const float* p = in + ((size_t)n*64+c)*H*W;
        float r;
        if (doPool){
            float x0 = p[(size_t)(2*oy)*W + 2*ox  ]*sc+sh;
            float x1 = p[(size_t)(2*oy)*W + 2*ox+1]*sc+sh;
            float x2 = p[(size_t)(2*oy+1)*W + 2*ox  ]*sc+sh;
            float x3 = p[(size_t)(2*oy+1)*W + 2*ox+1]*sc+sh;
            x0 = x0>=0.f?x0:0.2f*x0; x1 = x1>=0.f?x1:0.2f*x1;
            x2 = x2>=0.f?x2:0.2f*x2; x3 = x3>=0.f?x3:0.2f*x3;
            r = fmaxf(fmaxf(x0,x1), fmaxf(x2,x3));
        } else {
            float x = p[(size_t)oy*W+ox]*sc+sh;
            r = x>=0.f?x:0.2f*x;
        }
        out[idx] = r;
    }
}

// ---------- descriptor norms ----------
__global__ void norm_kernel()
{
    int img = blockIdx.x;
    for (int p = threadIdx.x; p < PP; p += blockDim.x){
        float ss = 0.f;
        const float* f = g_bufD + (size_t)img*64*PP + p;
#pragma unroll
        for (int c=0;c<64;c++){ float x = f[(size_t)c*PP]; ss += x*x; }
        g_rinv[(size_t)img*PP + p] = rsqrtf(ss);
    }
}

// ---------- normalized transposed descriptors [img][k][p] (p padded to 512) ----------
__global__ void ndescT_kernel()
{
    const size_t total = (size_t)NALL*64*PPAD;
    for (size_t idx = (size_t)blockIdx.x*blockDim.x + threadIdx.x; idx < total;
         idx += (size_t)gridDim.x*blockDim.x) {
        int p = (int)(idx % PPAD); size_t t = idx / PPAD;
        int c = (int)(t % 64); int img = (int)(t / 64);
        float v = 0.f;
        if (p < PP)
            v = g_bufD[((size_t)img*64+c)*PP + p] * g_rinv[(size_t)img*PP + p];
        g_ndescT[idx] = v;
    }
}

// ---------- bank fills (transposed) ----------
__global__ void fillT_support_kernel()
{
    const size_t total = (size_t)KCLS*64*MSUP;
    for (size_t i = (size_t)blockIdx.x*blockDim.x + threadIdx.x; i < total;
         i += (size_t)gridDim.x*blockDim.x) {
        int col = (int)(i % MSUP); size_t t = i / MSUP;
        int k = (int)(t % 64); int j = (int)(t / 64);
        int s = col / PP, p = col % PP;
        int img = NQ + j*SHOT + s;
        g_bankT[((size_t)j*64+k)*BCOLS + col] = g_ndescT[((size_t)img*64+k)*PPAD + p];
    }
}
__global__ void fillT_aug_kernel()
{
    const size_t total = (size_t)KCLS*64*(SELN*PP);
    for (size_t i = (size_t)blockIdx.x*blockDim.x + threadIdx.x; i < total;
         i += (size_t)gridDim.x*blockDim.x) {
        int a = (int)(i % (SELN*PP)); size_t t = i / (SELN*PP);
        int k = (int)(t % 64); int j = (int)(t / 64);
        int sel = a / PP, p = a % PP;
        int img = NQ + NS + g_selidx[j*SELN + sel];
        g_bankT[((size_t)j*64+k)*BCOLS + MSUP + a] = g_ndescT[((size_t)img*64+k)*PPAD + p];
    }
}

// ---------- top-3-fused GEMM v2: k-major, float4, cp.async double-buffer ----------
// grid (4 rowblocks, KCLS, nImg), block 256. dyn smem = 96KB.
__global__ void __launch_bounds__(256, 2) topk_gemm_kernel(int img_base, int cols, int partSel)
{
    extern __shared__ float sm[];
    float* As = sm;            // [64][128]
    float* Bs = sm + 8192;     // [2][64][128]
    const int tid = threadIdx.x;
    const int txc = tid & 15;         // col group
    const int tyr = tid >> 4;         // row group
    const int rowg = tyr*8, colg = txc*8;
    const int cls = blockIdx.y;
    const int img = img_base + blockIdx.z;
    const int row0 = blockIdx.x*128;
    const int ntiles = (cols + 127)/128;

    const float* aSrc = g_ndescT + (size_t)img*64*PPAD + row0;
    const float* bSrc = g_bankT + (size_t)cls*64*BCOLS;

    uint32_t sAs = (uint32_t)__cvta_generic_to_shared(As);
    uint32_t sBs = (uint32_t)__cvta_generic_to_shared(Bs);

    // A tile: 64 k-rows x 512B ; 2048 chunks of 16B
    for (int c = tid; c < 2048; c += 256) {
        int k = c >> 5, off = (c & 31)*4;     // off in floats
        cpasync16(sAs + (uint32_t)(k*128 + off)*4, aSrc + (size_t)k*PPAD + off);
    }
    // B tile 0
    for (int c = tid; c < 2048; c += 256) {
        int k = c >> 5, off = (c & 31)*4;
        cpasync16(sBs + (uint32_t)(k*128 + off)*4, bSrc + (size_t)k*BCOLS + off);
    }
    CP_COMMIT();
    CP_WAIT0();
    __syncthreads();

    float t0[8], t1[8], t2[8];
#pragma unroll
    for (int r=0;r<8;r++){ t0[r]=NEGINF; t1[r]=NEGINF; t2[r]=NEGINF; }

    for (int t=0; t<ntiles; t++){
        if (t+1 < ntiles){
            const float* bN = bSrc + (t+1)*128;
            uint32_t dBuf = sBs + (uint32_t)(((t+1)&1)*8192)*4;
            for (int c = tid; c < 2048; c += 256) {
                int k = c >> 5, off = (c & 31)*4;
                cpasync16(dBuf + (uint32_t)(k*128 + off)*4, bN + (size_t)k*BCOLS + off);
            }
            CP_COMMIT();
        }
        const float* Bp = Bs + (t&1)*8192;
        float acc[8][8];
#pragma unroll
        for (int r=0;r<8;r++)
#pragma unroll
          for (int c=0;c<8;c++) acc[r][c]=0.f;
#pragma unroll 8
        for (int k=0;k<64;k++){
            float4 a0 = *(const float4*)(As + k*128 + rowg);
            float4 a1 = *(const float4*)(As + k*128 + rowg + 4);
            float4 b0 = *(const float4*)(Bp + k*128 + colg);
            float4 b1 = *(const float4*)(Bp + k*128 + colg + 4);
            float av[8] = {a0.x,a0.y,a0.z,a0.w,a1.x,a1.y,a1.z,a1.w};
            float bv[8] = {b0.x,b0.y,b0.z,b0.w,b1.x,b1.y,b1.z,b1.w};
#pragma unroll
            for (int r=0;r<8;r++)
#pragma unroll
              for (int c=0;c<8;c++) acc[r][c] += av[r]*bv[c];
        }
        const int colbase = t*128 + colg;
#pragma unroll
        for (int c=0;c<8;c++){
            bool ok = (colbase + c) < cols;
#pragma unroll
            for (int r=0;r<8;r++){
                float v = ok ? acc[r][c] : NEGINF;
                if (v > t2[r]) {
                    if (v > t0[r]) { t2[r]=t1[r]; t1[r]=t0[r]; t0[r]=v; }
                    else if (v > t1[r]) { t2[r]=t1[r]; t1[r]=v; }
                    else t2[r]=v;
                }
            }
        }
        if (t+1 < ntiles) CP_WAIT0();
        __syncthreads();
    }

    // merge: rows rowg..rowg+7 per thread, 16 col-lanes each
    float* M = sm;           // [128][16][3] = 6144 floats (As dead now)
#pragma unroll
    for (int r=0;r<8;r++){
        int row = rowg + r;
        M[(row*16+txc)*3+0] = t0[r];
        M[(row*16+txc)*3+1] = t1[r];
        M[(row*16+txc)*3+2] = t2[r];
    }
    __syncthreads();
    float* P = sm + 8192;
    if (tid < 128){
        float u0=NEGINF, u1=NEGINF, u2=NEGINF;
        const float* m = M + (size_t)tid*48;
        for (int j=0;j<48;j++){
            float v = m[j];
            if (v > u2){
                if (v > u0){ u2=u1; u1=u0; u0=v; }
                else if (v > u1){ u2=u1; u1=v; }
                else u2=v;
            }
        }
        P[tid] = (row0 + tid < PP) ? (u0+u1+u2) : 0.f;
    }
    __syncthreads();
    for (int st=64; st>0; st>>=1){
        if (tid < st) P[tid] += P[tid+st];
        __syncthreads();
    }
    if (tid==0){
        float* part = (partSel == 0) ? g_partU : g_partQ;
        part[((size_t)blockIdx.z*KCLS + cls)*4 + blockIdx.x] = P[0];
    }
}

// ---------- deterministic 4-way reduce ----------
__global__ void reduce4_kernel(int sel, float* __restrict__ outp, int n)
{
    int i = blockIdx.x*blockDim.x + threadIdx.x;
    if (i >= n) return;
    const float* part = (sel == 0) ? g_partU : g_partQ;
    float* out = (sel == 0) ? g_simu : outp;
    out[i] = part[4*i] + part[4*i+1] + part[4*i+2] + part[4*i+3];
}

// ---------- softmax + per-class top-10 (lowest-index ties) ----------
__global__ void select_kernel()
{
    __shared__ float pm[NU*KCLS];
    int tid = threadIdx.x;
    if (tid < NU){
        float v[KCLS]; float mx = NEGINF;
#pragma unroll
        for (int j=0;j<KCLS;j++){ v[j] = g_simu[tid*KCLS+j]; mx = fmaxf(mx, v[j]); }
        float s = 0.f;
#pragma unroll
        for (int j=0;j<KCLS;j++){ v[j] = expf(v[j]-mx); s += v[j]; }
#pragma unroll
        for (int j=0;j<KCLS;j++) pm[tid*KCLS+j] = v[j]/s;
    }
    __syncthreads();
    if (tid < KCLS){
        unsigned long long taken = 0ull;
        for (int i=0;i<SELN;i++){
            float best = NEGINF; int bi = 0;
            for (int b=0;b<NU;b++){
                if (taken & (1ull<<b)) continue;
                float val = pm[b*KCLS+tid];
                if (val > best){ best = val; bi = b; }
            }
            taken |= (1ull<<bi);
            g_selidx[tid*SELN+i] = bi;
        }
    }
}

extern "C" void kernel_launch(void* const* d_in, const int* in_sizes, int n_in,
                              void* d_out, int out_size)
{
    (void)in_sizes; (void)n_in; (void)out_size;
    // dict order: input1..3, w1, w2, w3, w4, g1, b1, g2, b2, g3, b3, g4, b4
    const float* in1 = (const float*)d_in[0];
    const float* in2 = (const float*)d_in[1];
    const float* in3 = (const float*)d_in[2];
    const float* w1  = (const float*)d_in[3];
    const float* w2  = (const float*)d_in[4];
    const float* w3  = (const float*)d_in[5];
    const float* w4  = (const float*)d_in[6];
    const float* gg1 = (const float*)d_in[7];
    const float* bb1 = (const float*)d_in[8];
    const float* gg2 = (const float*)d_in[9];
    const float* bb2 = (const float*)d_in[10];
    const float* gg3 = (const float*)d_in[11];
    const float* bb3 = (const float*)d_in[12];
    const float* gg4 = (const float*)d_in[13];
    const float* bb4 = (const float*)d_in[14];
    float* out = (float*)d_out;

    const int SM3 = (36864 + 16*(50*18))*4;
    const int SM2 = (36864 + 16*(34*18))*4;
    const int SMG = (8192 + 16384)*4;     // 96KB
    cudaFuncSetAttribute(conv64_kernel<3>, cudaFuncAttributeMaxDynamicSharedMemorySize, SM3);
    cudaFuncSetAttribute(conv64_kernel<2>, cudaFuncAttributeMaxDynamicSharedMemorySize, SM2);
    cudaFuncSetAttribute(topk_gemm_kernel,  cudaFuncAttributeMaxDynamicSharedMemorySize, SMG);

    dim3 blk(16,16);
    conv1_kernel<<<dim3(6,6,NALL), blk>>>(in1, in2, in3, w1);
    bn_stats_kernel<<<dim3(64,3), 256>>>(0, H1*H1);
    bn_pool_kernel<<<2048, 256>>>(0, 1, gg1, bb1, H1, H1, 1);
    conv64_kernel<3><<<dim3(3,1,NALL), blk, SM3>>>(1, 2, w2, H2, H2);
    bn_stats_kernel<<<dim3(64,3), 256>>>(2, H2*H2);
    bn_pool_kernel<<<2048, 256>>>(2, 3, gg2, bb2, H2, H2, 1);
    conv64_kernel<2><<<dim3(2,1,NALL), blk, SM2>>>(3, 4, w3, H3, H3);
    bn_stats_kernel<<<dim3(64,3), 256>>>(4, H3*H3);
    bn_pool_kernel<<<2048, 256>>>(4, 3, gg3, bb3, H3, H3, 0);
    conv64_kernel<2><<<dim3(2,1,NALL), blk, SM2>>>(3, 4, w4, H3, H3);
    bn_stats_kernel<<<dim3(64,3), 256>>>(4, H3*H3);
    bn_pool_kernel<<<2048, 256>>>(4, 3, gg4, bb4, H3, H3, 0);   // final feats in D

    norm_kernel<<<NALL, 256>>>();
    ndescT_kernel<<<2048, 256>>>();
    fillT_support_kernel<<<2048, 256>>>();

    topk_gemm_kernel<<<dim3(4,KCLS,NU), 256, SMG>>>(NQ+NS, MSUP, 0);
    reduce4_kernel<<<(NU*KCLS + 255)/256, 256>>>(0, nullptr, NU*KCLS);
    select_kernel<<<1, 64>>>();
    fillT_aug_kernel<<<2048, 256>>>();

    topk_gemm_kernel<<<dim3(4,KCLS,NQ), 256, SMG>>>(0, MAUG, 1);
    reduce4_kernel<<<(NQ*KCLS + 255)/256, 256>>>(1, out, NQ*KCLS);
}

// round 6
// speedup vs baseline: 1.6493x; 1.6493x over previous
#include <cuda_runtime.h>
#include <math.h>
#include <stdint.h>

#define NQ 75
#define NS 25
#define NU 64
#define NALL 164
#define H1 84
#define H2 42
#define H3 21
#define PP 441
#define KCLS 5
#define SHOT 5
#define MSUP (SHOT*PP)          // 2205
#define MAUG (MSUP + 10*PP)     // 6615
#define BCOLS 6656              // 52*128
#define QROWS (NQ*PP)           // 33075
#define QPAD  33152             // 259*128
#define UROWS (NU*PP)           // 28224
#define UPAD  28288             // 221*128
#define SELN 10
#define NEGINF -3.4e38f

__device__ float g_bufA[(size_t)NALL*64*H1*H1];
__device__ float g_bufC[(size_t)NALL*64*H2*H2];
__device__ float g_bufD[(size_t)NALL*64*H3*H3];
__device__ float g_bufE[(size_t)NALL*64*H3*H3];
__device__ float g_bufB[(size_t)NALL*64*H2*H2];
__device__ float g_rinv[(size_t)NALL*PP];
__device__ float g_qkT[(size_t)64*QPAD];          // [k][row] query rows flattened
__device__ float g_ukT[(size_t)64*UPAD];          // [k][row] unlabeled rows flattened
__device__ float g_bankT[(size_t)KCLS*64*BCOLS];  // [cls][k][col]
__device__ float g_rowsum[(size_t)KCLS*QPAD];     // per-row top3 sums
__device__ float g_stats[3*64*2];
__device__ float g_simu[NU*KCLS];
__device__ int   g_selidx[KCLS*SELN];

__device__ __forceinline__ float* bufPtr(int s){
    switch(s){
        case 0: return g_bufA; case 1: return g_bufB; case 2: return g_bufC;
        case 3: return g_bufD; default: return g_bufE;
    }
}
__device__ __forceinline__ int groupOf(int n){ return (n < NQ) ? 0 : ((n < NQ+NS) ? 1 : 2); }

__device__ __forceinline__ void cpasync16(uint32_t dst, const void* src){
    asm volatile("cp.async.cg.shared.global [%0], [%1], 16;\n" :: "r"(dst), "l"(src));
}
#define CP_COMMIT() asm volatile("cp.async.commit_group;\n" ::: "memory")
#define CP_WAIT0()  asm volatile("cp.async.wait_group 0;\n" ::: "memory")

// ---------- conv1: 3->64, 84x84 SAME ----------
__global__ void conv1_kernel(const float* __restrict__ in1, const float* __restrict__ in2,
                             const float* __restrict__ in3, const float* __restrict__ w)
{
    __shared__ float sW[64*27];
    __shared__ float sIn[3*18*18];
    const int n = blockIdx.z;
    const int gx0 = blockIdx.x*16, gy0 = blockIdx.y*16;
    const int tx = threadIdx.x, ty = threadIdx.y;
    const int tid = ty*16 + tx;
    const float* img = (n < NQ)    ? (in1 + (size_t)n*3*H1*H1)
                     : (n < NQ+NS) ? (in2 + (size_t)(n-NQ)*3*H1*H1)
                                   : (in3 + (size_t)(n-NQ-NS)*3*H1*H1);
    for (int i = tid; i < 64*27; i += 256) sW[i] = w[i];
    for (int i = tid; i < 3*18*18; i += 256) {
        int c = i / 324, rem = i % 324, r = rem/18, cc = rem%18;
        int gy = gy0 - 1 + r, gx = gx0 - 1 + cc;
        sIn[i] = (gy>=0 && gy<H1 && gx>=0 && gx<H1) ? img[((size_t)c*H1+gy)*H1+gx] : 0.f;
    }
    __syncthreads();
    int ox = gx0+tx, oy = gy0+ty;
    if (ox >= H1 || oy >= H1) return;
    float v[27];
#pragma unroll
    for (int c=0;c<3;c++)
#pragma unroll
      for (int dy=0;dy<3;dy++)
#pragma unroll
        for (int dx=0;dx<3;dx++)
          v[c*9+dy*3+dx] = sIn[c*324 + (ty+dy)*18 + (tx+dx)];
#pragma unroll 4
    for (int oc=0; oc<64; oc++){
        float acc = 0.f;
        const float* wp = sW + oc*27;
#pragma unroll
        for (int j=0;j<27;j++) acc += wp[j]*v[j];
        g_bufA[(((size_t)n*64+oc)*H1+oy)*H1+ox] = acc;
    }
}

// ---------- conv 64->64 3x3 SAME ----------
template<int RPT>
__global__ void conv64_kernel(int inSel, int outSel, const float* __restrict__ wt, int H, int W)
{
    extern __shared__ float sm[];
    float* sW  = sm;
    float* sIn = sm + 36864;
    constexpr int TH   = 16*RPT;
    constexpr int HALO = (TH+2)*18;
    const int n   = blockIdx.z;
    const int gx0 = blockIdx.x*16;
    const int gy0 = blockIdx.y*TH;
    const int tx = threadIdx.x, ty = threadIdx.y;
    const int tid = ty*16 + tx;
    for (int i = tid; i < 64*64*9; i += 256) sW[i] = wt[i];
    const int oyb = gy0 + ty*RPT;
    const int ox  = gx0 + tx;
    const bool anyValid = (ox < W) && (oyb < H);
    const float* inN  = bufPtr(inSel)  + (size_t)n*64*H*W;
    float*       outN = bufPtr(outSel) + (size_t)n*64*H*W;

    for (int ocg = 0; ocg < 4; ++ocg) {
        float acc[16][RPT];
#pragma unroll
        for (int o=0;o<16;o++)
#pragma unroll
          for (int r=0;r<RPT;r++) acc[o][r]=0.f;
        for (int cc = 0; cc < 4; ++cc) {
            __syncthreads();
            for (int i = tid; i < 16*HALO; i += 256) {
                int c = i / HALO, rem = i % HALO, r = rem/18, col = rem%18;
                int gy = gy0-1+r, gx = gx0-1+col;
                float v = 0.f;
                if (gy>=0 && gy<H && gx>=0 && gx<W)
                    v = inN[((size_t)(cc*16+c)*H+gy)*W+gx];
                sIn[i] = v;
            }
            __syncthreads();
            if (anyValid) {
                for (int ic=0; ic<16; ++ic) {
                    float v[RPT+2][3];
                    const float* sp = sIn + ic*HALO + (ty*RPT)*18 + tx;
#pragma unroll
                    for (int r=0;r<RPT+2;r++)
#pragma unroll
                      for (int d=0;d<3;d++) v[r][d] = sp[r*18+d];
                    const float* wp = sW + (size_t)(ocg*16)*576 + (cc*16+ic)*9;
#pragma unroll
                    for (int o=0;o<16;o++){
                        const float* wo = wp + o*576;
                        float w0=wo[0],w1=wo[1],w2=wo[2],w3=wo[3],w4=wo[4];
                        float w5=wo[5],w6=wo[6],w7=wo[7],w8=wo[8];
#pragma unroll
                        for (int r=0;r<RPT;r++){
                            float a = acc[o][r];
                            a += w0*v[r  ][0]; a += w1*v[r  ][1]; a += w2*v[r  ][2];
                            a += w3*v[r+1][0]; a += w4*v[r+1][1]; a += w5*v[r+1][2];
                            a += w6*v[r+2][0]; a += w7*v[r+2][1]; a += w8*v[r+2][2];
                            acc[o][r] = a;
                        }
                    }
                }
            }
        }
        if (anyValid) {
#pragma unroll
            for (int o=0;o<16;o++){
                int oc = ocg*16+o;
#pragma unroll
                for (int r=0;r<RPT;r++){
                    int oy = oyb + r;
                    if (oy < H) outN[((size_t)oc*H+oy)*W+ox] = acc[o][r];
                }
            }
        }
    }
}

// ---------- BN stats ----------
__global__ void bn_stats_kernel(int sel, int HW)
{
    __shared__ double ssum[256], ssum2[256];
    const int ch = blockIdx.x, g = blockIdx.y;
    const int n0 = (g==0)?0:((g==1)?NQ:(NQ+NS));
    const int n1 = (g==0)?NQ:((g==1)?(NQ+NS):NALL);
    const int tid = threadIdx.x;
    const float* buf = bufPtr(sel);
    double s=0.0, s2=0.0;
    for (int n=n0; n<n1; ++n) {
        const float* p = buf + ((size_t)n*64+ch)*HW;
        for (int i=tid;i<HW;i+=256){ double x = (double)p[i]; s+=x; s2+=x*x; }
    }
    ssum[tid]=s; ssum2[tid]=s2; __syncthreads();
    for (int st=128; st>0; st>>=1){
        if (tid<st){ ssum[tid]+=ssum[tid+st]; ssum2[tid]+=ssum2[tid+st]; }
        __syncthreads();
    }
    if (tid==0){
        double cnt = (double)(n1-n0)*HW;
        double mean = ssum[0]/cnt;
        double var  = ssum2[0]/cnt - mean*mean;
        g_stats[(g*64+ch)*2+0] = (float)mean;
        g_stats[(g*64+ch)*2+1] = (float)(1.0/sqrt(var + 1e-5));
    }
}

// ---------- BN + LeakyReLU (+pool) ----------
__global__ void bn_pool_kernel(int inSel, int outSel, const float* __restrict__ gamma,
                               const float* __restrict__ beta, int H, int W, int doPool)
{
    const int oH = doPool ? H/2 : H, oW = doPool ? W/2 : W;
    const size_t total = (size_t)NALL*64*oH*oW;
    const float* in = bufPtr(inSel);
    float* out = bufPtr(outSel);
    for (size_t idx = (size_t)blockIdx.x*blockDim.x + threadIdx.x; idx < total;
         idx += (size_t)gridDim.x*blockDim.x) {
        int ox = (int)(idx % oW); size_t t = idx / oW;
        int oy = (int)(t % oH);   t /= oH;
        int c  = (int)(t % 64);   int n = (int)(t / 64);
        int g = groupOf(n);
        float mean = g_stats[(g*64+c)*2+0], rsig = g_stats[(g*64+c)*2+1];
        float sc = gamma[c]*rsig;
        float sh = beta[c] - mean*sc;
        const float* p = in + ((size_t)n*64+c)*H*W;
        float r;
        if (doPool){
            float x0 = p[(size_t)(2*oy)*W + 2*ox  ]*sc+sh;
            float x1 = p[(size_t)(2*oy)*W + 2*ox+1]*sc+sh;
            float x2 = p[(size_t)(2*oy+1)*W + 2*ox  ]*sc+sh;
            float x3 = p[(size_t)(2*oy+1)*W + 2*ox+1]*sc+sh;
            x0 = x0>=0.f?x0:0.2f*x0; x1 = x1>=0.f?x1:0.2f*x1;
            x2 = x2>=0.f?x2:0.2f*x2; x3 = x3>=0.f?x3:0.2f*x3;
            r = fmaxf(fmaxf(x0,x1), fmaxf(x2,x3));
        } else {
            float x = p[(size_t)oy*W+ox]*sc+sh;
            r = x>=0.f?x:0.2f*x;
        }
        out[idx] = r;
    }
}

// ---------- descriptor inverse norms ----------
__global__ void norm_kernel()
{
    int img = blockIdx.x;
    for (int p = threadIdx.x; p < PP; p += blockDim.x){
        float ss = 0.f;
        const float* f = g_bufD + (size_t)img*64*PP + p;
#pragma unroll
        for (int c=0;c<64;c++){ float x = f[(size_t)c*PP]; ss += x*x; }
        g_rinv[(size_t)img*PP + p] = rsqrtf(ss);
    }
}

// ---------- flattened k-major normalized descriptors ----------
__global__ void flatT_kernel(int mode)
{
    const int pad = mode ? UPAD : QPAD;
    const int nrows = mode ? UROWS : QROWS;
    const int imgBase = mode ? (NQ+NS) : 0;
    float* dst = mode ? g_ukT : g_qkT;
    const size_t total = (size_t)64*pad;
    for (size_t idx = (size_t)blockIdx.x*blockDim.x + threadIdx.x; idx < total;
         idx += (size_t)gridDim.x*blockDim.x) {
        int row = (int)(idx % pad); int k = (int)(idx / pad);
        float v = 0.f;
        if (row < nrows){
            int im = row / PP, p = row % PP;
            int img = imgBase + im;
            v = g_bufD[((size_t)img*64+k)*PP + p] * g_rinv[(size_t)img*PP + p];
        }
        dst[idx] = v;
    }
}

// ---------- bank fills (k-major) ----------
__global__ void fillT_support_kernel()
{
    const size_t total = (size_t)KCLS*64*MSUP;
    for (size_t i = (size_t)blockIdx.x*blockDim.x + threadIdx.x; i < total;
         i += (size_t)gridDim.x*blockDim.x) {
        int col = (int)(i % MSUP); size_t t = i / MSUP;
        int k = (int)(t % 64); int j = (int)(t / 64);
        int s = col / PP, p = col % PP;
        int img = NQ + j*SHOT + s;
        g_bankT[((size_t)j*64+k)*BCOLS + col] =
            g_bufD[((size_t)img*64+k)*PP + p] * g_rinv[(size_t)img*PP + p];
    }
}
__global__ void fillT_aug_kernel()
{
    const size_t total = (size_t)KCLS*64*(SELN*PP);
    for (size_t i = (size_t)blockIdx.x*blockDim.x + threadIdx.x; i < total;
         i += (size_t)gridDim.x*blockDim.x) {
        int a = (int)(i % (SELN*PP)); size_t t = i / (SELN*PP);
        int k = (int)(t % 64); int j = (int)(t / 64);
        int sel = a / PP, p = a % PP;
        int img = NQ + NS + g_selidx[j*SELN + sel];
        g_bankT[((size_t)j*64+k)*BCOLS + MSUP + a] =
            g_bufD[((size_t)img*64+k)*PP + p] * g_rinv[(size_t)img*PP + p];
    }
}

// ---------- top-3-fused GEMM v3b: A selected ON DEVICE (aSel: 0=unlabeled, 1=query) ----------
// grid (rowtiles, KCLS), block 256, dyn smem 96KB
__global__ void __launch_bounds__(256) topk_gemm_kernel(
    int aSel, int aStride, int nrows, int cols)
{
    extern __shared__ float sm[];
    float* As = sm;            // [64][128]
    float* Bs = sm + 8192;     // [2][64][128]
    const float* aT = aSel ? g_qkT : g_ukT;     // device-side symbol resolution
    const int tid = threadIdx.x;
    const int txc = tid & 15;
    const int tyr = tid >> 4;
    const int rowg = tyr*8, colg = txc*8;
    const int cls = blockIdx.y;
    const int row0 = blockIdx.x*128;
    const int ntiles = (cols + 127)/128;

    const float* aSrc = aT + row0;
    const float* bSrc = g_bankT + (size_t)cls*64*BCOLS;
    uint32_t sAs = (uint32_t)__cvta_generic_to_shared(As);
    uint32_t sBs = (uint32_t)__cvta_generic_to_shared(Bs);

    for (int c = tid; c < 2048; c += 256) {
        int k = c >> 5, off = (c & 31)*4;
        cpasync16(sAs + (uint32_t)(k*128 + off)*4, aSrc + (size_t)k*aStride + off);
    }
    for (int c = tid; c < 2048; c += 256) {
        int k = c >> 5, off = (c & 31)*4;
        cpasync16(sBs + (uint32_t)(k*128 + off)*4, bSrc + (size_t)k*BCOLS + off);
    }
    CP_COMMIT();
    CP_WAIT0();
    __syncthreads();

    float t0[8], t1[8], t2[8];
#pragma unroll
    for (int r=0;r<8;r++){ t0[r]=NEGINF; t1[r]=NEGINF; t2[r]=NEGINF; }

    for (int t=0; t<ntiles; t++){
        if (t+1 < ntiles){
            const float* bN = bSrc + (t+1)*128;
            uint32_t dBuf = sBs + (uint32_t)(((t+1)&1)*8192)*4;
            for (int c = tid; c < 2048; c += 256) {
                int k = c >> 5, off = (c & 31)*4;
                cpasync16(dBuf + (uint32_t)(k*128 + off)*4, bN + (size_t)k*BCOLS + off);
            }
            CP_COMMIT();
        }
        const float* Bp = Bs + (t&1)*8192;
        float acc[8][8];
#pragma unroll
        for (int r=0;r<8;r++)
#pragma unroll
          for (int c=0;c<8;c++) acc[r][c]=0.f;
#pragma unroll 2
        for (int k=0;k<64;k++){
            float4 a0 = *(const float4*)(As + k*128 + rowg);
            float4 a1 = *(const float4*)(As + k*128 + rowg + 4);
            float4 b0 = *(const float4*)(Bp + k*128 + colg);
            float4 b1 = *(const float4*)(Bp + k*128 + colg + 4);
            acc[0][0]+=a0.x*b0.x; acc[0][1]+=a0.x*b0.y; acc[0][2]+=a0.x*b0.z; acc[0][3]+=a0.x*b0.w;
            acc[0][4]+=a0.x*b1.x; acc[0][5]+=a0.x*b1.y; acc[0][6]+=a0.x*b1.z; acc[0][7]+=a0.x*b1.w;
            acc[1][0]+=a0.y*b0.x; acc[1][1]+=a0.y*b0.y; acc[1][2]+=a0.y*b0.z; acc[1][3]+=a0.y*b0.w;
            acc[1][4]+=a0.y*b1.x; acc[1][5]+=a0.y*b1.y; acc[1][6]+=a0.y*b1.z; acc[1][7]+=a0.y*b1.w;
            acc[2][0]+=a0.z*b0.x; acc[2][1]+=a0.z*b0.y; acc[2][2]+=a0.z*b0.z; acc[2][3]+=a0.z*b0.w;
            acc[2][4]+=a0.z*b1.x; acc[2][5]+=a0.z*b1.y; acc[2][6]+=a0.z*b1.z; acc[2][7]+=a0.z*b1.w;
            acc[3][0]+=a0.w*b0.x; acc[3][1]+=a0.w*b0.y; acc[3][2]+=a0.w*b0.z; acc[3][3]+=a0.w*b0.w;
            acc[3][4]+=a0.w*b1.x; acc[3][5]+=a0.w*b1.y; acc[3][6]+=a0.w*b1.z; acc[3][7]+=a0.w*b1.w;
            acc[4][0]+=a1.x*b0.x; acc[4][1]+=a1.x*b0.y; acc[4][2]+=a1.x*b0.z; acc[4][3]+=a1.x*b0.w;
            acc[4][4]+=a1.x*b1.x; acc[4][5]+=a1.x*b1.y; acc[4][6]+=a1.x*b1.z; acc[4][7]+=a1.x*b1.w;
            acc[5][0]+=a1.y*b0.x; acc[5][1]+=a1.y*b0.y; acc[5][2]+=a1.y*b0.z; acc[5][3]+=a1.y*b0.w;
            acc[5][4]+=a1.y*b1.x; acc[5][5]+=a1.y*b1.y; acc[5][6]+=a1.y*b1.z; acc[5][7]+=a1.y*b1.w;
            acc[6][0]+=a1.z*b0.x; acc[6][1]+=a1.z*b0.y; acc[6][2]+=a1.z*b0.z; acc[6][3]+=a1.z*b0.w;
            acc[6][4]+=a1.z*b1.x; acc[6][5]+=a1.z*b1.y; acc[6][6]+=a1.z*b1.z; acc[6][7]+=a1.z*b1.w;
            acc[7][0]+=a1.w*b0.x; acc[7][1]+=a1.w*b0.y; acc[7][2]+=a1.w*b0.z; acc[7][3]+=a1.w*b0.w;
            acc[7][4]+=a1.w*b1.x; acc[7][5]+=a1.w*b1.y; acc[7][6]+=a1.w*b1.z; acc[7][7]+=a1.w*b1.w;
        }
        const int colbase = t*128 + colg;
#pragma unroll
        for (int c=0;c<8;c++){
            bool ok = (colbase + c) < cols;
#pragma unroll
            for (int r=0;r<8;r++){
                float v = ok ? acc[r][c] : NEGINF;
                if (v > t2[r]) {
                    if (v > t0[r]) { t2[r]=t1[r]; t1[r]=t0[r]; t0[r]=v; }
                    else if (v > t1[r]) { t2[r]=t1[r]; t1[r]=v; }
                    else t2[r]=v;
                }
            }
        }
        if (t+1 < ntiles) CP_WAIT0();
        __syncthreads();
    }

    float* M = sm;   // [128][16][3], reuses As (dead)
#pragma unroll
    for (int r=0;r<8;r++){
        int row = rowg + r;
        M[(row*16+txc)*3+0] = t0[r];
        M[(row*16+txc)*3+1] = t1[r];
        M[(row*16+txc)*3+2] = t2[r];
    }
    __syncthreads();
    if (tid < 128){
        float u0=NEGINF, u1=NEGINF, u2=NEGINF;
        const float* m = M + (size_t)tid*48;
        for (int j=0;j<48;j++){
            float v = m[j];
            if (v > u2){
                if (v > u0){ u2=u1; u1=u0; u0=v; }
                else if (v > u1){ u2=u1; u1=v; }
                else u2=v;
            }
        }
        int row = row0 + tid;
        if (row < nrows)
            g_rowsum[(size_t)cls*QPAD + row] = u0+u1+u2;
    }
}

// ---------- per-image deterministic sum of 441 row-top3 values ----------
__global__ void imgsum_kernel(float* __restrict__ outp, int useOut)
{
    __shared__ float s[128];
    const int img = blockIdx.x, cls = blockIdx.y;
    const int tid = threadIdx.x;
    const float* src = g_rowsum + (size_t)cls*QPAD + (size_t)img*PP;
    float v = 0.f;
    for (int i = tid; i < PP; i += 128) v += src[i];
    s[tid] = v; __syncthreads();
    for (int st=64; st>0; st>>=1){
        if (tid < st) s[tid] += s[tid+st];
        __syncthreads();
    }
    if (tid==0){
        float* dst = useOut ? outp : g_simu;
        dst[img*KCLS + cls] = s[0];
    }
}

// ---------- softmax + per-class top-10 (lowest-index ties) ----------
__global__ void select_kernel()
{
    __shared__ float pm[NU*KCLS];
    int tid = threadIdx.x;
    if (tid < NU){
        float v[KCLS]; float mx = NEGINF;
#pragma unroll
        for (int j=0;j<KCLS;j++){ v[j] = g_simu[tid*KCLS+j]; mx = fmaxf(mx, v[j]); }
        float s = 0.f;
#pragma unroll
        for (int j=0;j<KCLS;j++){ v[j] = expf(v[j]-mx); s += v[j]; }
#pragma unroll
        for (int j=0;j<KCLS;j++) pm[tid*KCLS+j] = v[j]/s;
    }
    __syncthreads();
    if (tid < KCLS){
        unsigned long long taken = 0ull;
        for (int i=0;i<SELN;i++){
            float best = NEGINF; int bi = 0;
            for (int b=0;b<NU;b++){
                if (taken & (1ull<<b)) continue;
                float val = pm[b*KCLS+tid];
                if (val > best){ best = val; bi = b; }
            }
            taken |= (1ull<<bi);
            g_selidx[tid*SELN+i] = bi;
        }
    }
}

extern "C" void kernel_launch(void* const* d_in, const int* in_sizes, int n_in,
                              void* d_out, int out_size)
{
    (void)in_sizes; (void)n_in; (void)out_size;
    // dict order: input1..3, w1, w2, w3, w4, g1, b1, g2, b2, g3, b3, g4, b4
    const float* in1 = (const float*)d_in[0];
    const float* in2 = (const float*)d_in[1];
    const float* in3 = (const float*)d_in[2];
    const float* w1  = (const float*)d_in[3];
    const float* w2  = (const float*)d_in[4];
    const float* w3  = (const float*)d_in[5];
    const float* w4  = (const float*)d_in[6];
    const float* gg1 = (const float*)d_in[7];
    const float* bb1 = (const float*)d_in[8];
    const float* gg2 = (const float*)d_in[9];
    const float* bb2 = (const float*)d_in[10];
    const float* gg3 = (const float*)d_in[11];
    const float* bb3 = (const float*)d_in[12];
    const float* gg4 = (const float*)d_in[13];
    const float* bb4 = (const float*)d_in[14];
    float* out = (float*)d_out;

    const int SM3 = (36864 + 16*(50*18))*4;
    const int SM2 = (36864 + 16*(34*18))*4;
    const int SMG = (8192 + 16384)*4;     // 96KB
    cudaFuncSetAttribute(conv64_kernel<3>, cudaFuncAttributeMaxDynamicSharedMemorySize, SM3);
    cudaFuncSetAttribute(conv64_kernel<2>, cudaFuncAttributeMaxDynamicSharedMemorySize, SM2);
    cudaFuncSetAttribute(topk_gemm_kernel,  cudaFuncAttributeMaxDynamicSharedMemorySize, SMG);

    dim3 blk(16,16);
    conv1_kernel<<<dim3(6,6,NALL), blk>>>(in1, in2, in3, w1);
    bn_stats_kernel<<<dim3(64,3), 256>>>(0, H1*H1);
    bn_pool_kernel<<<2048, 256>>>(0, 1, gg1, bb1, H1, H1, 1);
    conv64_kernel<3><<<dim3(3,1,NALL), blk, SM3>>>(1, 2, w2, H2, H2);
    bn_stats_kernel<<<dim3(64,3), 256>>>(2, H2*H2);
    bn_pool_kernel<<<2048, 256>>>(2, 3, gg2, bb2, H2, H2, 1);
    conv64_kernel<2><<<dim3(2,1,NALL), blk, SM2>>>(3, 4, w3, H3, H3);
    bn_stats_kernel<<<dim3(64,3), 256>>>(4, H3*H3);
    bn_pool_kernel<<<2048, 256>>>(4, 3, gg3, bb3, H3, H3, 0);
    conv64_kernel<2><<<dim3(2,1,NALL), blk, SM2>>>(3, 4, w4, H3, H3);
    bn_stats_kernel<<<dim3(64,3), 256>>>(4, H3*H3);
    bn_pool_kernel<<<2048, 256>>>(4, 3, gg4, bb4, H3, H3, 0);   // final feats in D

    norm_kernel<<<NALL, 256>>>();
    flatT_kernel<<<2048, 256>>>(0);                     // queries
    flatT_kernel<<<2048, 256>>>(1);                     // unlabeled
    fillT_support_kernel<<<2048, 256>>>();

    // stage 1: unlabeled rows vs support banks (aSel=0 -> g_ukT)
    topk_gemm_kernel<<<dim3(UPAD/128, KCLS), 256, SMG>>>(0, UPAD, UROWS, MSUP);
    imgsum_kernel<<<dim3(NU, KCLS), 128>>>(nullptr, 0);
    select_kernel<<<1, 64>>>();
    fillT_aug_kernel<<<2048, 256>>>();

    // stage 2: query rows vs augmented banks -> out [75,5] (aSel=1 -> g_qkT)
    topk_gemm_kernel<<<dim3(QPAD/128, KCLS), 256, SMG>>>(1, QPAD, QROWS, MAUG);
    imgsum_kernel<<<dim3(NQ, KCLS), 128>>>(out, 1);
}

// round 8
// speedup vs baseline: 1.6626x; 1.0081x over previous
#include <cuda_runtime.h>
#include <cuda_bf16.h>
#include <mma.h>
#include <math.h>
#include <stdint.h>

using namespace nvcuda;

#define NQ 75
#define NS 25
#define NU 64
#define NALL 164
#define H1 84
#define H2 42
#define H3 21
#define PP 441
#define KCLS 5
#define SHOT 5
#define MSUP (SHOT*PP)          // 2205
#define MAUG (MSUP + 10*PP)     // 6615
#define BCOLS 6656              // 52*128
#define QROWS (NQ*PP)           // 33075
#define QPAD  33152             // 259*128
#define UROWS (NU*PP)           // 28224
#define UPAD  28288             // 221*128
#define SELN 10
#define NEGINF -3.4e38f
#define CT2 128
#define CTILES2 (BCOLS/CT2)     // 52

__device__ float g_bufA[(size_t)NALL*64*H1*H1];
__device__ float g_bufC[(size_t)NALL*64*H2*H2];
__device__ float g_bufD[(size_t)NALL*64*H3*H3];
__device__ float g_bufE[(size_t)NALL*64*H3*H3];
__device__ float g_bufB[(size_t)NALL*64*H2*H2];
__device__ float g_rinv[(size_t)NALL*PP];
__device__ float g_ukT[(size_t)64*UPAD];                 // [k][row] fp32 stage1
__device__ float g_bankT[(size_t)KCLS*64*BCOLS];         // [cls][k][col] fp32 stage1
__device__ __nv_bfloat16 g_qbf[(size_t)QPAD*64];         // [row][k] bf16 stage2 A
__device__ __nv_bfloat16 g_bankbf[(size_t)KCLS*BCOLS*64];// [cls][col][k] bf16 stage2 B
__device__ float g_rowsum[(size_t)KCLS*QPAD];
__device__ float g_stats[3*64*2];
__device__ float g_simu[NU*KCLS];
__device__ int   g_selidx[KCLS*SELN];

__device__ __forceinline__ float* bufPtr(int s){
    switch(s){
        case 0: return g_bufA; case 1: return g_bufB; case 2: return g_bufC;
        case 3: return g_bufD; default: return g_bufE;
    }
}
__device__ __forceinline__ int groupOf(int n){ return (n < NQ) ? 0 : ((n < NQ+NS) ? 1 : 2); }

__device__ __forceinline__ void cpasync16(uint32_t dst, const void* src){
    asm volatile("cp.async.cg.shared.global [%0], [%1], 16;\n" :: "r"(dst), "l"(src));
}
#define CP_COMMIT() asm volatile("cp.async.commit_group;\n" ::: "memory")
#define CP_WAIT0()  asm volatile("cp.async.wait_group 0;\n" ::: "memory")

// ---------- conv1: 3->64, 84x84 SAME ----------
__global__ void conv1_kernel(const float* __restrict__ in1, const float* __restrict__ in2,
                             const float* __restrict__ in3, const float* __restrict__ w)
{
    __shared__ float sW[64*27];
    __shared__ float sIn[3*18*18];
    const int n = blockIdx.z;
    const int gx0 = blockIdx.x*16, gy0 = blockIdx.y*16;
    const int tx = threadIdx.x, ty = threadIdx.y;
    const int tid = ty*16 + tx;
    const float* img = (n < NQ)    ? (in1 + (size_t)n*3*H1*H1)
                     : (n < NQ+NS) ? (in2 + (size_t)(n-NQ)*3*H1*H1)
                                   : (in3 + (size_t)(n-NQ-NS)*3*H1*H1);
    for (int i = tid; i < 64*27; i += 256) sW[i] = w[i];
    for (int i = tid; i < 3*18*18; i += 256) {
        int c = i / 324, rem = i % 324, r = rem/18, cc = rem%18;
        int gy = gy0 - 1 + r, gx = gx0 - 1 + cc;
        sIn[i] = (gy>=0 && gy<H1 && gx>=0 && gx<H1) ? img[((size_t)c*H1+gy)*H1+gx] : 0.f;
    }
    __syncthreads();
    int ox = gx0+tx, oy = gy0+ty;
    if (ox >= H1 || oy >= H1) return;
    float v[27];
#pragma unroll
    for (int c=0;c<3;c++)
#pragma unroll
      for (int dy=0;dy<3;dy++)
#pragma unroll
        for (int dx=0;dx<3;dx++)
          v[c*9+dy*3+dx] = sIn[c*324 + (ty+dy)*18 + (tx+dx)];
#pragma unroll 4
    for (int oc=0; oc<64; oc++){
        float acc = 0.f;
        const float* wp = sW + oc*27;
#pragma unroll
        for (int j=0;j<27;j++) acc += wp[j]*v[j];
        g_bufA[(((size_t)n*64+oc)*H1+oy)*H1+ox] = acc;
    }
}

// ---------- conv 64->64 3x3 SAME ----------
template<int RPT>
__global__ void conv64_kernel(int inSel, int outSel, const float* __restrict__ wt, int H, int W)
{
    extern __shared__ float sm[];
    float* sW  = sm;
    float* sIn = sm + 36864;
    constexpr int TH   = 16*RPT;
    constexpr int HALO = (TH+2)*18;
    const int n   = blockIdx.z;
    const int gx0 = blockIdx.x*16;
    const int gy0 = blockIdx.y*TH;
    const int tx = threadIdx.x, ty = threadIdx.y;
    const int tid = ty*16 + tx;
    for (int i = tid; i < 64*64*9; i += 256) sW[i] = wt[i];
    const int oyb = gy0 + ty*RPT;
    const int ox  = gx0 + tx;
    const bool anyValid = (ox < W) && (oyb < H);
    const float* inN  = bufPtr(inSel)  + (size_t)n*64*H*W;
    float*       outN = bufPtr(outSel) + (size_t)n*64*H*W;

    for (int ocg = 0; ocg < 4; ++ocg) {
        float acc[16][RPT];
#pragma unroll
        for (int o=0;o<16;o++)
#pragma unroll
          for (int r=0;r<RPT;r++) acc[o][r]=0.f;
        for (int cc = 0; cc < 4; ++cc) {
            __syncthreads();
            for (int i = tid; i < 16*HALO; i += 256) {
                int c = i / HALO, rem = i % HALO, r = rem/18, col = rem%18;
                int gy = gy0-1+r, gx = gx0-1+col;
                float v = 0.f;
                if (gy>=0 && gy<H && gx>=0 && gx<W)
                    v = inN[((size_t)(cc*16+c)*H+gy)*W+gx];
                sIn[i] = v;
            }
            __syncthreads();
            if (anyValid) {
                for (int ic=0; ic<16; ++ic) {
                    float v[RPT+2][3];
                    const float* sp = sIn + ic*HALO + (ty*RPT)*18 + tx;
#pragma unroll
                    for (int r=0;r<RPT+2;r++)
#pragma unroll
                      for (int d=0;d<3;d++) v[r][d] = sp[r*18+d];
                    const float* wp = sW + (size_t)(ocg*16)*576 + (cc*16+ic)*9;
#pragma unroll
                    for (int o=0;o<16;o++){
                        const float* wo = wp + o*576;
                        float w0=wo[0],w1=wo[1],w2=wo[2],w3=wo[3],w4=wo[4];
                        float w5=wo[5],w6=wo[6],w7=wo[7],w8=wo[8];
#pragma unroll
                        for (int r=0;r<RPT;r++){
                            float a = acc[o][r];
                            a += w0*v[r  ][0]; a += w1*v[r  ][1]; a += w2*v[r  ][2];
                            a += w3*v[r+1][0]; a += w4*v[r+1][1]; a += w5*v[r+1][2];
                            a += w6*v[r+2][0]; a += w7*v[r+2][1]; a += w8*v[r+2][2];
                            acc[o][r] = a;
                        }
                    }
                }
            }
        }
        if (anyValid) {
#pragma unroll
            for (int o=0;o<16;o++){
                int oc = ocg*16+o;
#pragma unroll
                for (int r=0;r<RPT;r++){
                    int oy = oyb + r;
                    if (oy < H) outN[((size_t)oc*H+oy)*W+ox] = acc[o][r];
                }
            }
        }
    }
}

// ---------- BN stats ----------
__global__ void bn_stats_kernel(int sel, int HW)
{
    __shared__ double ssum[256], ssum2[256];
    const int ch = blockIdx.x, g = blockIdx.y;
    const int n0 = (g==0)?0:((g==1)?NQ:(NQ+NS));
    const int n1 = (g==0)?NQ:((g==1)?(NQ+NS):NALL);
    const int tid = threadIdx.x;
    const float* buf = bufPtr(sel);
    double s=0.0, s2=0.0;
    for (int n=n0; n<n1; ++n) {
        const float* p = buf + ((size_t)n*64+ch)*HW;
        for (int i=tid;i<HW;i+=256){ double x = (double)p[i]; s+=x; s2+=x*x; }
    }
    ssum[tid]=s; ssum2[tid]=s2; __syncthreads();
    for (int st=128; st>0; st>>=1){
        if (tid<st){ ssum[tid]+=ssum[tid+st]; ssum2[tid]+=ssum2[tid+st]; }
        __syncthreads();
    }
    if (tid==0){
        double cnt = (double)(n1-n0)*HW;
        double mean = ssum[0]/cnt;
        double var  = ssum2[0]/cnt - mean*mean;
        g_stats[(g*64+ch)*2+0] = (float)mean;
        g_stats[(g*64+ch)*2+1] = (float)(1.0/sqrt(var + 1e-5));
    }
}

// ---------- BN + LeakyReLU (+pool) ----------
__global__ void bn_pool_kernel(int inSel, int outSel, const float* __restrict__ gamma,
                               const float* __restrict__ beta, int H, int W, int doPool)
{
    const int oH = doPool ? H/2 : H, oW = doPool ? W/2 : W;
    const size_t total = (size_t)NALL*64*oH*oW;
    const float* in = bufPtr(inSel);
    float* out = bufPtr(outSel);
    for (size_t idx = (size_t)blockIdx.x*blockDim.x + threadIdx.x; idx < total;
         idx += (size_t)gridDim.x*blockDim.x) {
        int ox = (int)(idx % oW); size_t t = idx / oW;
        int oy = (int)(t % oH);   t /= oH;
        int c  = (int)(t % 64);   int n = (int)(t / 64);
        int g = groupOf(n);
        float mean = g_stats[(g*64+c)*2+0], rsig = g_stats[(g*64+c)*2+1];
        float sc = gamma[c]*rsig;
        float sh = beta[c] - mean*sc;
        const float* p = in + ((size_t)n*64+c)*H*W;
        float r;
        if (doPool){
            float x0 = p[(size_t)(2*oy)*W + 2*ox  ]*sc+sh;
            float x1 = p[(size_t)(2*oy)*W + 2*ox+1]*sc+sh;
            float x2 = p[(size_t)(2*oy+1)*W + 2*ox  ]*sc+sh;
            float x3 = p[(size_t)(2*oy+1)*W + 2*ox+1]*sc+sh;
            x0 = x0>=0.f?x0:0.2f*x0; x1 = x1>=0.f?x1:0.2f*x1;
            x2 = x2>=0.f?x2:0.2f*x2; x3 = x3>=0.f?x3:0.2f*x3;
            r = fmaxf(fmaxf(x0,x1), fmaxf(x2,x3));
        } else {
            float x = p[(size_t)oy*W+ox]*sc+sh;
            r = x>=0.f?x:0.2f*x;
        }
        out[idx] = r;
    }
}

// ---------- descriptor inverse norms ----------
__global__ void norm_kernel()
{
    int img = blockIdx.x;
    for (int p = threadIdx.x; p < PP; p += blockDim.x){
        float ss = 0.f;
        const float* f = g_bufD + (size_t)img*64*PP + p;
#pragma unroll
        for (int c=0;c<64;c++){ float x = f[(size_t)c*PP]; ss += x*x; }
        g_rinv[(size_t)img*PP + p] = rsqrtf(ss);
    }
}

// ---------- stage1 fp32 k-major unlabeled rows ----------
__global__ void flatT_kernel()
{
    const size_t total = (size_t)64*UPAD;
    for (size_t idx = (size_t)blockIdx.x*blockDim.x + threadIdx.x; idx < total;
         idx += (size_t)gridDim.x*blockDim.x) {
        int row = (int)(idx % UPAD); int k = (int)(idx / UPAD);
        float v = 0.f;
        if (row < UROWS){
            int im = row / PP, p = row % PP;
            int img = NQ + NS + im;
            v = g_bufD[((size_t)img*64+k)*PP + p] * g_rinv[(size_t)img*PP + p];
        }
        g_ukT[idx] = v;
    }
}

// ---------- stage1 fp32 support bank ----------
__global__ void fillT_support_kernel()
{
    const size_t total = (size_t)KCLS*64*MSUP;
    for (size_t i = (size_t)blockIdx.x*blockDim.x + threadIdx.x; i < total;
         i += (size_t)gridDim.x*blockDim.x) {
        int col = (int)(i % MSUP); size_t t = i / MSUP;
        int k = (int)(t % 64); int j = (int)(t / 64);
        int s = col / PP, p = col % PP;
        int img = NQ + j*SHOT + s;
        g_bankT[((size_t)j*64+k)*BCOLS + col] =
            g_bufD[((size_t)img*64+k)*PP + p] * g_rinv[(size_t)img*PP + p];
    }
}

// ---------- stage2 bf16 buffers ----------
__global__ void fillbf_q_kernel()
{
    const size_t total = (size_t)QPAD*64;
    for (size_t i = (size_t)blockIdx.x*blockDim.x + threadIdx.x; i < total;
         i += (size_t)gridDim.x*blockDim.x) {
        int k = (int)(i & 63); int row = (int)(i >> 6);
        float v = 0.f;
        if (row < QROWS){
            int img = row / PP, p = row % PP;
            v = g_bufD[((size_t)img*64+k)*PP + p] * g_rinv[(size_t)img*PP + p];
        }
        g_qbf[i] = __float2bfloat16(v);
    }
}
__global__ void fillbf_support_kernel()
{
    const size_t total = (size_t)KCLS*BCOLS*64;
    for (size_t i = (size_t)blockIdx.x*blockDim.x + threadIdx.x; i < total;
         i += (size_t)gridDim.x*blockDim.x) {
        int k = (int)(i & 63); size_t t = i >> 6;
        int col = (int)(t % BCOLS); int j = (int)(t / BCOLS);
        if (col < MSUP){
            int s = col / PP, p = col % PP;
            int img = NQ + j*SHOT + s;
            g_bankbf[i] = __float2bfloat16(
                g_bufD[((size_t)img*64+k)*PP + p] * g_rinv[(size_t)img*PP + p]);
        } else if (col >= MAUG){
            g_bankbf[i] = __float2bfloat16(0.f);
        }
    }
}
__global__ void fillbf_aug_kernel()
{
    const size_t total = (size_t)KCLS*(SELN*PP)*64;
    for (size_t i = (size_t)blockIdx.x*blockDim.x + threadIdx.x; i < total;
         i += (size_t)gridDim.x*blockDim.x) {
        int k = (int)(i & 63); size_t t = i >> 6;
        int a = (int)(t % (SELN*PP)); int j = (int)(t / (SELN*PP));
        int sel = a / PP, p = a % PP;
        int img = NQ + NS + g_selidx[j*SELN + sel];
        g_bankbf[(((size_t)j*BCOLS) + MSUP + a)*64 + k] = __float2bfloat16(
            g_bufD[((size_t)img*64+k)*PP + p] * g_rinv[(size_t)img*PP + p]);
    }
}

// ---------- stage1 top-3-fused SIMT GEMM (fp32, exact) ----------
__global__ void __launch_bounds__(256) topk_gemm_kernel(int aStride, int nrows, int cols)
{
    extern __shared__ float sm[];
    float* As = sm;
    float* Bs = sm + 8192;
    const float* aT = g_ukT;
    const int tid = threadIdx.x;
    const int txc = tid & 15;
    const int tyr = tid >> 4;
    const int rowg = tyr*8, colg = txc*8;
    const int cls = blockIdx.y;
    const int row0 = blockIdx.x*128;
    const int ntiles = (cols + 127)/128;

    const float* aSrc = aT + row0;
    const float* bSrc = g_bankT + (size_t)cls*64*BCOLS;
    uint32_t sAs = (uint32_t)__cvta_generic_to_shared(As);
    uint32_t sBs = (uint32_t)__cvta_generic_to_shared(Bs);

    for (int c = tid; c < 2048; c += 256) {
        int k = c >> 5, off = (c & 31)*4;
        cpasync16(sAs + (uint32_t)(k*128 + off)*4, aSrc + (size_t)k*aStride + off);
    }
    for (int c = tid; c < 2048; c += 256) {
        int k = c >> 5, off = (c & 31)*4;
        cpasync16(sBs + (uint32_t)(k*128 + off)*4, bSrc + (size_t)k*BCOLS + off);
    }
    CP_COMMIT();
    CP_WAIT0();
    __syncthreads();

    float t0[8], t1[8], t2[8];
#pragma unroll
    for (int r=0;r<8;r++){ t0[r]=NEGINF; t1[r]=NEGINF; t2[r]=NEGINF; }

    for (int t=0; t<ntiles; t++){
        if (t+1 < ntiles){
            const float* bN = bSrc + (t+1)*128;
            uint32_t dBuf = sBs + (uint32_t)(((t+1)&1)*8192)*4;
            for (int c = tid; c < 2048; c += 256) {
                int k = c >> 5, off = (c & 31)*4;
                cpasync16(dBuf + (uint32_t)(k*128 + off)*4, bN + (size_t)k*BCOLS + off);
            }
            CP_COMMIT();
        }
        const float* Bp = Bs + (t&1)*8192;
        float acc[8][8];
#pragma unroll
        for (int r=0;r<8;r++)
#pragma unroll
          for (int c=0;c<8;c++) acc[r][c]=0.f;
#pragma unroll 2
        for (int k=0;k<64;k++){
            float4 a0 = *(const float4*)(As + k*128 + rowg);
            float4 a1 = *(const float4*)(As + k*128 + rowg + 4);
            float4 b0 = *(const float4*)(Bp + k*128 + colg);
            float4 b1 = *(const float4*)(Bp + k*128 + colg + 4);
            float av[8] = {a0.x,a0.y,a0.z,a0.w,a1.x,a1.y,a1.z,a1.w};
            float bv[8] = {b0.x,b0.y,b0.z,b0.w,b1.x,b1.y,b1.z,b1.w};
#pragma unroll
            for (int r=0;r<8;r++)
#pragma unroll
              for (int c=0;c<8;c++) acc[r][c] += av[r]*bv[c];
        }
        const int colbase = t*128 + colg;
#pragma unroll
        for (int c=0;c<8;c++){
            bool ok = (colbase + c) < cols;
#pragma unroll
            for (int r=0;r<8;r++){
                float v = ok ? acc[r][c] : NEGINF;
                if (v > t2[r]) {
                    if (v > t0[r]) { t2[r]=t1[r]; t1[r]=t0[r]; t0[r]=v; }
                    else if (v > t1[r]) { t2[r]=t1[r]; t1[r]=v; }
                    else t2[r]=v;
                }
            }
        }
        if (t+1 < ntiles) CP_WAIT0();
        __syncthreads();
    }

    float* M = sm;
#pragma unroll
    for (int r=0;r<8;r++){
        int row = rowg + r;
        M[(row*16+txc)*3+0] = t0[r];
        M[(row*16+txc)*3+1] = t1[r];
        M[(row*16+txc)*3+2] = t2[r];
    }
    __syncthreads();
    if (tid < 128){
        float u0=NEGINF, u1=NEGINF, u2=NEGINF;
        const float* m = M + (size_t)tid*48;
        for (int j=0;j<48;j++){
            float v = m[j];
            if (v > u2){
                if (v > u0){ u2=u1; u1=u0; u0=v; }
                else if (v > u1){ u2=u1; u1=v; }
                else u2=v;
            }
        }
        int row = row0 + tid;
        if (row < nrows)
            g_rowsum[(size_t)cls*QPAD + row] = u0+u1+u2;
    }
}

// ---------- stage2: wmma bf16 HMMA GEMM + fused top-3 ----------
// grid (QPAD/128, KCLS), block 256 (8 warps), dyn smem 116736B
__global__ void __launch_bounds__(256) wmma_topk_kernel()
{
    extern __shared__ char smc[];
    __nv_bfloat16* As = (__nv_bfloat16*)smc;             // [128][64]    16KB
    __nv_bfloat16* Bs = (__nv_bfloat16*)(smc + 16384);   // [2][128][64] 32KB
    float*         Cs = (float*)(smc + 16384 + 32768);   // [128][132]   67584B
    const int tid = threadIdx.x;
    const int wid = tid >> 5;
    const int cls = blockIdx.y;
    const int row0 = blockIdx.x*128;

    uint32_t sA = (uint32_t)__cvta_generic_to_shared(As);
    uint32_t sB = (uint32_t)__cvta_generic_to_shared(Bs);

    const char* aG = (const char*)g_qbf + (size_t)row0*128;
    for (int c = tid; c < 1024; c += 256) cpasync16(sA + (uint32_t)c*16, aG + (size_t)c*16);
    const char* bG = (const char*)g_bankbf + (size_t)cls*BCOLS*128;
    for (int c = tid; c < 1024; c += 256) cpasync16(sB + (uint32_t)c*16, bG + (size_t)c*16);
    CP_COMMIT(); CP_WAIT0();
    __syncthreads();

    // A fragments for this warp's 16 rows, one per k-step; loaded once
    wmma::fragment<wmma::matrix_a, 16,16,16, __nv_bfloat16, wmma::row_major> afrag[4];
#pragma unroll
    for (int k = 0; k < 4; k++)
        wmma::load_matrix_sync(afrag[k], As + (wid*16)*64 + k*16, 64);

    // per-thread running top3 for (row = tid&127, half = tid>>7)
    float t0=NEGINF, t1=NEGINF, t2=NEGINF;
    const int srow = tid & 127, shalf = tid >> 7;

    for (int t = 0; t < CTILES2; t++){
        if (t+1 < CTILES2){
            const char* bN = bG + (size_t)(t+1)*CT2*128;
            uint32_t bb = sB + (uint32_t)(((t+1)&1)*16384);
            for (int c = tid; c < 1024; c += 256) cpasync16(bb + (uint32_t)c*16, bN + (size_t)c*16);
            CP_COMMIT();
        }
        const __nv_bfloat16* Bp = Bs + (t&1)*8192;
#pragma unroll
        for (int n = 0; n < 8; n++){
            wmma::fragment<wmma::accumulator, 16,16,16, float> cfrag;
            wmma::fill_fragment(cfrag, 0.f);
#pragma unroll
            for (int k = 0; k < 4; k++){
                wmma::fragment<wmma::matrix_b, 16,16,16, __nv_bfloat16, wmma::col_major> bfrag;
                wmma::load_matrix_sync(bfrag, Bp + (n*16)*64 + k*16, 64);
                wmma::mma_sync(cfrag, afrag[k], bfrag, cfrag);
            }
            wmma::store_matrix_sync(Cs + (wid*16)*132 + n*16, cfrag, 132, wmma::mem_row_major);
        }
        __syncthreads();
        {
            const float* cr = Cs + srow*132 + shalf*64;
            const int colb = t*CT2 + shalf*64;
#pragma unroll 8
            for (int j = 0; j < 64; j++){
                float v = (colb + j < MAUG) ? cr[j] : NEGINF;
                if (v > t2){
                    if (v > t0){ t2=t1; t1=t0; t0=v; }
                    else if (v > t1){ t2=t1; t1=v; }
                    else t2=v;
                }
            }
        }
        if (t+1 < CTILES2) CP_WAIT0();
        __syncthreads();
    }

    // merge the two halves of each row
    float* M = Cs;
    M[tid*3+0]=t0; M[tid*3+1]=t1; M[tid*3+2]=t2;
    __syncthreads();
    if (tid < 128){
        float u0=NEGINF, u1=NEGINF, u2=NEGINF;
        const float* m0 = M + (size_t)tid*3;
        const float* m1 = M + (size_t)(tid+128)*3;
#pragma unroll
        for (int j=0;j<6;j++){
            float v = (j<3) ? m0[j] : m1[j-3];
            if (v > u2){
                if (v > u0){ u2=u1; u1=u0; u0=v; }
                else if (v > u1){ u2=u1; u1=v; }
                else u2=v;
            }
        }
        int row = row0 + tid;
        if (row < QROWS) g_rowsum[(size_t)cls*QPAD + row] = u0+u1+u2;
    }
}

// ---------- per-image deterministic sum ----------
__global__ void imgsum_kernel(float* __restrict__ outp, int useOut)
{
    __shared__ float s[128];
    const int img = blockIdx.x, cls = blockIdx.y;
    const int tid = threadIdx.x;
    const float* src = g_rowsum + (size_t)cls*QPAD + (size_t)img*PP;
    float v = 0.f;
    for (int i = tid; i < PP; i += 128) v += src[i];
    s[tid] = v; __syncthreads();
    for (int st=64; st>0; st>>=1){
        if (tid < st) s[tid] += s[tid+st];
        __syncthreads();
    }
    if (tid==0){
        float* dst = useOut ? outp : g_simu;
        dst[img*KCLS + cls] = s[0];
    }
}

// ---------- softmax + per-class top-10 (lowest-index ties) ----------
__global__ void select_kernel()
{
    __shared__ float pm[NU*KCLS];
    int tid = threadIdx.x;
    if (tid < NU){
        float v[KCLS]; float mx = NEGINF;
#pragma unroll
        for (int j=0;j<KCLS;j++){ v[j] = g_simu[tid*KCLS+j]; mx = fmaxf(mx, v[j]); }
        float s = 0.f;
#pragma unroll
        for (int j=0;j<KCLS;j++){ v[j] = expf(v[j]-mx); s += v[j]; }
#pragma unroll
        for (int j=0;j<KCLS;j++) pm[tid*KCLS+j] = v[j]/s;
    }
    __syncthreads();
    if (tid < KCLS){
        unsigned long long taken = 0ull;
        for (int i=0;i<SELN;i++){
            float best = NEGINF; int bi = 0;
            for (int b=0;b<NU;b++){
                if (taken & (1ull<<b)) continue;
                float val = pm[b*KCLS+tid];
                if (val > best){ best = val; bi = b; }
            }
            taken |= (1ull<<bi);
            g_selidx[tid*SELN+i] = bi;
        }
    }
}

extern "C" void kernel_launch(void* const* d_in, const int* in_sizes, int n_in,
                              void* d_out, int out_size)
{
    (void)in_sizes; (void)n_in; (void)out_size;
    // dict order: input1..3, w1, w2, w3, w4, g1, b1, g2, b2, g3, b3, g4, b4
    const float* in1 = (const float*)d_in[0];
    const float* in2 = (const float*)d_in[1];
    const float* in3 = (const float*)d_in[2];
    const float* w1  = (const float*)d_in[3];
    const float* w2  = (const float*)d_in[4];
    const float* w3  = (const float*)d_in[5];
    const float* w4  = (const float*)d_in[6];
    const float* gg1 = (const float*)d_in[7];
    const float* bb1 = (const float*)d_in[8];
    const float* gg2 = (const float*)d_in[9];
    const float* bb2 = (const float*)d_in[10];
    const float* gg3 = (const float*)d_in[11];
    const float* bb3 = (const float*)d_in[12];
    const float* gg4 = (const float*)d_in[13];
    const float* bb4 = (const float*)d_in[14];
    float* out = (float*)d_out;

    const int SM3 = (36864 + 16*(50*18))*4;
    const int SM2 = (36864 + 16*(34*18))*4;
    const int SMG = (8192 + 16384)*4;           // 96KB  (stage1)
    const int SMW = 16384 + 32768 + 128*132*4;  // 116736B (stage2 wmma)
    cudaFuncSetAttribute(conv64_kernel<3>, cudaFuncAttributeMaxDynamicSharedMemorySize, SM3);
    cudaFuncSetAttribute(conv64_kernel<2>, cudaFuncAttributeMaxDynamicSharedMemorySize, SM2);
    cudaFuncSetAttribute(topk_gemm_kernel,  cudaFuncAttributeMaxDynamicSharedMemorySize, SMG);
    cudaFuncSetAttribute(wmma_topk_kernel,  cudaFuncAttributeMaxDynamicSharedMemorySize, SMW);

    dim3 blk(16,16);
    conv1_kernel<<<dim3(6,6,NALL), blk>>>(in1, in2, in3, w1);
    bn_stats_kernel<<<dim3(64,3), 256>>>(0, H1*H1);
    bn_pool_kernel<<<2048, 256>>>(0, 1, gg1, bb1, H1, H1, 1);
    conv64_kernel<3><<<dim3(3,1,NALL), blk, SM3>>>(1, 2, w2, H2, H2);
    bn_stats_kernel<<<dim3(64,3), 256>>>(2, H2*H2);
    bn_pool_kernel<<<2048, 256>>>(2, 3, gg2, bb2, H2, H2, 1);
    conv64_kernel<2><<<dim3(2,1,NALL), blk, SM2>>>(3, 4, w3, H3, H3);
    bn_stats_kernel<<<dim3(64,3), 256>>>(4, H3*H3);
    bn_pool_kernel<<<2048, 256>>>(4, 3, gg3, bb3, H3, H3, 0);
    conv64_kernel<2><<<dim3(2,1,NALL), blk, SM2>>>(3, 4, w4, H3, H3);
    bn_stats_kernel<<<dim3(64,3), 256>>>(4, H3*H3);
    bn_pool_kernel<<<2048, 256>>>(4, 3, gg4, bb4, H3, H3, 0);   // final feats in D

    norm_kernel<<<NALL, 256>>>();
    flatT_kernel<<<2048, 256>>>();
    fillT_support_kernel<<<2048, 256>>>();
    fillbf_q_kernel<<<2048, 256>>>();
    fillbf_support_kernel<<<2048, 256>>>();

    // stage 1: unlabeled rows vs support banks (fp32, exact selection)
    topk_gemm_kernel<<<dim3(UPAD/128, KCLS), 256, SMG>>>(UPAD, UROWS, MSUP);
    imgsum_kernel<<<dim3(NU, KCLS), 128>>>(nullptr, 0);
    select_kernel<<<1, 64>>>();
    fillbf_aug_kernel<<<2048, 256>>>();

    // stage 2: query rows vs augmented banks via wmma bf16 -> out [75,5]
    wmma_topk_kernel<<<dim3(QPAD/128, KCLS), 256, SMW>>>();
    imgsum_kernel<<<dim3(NQ, KCLS), 128>>>(out, 1);
}

// round 9
// speedup vs baseline: 2.2762x; 1.3690x over previous
#include <cuda_runtime.h>
#include <cuda_bf16.h>
#include <math.h>
#include <stdint.h>

#define NQ 75
#define NS 25
#define NU 64
#define NALL 164
#define H1 84
#define H2 42
#define H3 21
#define PP 441
#define KCLS 5
#define SHOT 5
#define MSUP (SHOT*PP)          // 2205
#define MAUG (MSUP + 10*PP)     // 6615
#define BCOLS 6656              // 52*128
#define QROWS (NQ*PP)           // 33075
#define QPAD  33152             // 259*128
#define UROWS (NU*PP)           // 28224
#define UPAD  28288             // 221*128
#define SELN 10
#define NEGINF -3.4e38f
#define CT2 128
#define CTILES2 (BCOLS/CT2)     // 52
#define BROW 144                // padded smem row bytes (conflict-free)

__device__ float g_bufA[(size_t)NALL*64*H1*H1];
__device__ float g_bufC[(size_t)NALL*64*H2*H2];
__device__ float g_bufD[(size_t)NALL*64*H3*H3];
__device__ float g_bufE[(size_t)NALL*64*H3*H3];
__device__ float g_bufB[(size_t)NALL*64*H2*H2];
__device__ float g_rinv[(size_t)NALL*PP];
__device__ float g_ukT[(size_t)64*UPAD];                 // [k][row] fp32 stage1
__device__ float g_bankT[(size_t)KCLS*64*BCOLS];         // [cls][k][col] fp32 stage1
__device__ __nv_bfloat16 g_qbf[(size_t)QPAD*64];         // [row][k] bf16 stage2 A
__device__ __nv_bfloat16 g_bankbf[(size_t)KCLS*BCOLS*64];// [cls][col][k] bf16 stage2 B
__device__ float g_rowsum[(size_t)KCLS*QPAD];
__device__ float g_stats[3*64*2];
__device__ float g_simu[NU*KCLS];
__device__ int   g_selidx[KCLS*SELN];

__device__ __forceinline__ float* bufPtr(int s){
    switch(s){
        case 0: return g_bufA; case 1: return g_bufB; case 2: return g_bufC;
        case 3: return g_bufD; default: return g_bufE;
    }
}
__device__ __forceinline__ int groupOf(int n){ return (n < NQ) ? 0 : ((n < NQ+NS) ? 1 : 2); }

__device__ __forceinline__ void cpasync16(uint32_t dst, const void* src){
    asm volatile("cp.async.cg.shared.global [%0], [%1], 16;\n" :: "r"(dst), "l"(src));
}
#define CP_COMMIT() asm volatile("cp.async.commit_group;\n" ::: "memory")
#define CP_WAIT0()  asm volatile("cp.async.wait_group 0;\n" ::: "memory")

__device__ __forceinline__ void ins3(float v, float& t0, float& t1, float& t2){
    if (v > t2){
        if (v > t0){ t2 = t1; t1 = t0; t0 = v; }
        else if (v > t1){ t2 = t1; t1 = v; }
        else t2 = v;
    }
}

// ---------- conv1: 3->64, 84x84 SAME ----------
__global__ void conv1_kernel(const float* __restrict__ in1, const float* __restrict__ in2,
                             const float* __restrict__ in3, const float* __restrict__ w)
{
    __shared__ float sW[64*27];
    __shared__ float sIn[3*18*18];
    const int n = blockIdx.z;
    const int gx0 = blockIdx.x*16, gy0 = blockIdx.y*16;
    const int tx = threadIdx.x, ty = threadIdx.y;
    const int tid = ty*16 + tx;
    const float* img = (n < NQ)    ? (in1 + (size_t)n*3*H1*H1)
                     : (n < NQ+NS) ? (in2 + (size_t)(n-NQ)*3*H1*H1)
                                   : (in3 + (size_t)(n-NQ-NS)*3*H1*H1);
    for (int i = tid; i < 64*27; i += 256) sW[i] = w[i];
    for (int i = tid; i < 3*18*18; i += 256) {
        int c = i / 324, rem = i % 324, r = rem/18, cc = rem%18;
        int gy = gy0 - 1 + r, gx = gx0 - 1 + cc;
        sIn[i] = (gy>=0 && gy<H1 && gx>=0 && gx<H1) ? img[((size_t)c*H1+gy)*H1+gx] : 0.f;
    }
    __syncthreads();
    int ox = gx0+tx, oy = gy0+ty;
    if (ox >= H1 || oy >= H1) return;
    float v[27];
#pragma unroll
    for (int c=0;c<3;c++)
#pragma unroll
      for (int dy=0;dy<3;dy++)
#pragma unroll
        for (int dx=0;dx<3;dx++)
          v[c*9+dy*3+dx] = sIn[c*324 + (ty+dy)*18 + (tx+dx)];
#pragma unroll 4
    for (int oc=0; oc<64; oc++){
        float acc = 0.f;
        const float* wp = sW + oc*27;
#pragma unroll
        for (int j=0;j<27;j++) acc += wp[j]*v[j];
        g_bufA[(((size_t)n*64+oc)*H1+oy)*H1+ox] = acc;
    }
}

// ---------- conv 64->64 3x3 SAME ----------
template<int RPT>
__global__ void conv64_kernel(int inSel, int outSel, const float* __restrict__ wt, int H, int W)
{
    extern __shared__ float sm[];
    float* sW  = sm;
    float* sIn = sm + 36864;
    constexpr int TH   = 16*RPT;
    constexpr int HALO = (TH+2)*18;
    const int n   = blockIdx.z;
    const int gx0 = blockIdx.x*16;
    const int gy0 = blockIdx.y*TH;
    const int tx = threadIdx.x, ty = threadIdx.y;
    const int tid = ty*16 + tx;
    for (int i = tid; i < 64*64*9; i += 256) sW[i] = wt[i];
    const int oyb = gy0 + ty*RPT;
    const int ox  = gx0 + tx;
    const bool anyValid = (ox < W) && (oyb < H);
    const float* inN  = bufPtr(inSel)  + (size_t)n*64*H*W;
    float*       outN = bufPtr(outSel) + (size_t)n*64*H*W;

    for (int ocg = 0; ocg < 4; ++ocg) {
        float acc[16][RPT];
#pragma unroll
        for (int o=0;o<16;o++)
#pragma unroll
          for (int r=0;r<RPT;r++) acc[o][r]=0.f;
        for (int cc = 0; cc < 4; ++cc) {
            __syncthreads();
            for (int i = tid; i < 16*HALO; i += 256) {
                int c = i / HALO, rem = i % HALO, r = rem/18, col = rem%18;
                int gy = gy0-1+r, gx = gx0-1+col;
                float v = 0.f;
                if (gy>=0 && gy<H && gx>=0 && gx<W)
                    v = inN[((size_t)(cc*16+c)*H+gy)*W+gx];
                sIn[i] = v;
            }
            __syncthreads();
            if (anyValid) {
                for (int ic=0; ic<16; ++ic) {
                    float v[RPT+2][3];
                    const float* sp = sIn + ic*HALO + (ty*RPT)*18 + tx;
#pragma unroll
                    for (int r=0;r<RPT+2;r++)
#pragma unroll
                      for (int d=0;d<3;d++) v[r][d] = sp[r*18+d];
                    const float* wp = sW + (size_t)(ocg*16)*576 + (cc*16+ic)*9;
#pragma unroll
                    for (int o=0;o<16;o++){
                        const float* wo = wp + o*576;
                        float w0=wo[0],w1=wo[1],w2=wo[2],w3=wo[3],w4=wo[4];
                        float w5=wo[5],w6=wo[6],w7=wo[7],w8=wo[8];
#pragma unroll
                        for (int r=0;r<RPT;r++){
                            float a = acc[o][r];
                            a += w0*v[r  ][0]; a += w1*v[r  ][1]; a += w2*v[r  ][2];
                            a += w3*v[r+1][0]; a += w4*v[r+1][1]; a += w5*v[r+1][2];
                            a += w6*v[r+2][0]; a += w7*v[r+2][1]; a += w8*v[r+2][2];
                            acc[o][r] = a;
                        }
                    }
                }
            }
        }
        if (anyValid) {
#pragma unroll
            for (int o=0;o<16;o++){
                int oc = ocg*16+o;
#pragma unroll
                for (int r=0;r<RPT;r++){
                    int oy = oyb + r;
                    if (oy < H) outN[((size_t)oc*H+oy)*W+ox] = acc[o][r];
                }
            }
        }
    }
}

// ---------- BN stats ----------
__global__ void bn_stats_kernel(int sel, int HW)
{
    __shared__ double ssum[256], ssum2[256];
    const int ch = blockIdx.x, g = blockIdx.y;
    const int n0 = (g==0)?0:((g==1)?NQ:(NQ+NS));
    const int n1 = (g==0)?NQ:((g==1)?(NQ+NS):NALL);
    const int tid = threadIdx.x;
    const float* buf = bufPtr(sel);
    double s=0.0, s2=0.0;
    for (int n=n0; n<n1; ++n) {
        const float* p = buf + ((size_t)n*64+ch)*HW;
        for (int i=tid;i<HW;i+=256){ double x = (double)p[i]; s+=x; s2+=x*x; }
    }
    ssum[tid]=s; ssum2[tid]=s2; __syncthreads();
    for (int st=128; st>0; st>>=1){
        if (tid<st){ ssum[tid]+=ssum[tid+st]; ssum2[tid]+=ssum2[tid+st]; }
        __syncthreads();
    }
    if (tid==0){
        double cnt = (double)(n1-n0)*HW;
        double mean = ssum[0]/cnt;
        double var  = ssum2[0]/cnt - mean*mean;
        g_stats[(g*64+ch)*2+0] = (float)mean;
        g_stats[(g*64+ch)*2+1] = (float)(1.0/sqrt(var + 1e-5));
    }
}

// ---------- BN + LeakyReLU (+pool) ----------
__global__ void bn_pool_kernel(int inSel, int outSel, const float* __restrict__ gamma,
                               const float* __restrict__ beta, int H, int W, int doPool)
{
    const int oH = doPool ? H/2 : H, oW = doPool ? W/2 : W;
    const size_t total = (size_t)NALL*64*oH*oW;
    const float* in = bufPtr(inSel);
    float* out = bufPtr(outSel);
    for (size_t idx = (size_t)blockIdx.x*blockDim.x + threadIdx.x; idx < total;
         idx += (size_t)gridDim.x*blockDim.x) {
        int ox = (int)(idx % oW); size_t t = idx / oW;
        int oy = (int)(t % oH);   t /= oH;
        int c  = (int)(t % 64);   int n = (int)(t / 64);
        int g = groupOf(n);
        float mean = g_stats[(g*64+c)*2+0], rsig = g_stats[(g*64+c)*2+1];
        float sc = gamma[c]*rsig;
        float sh = beta[c] - mean*sc;
        const float* p = in + ((size_t)n*64+c)*H*W;
        float r;
        if (doPool){
            float x0 = p[(size_t)(2*oy)*W + 2*ox  ]*sc+sh;
            float x1 = p[(size_t)(2*oy)*W + 2*ox+1]*sc+sh;
            float x2 = p[(size_t)(2*oy+1)*W + 2*ox  ]*sc+sh;
            float x3 = p[(size_t)(2*oy+1)*W + 2*ox+1]*sc+sh;
            x0 = x0>=0.f?x0:0.2f*x0; x1 = x1>=0.f?x1:0.2f*x1;
            x2 = x2>=0.f?x2:0.2f*x2; x3 = x3>=0.f?x3:0.2f*x3;
            r = fmaxf(fmaxf(x0,x1), fmaxf(x2,x3));
        } else {
            float x = p[(size_t)oy*W+ox]*sc+sh;
            r = x>=0.f?x:0.2f*x;
        }
        out[idx] = r;
    }
}

// ---------- descriptor inverse norms ----------
__global__ void norm_kernel()
{
    int img = blockIdx.x;
    for (int p = threadIdx.x; p < PP; p += blockDim.x){
        float ss = 0.f;
        const float* f = g_bufD + (size_t)img*64*PP + p;
#pragma unroll
        for (int c=0;c<64;c++){ float x = f[(size_t)c*PP]; ss += x*x; }
        g_rinv[(size_t)img*PP + p] = rsqrtf(ss);
    }
}

// ---------- stage1 fp32 k-major unlabeled rows ----------
__global__ void flatT_kernel()
{
    const size_t total = (size_t)64*UPAD;
    for (size_t idx = (size_t)blockIdx.x*blockDim.x + threadIdx.x; idx < total;
         idx += (size_t)gridDim.x*blockDim.x) {
        int row = (int)(idx % UPAD); int k = (int)(idx / UPAD);
        float v = 0.f;
        if (row < UROWS){
            int im = row / PP, p = row % PP;
            int img = NQ + NS + im;
            v = g_bufD[((size_t)img*64+k)*PP + p] * g_rinv[(size_t)img*PP + p];
        }
        g_ukT[idx] = v;
    }
}

// ---------- stage1 fp32 support bank ----------
__global__ void fillT_support_kernel()
{
    const size_t total = (size_t)KCLS*64*MSUP;
    for (size_t i = (size_t)blockIdx.x*blockDim.x + threadIdx.x; i < total;
         i += (size_t)gridDim.x*blockDim.x) {
        int col = (int)(i % MSUP); size_t t = i / MSUP;
        int k = (int)(t % 64); int j = (int)(t / 64);
        int s = col / PP, p = col % PP;
        int img = NQ + j*SHOT + s;
        g_bankT[((size_t)j*64+k)*BCOLS + col] =
            g_bufD[((size_t)img*64+k)*PP + p] * g_rinv[(size_t)img*PP + p];
    }
}

// ---------- stage2 bf16 buffers ----------
__global__ void fillbf_q_kernel()
{
    const size_t total = (size_t)QPAD*64;
    for (size_t i = (size_t)blockIdx.x*blockDim.x + threadIdx.x; i < total;
         i += (size_t)gridDim.x*blockDim.x) {
        int k = (int)(i & 63); int row = (int)(i >> 6);
        float v = 0.f;
        if (row < QROWS){
            int img = row / PP, p = row % PP;
            v = g_bufD[((size_t)img*64+k)*PP + p] * g_rinv[(size_t)img*PP + p];
        }
        g_qbf[i] = __float2bfloat16(v);
    }
}
__global__ void fillbf_support_kernel()
{
    const size_t total = (size_t)KCLS*BCOLS*64;
    for (size_t i = (size_t)blockIdx.x*blockDim.x + threadIdx.x; i < total;
         i += (size_t)gridDim.x*blockDim.x) {
        int k = (int)(i & 63); size_t t = i >> 6;
        int col = (int)(t % BCOLS); int j = (int)(t / BCOLS);
        if (col < MSUP){
            int s = col / PP, p = col % PP;
            int img = NQ + j*SHOT + s;
            g_bankbf[i] = __float2bfloat16(
                g_bufD[((size_t)img*64+k)*PP + p] * g_rinv[(size_t)img*PP + p]);
        } else if (col >= MAUG){
            g_bankbf[i] = __float2bfloat16(0.f);
        }
    }
}
__global__ void fillbf_aug_kernel()
{
    const size_t total = (size_t)KCLS*(SELN*PP)*64;
    for (size_t i = (size_t)blockIdx.x*blockDim.x + threadIdx.x; i < total;
         i += (size_t)gridDim.x*blockDim.x) {
        int k = (int)(i & 63); size_t t = i >> 6;
        int a = (int)(t % (SELN*PP)); int j = (int)(t / (SELN*PP));
        int sel = a / PP, p = a % PP;
        int img = NQ + NS + g_selidx[j*SELN + sel];
        g_bankbf[(((size_t)j*BCOLS) + MSUP + a)*64 + k] = __float2bfloat16(
            g_bufD[((size_t)img*64+k)*PP + p] * g_rinv[(size_t)img*PP + p]);
    }
}

// ---------- stage1 top-3-fused SIMT GEMM (fp32, exact) ----------
__global__ void __launch_bounds__(256) topk_gemm_kernel(int aStride, int nrows, int cols)
{
    extern __shared__ float sm[];
    float* As = sm;
    float* Bs = sm + 8192;
    const float* aT = g_ukT;
    const int tid = threadIdx.x;
    const int txc = tid & 15;
    const int tyr = tid >> 4;
    const int rowg = tyr*8, colg = txc*8;
    const int cls = blockIdx.y;
    const int row0 = blockIdx.x*128;
    const int ntiles = (cols + 127)/128;

    const float* aSrc = aT + row0;
    const float* bSrc = g_bankT + (size_t)cls*64*BCOLS;
    uint32_t sAs = (uint32_t)__cvta_generic_to_shared(As);
    uint32_t sBs = (uint32_t)__cvta_generic_to_shared(Bs);

    for (int c = tid; c < 2048; c += 256) {
        int k = c >> 5, off = (c & 31)*4;
        cpasync16(sAs + (uint32_t)(k*128 + off)*4, aSrc + (size_t)k*aStride + off);
    }
    for (int c = tid; c < 2048; c += 256) {
        int k = c >> 5, off = (c & 31)*4;
        cpasync16(sBs + (uint32_t)(k*128 + off)*4, bSrc + (size_t)k*BCOLS + off);
    }
    CP_COMMIT();
    CP_WAIT0();
    __syncthreads();

    float t0[8], t1[8], t2[8];
#pragma unroll
    for (int r=0;r<8;r++){ t0[r]=NEGINF; t1[r]=NEGINF; t2[r]=NEGINF; }

    for (int t=0; t<ntiles; t++){
        if (t+1 < ntiles){
            const float* bN = bSrc + (t+1)*128;
            uint32_t dBuf = sBs + (uint32_t)(((t+1)&1)*8192)*4;
            for (int c = tid; c < 2048; c += 256) {
                int k = c >> 5, off = (c & 31)*4;
                cpasync16(dBuf + (uint32_t)(k*128 + off)*4, bN + (size_t)k*BCOLS + off);
            }
            CP_COMMIT();
        }
        const float* Bp = Bs + (t&1)*8192;
        float acc[8][8];
#pragma unroll
        for (int r=0;r<8;r++)
#pragma unroll
          for (int c=0;c<8;c++) acc[r][c]=0.f;
#pragma unroll 2
        for (int k=0;k<64;k++){
            float4 a0 = *(const float4*)(As + k*128 + rowg);
            float4 a1 = *(const float4*)(As + k*128 + rowg + 4);
            float4 b0 = *(const float4*)(Bp + k*128 + colg);
            float4 b1 = *(const float4*)(Bp + k*128 + colg + 4);
            float av[8] = {a0.x,a0.y,a0.z,a0.w,a1.x,a1.y,a1.z,a1.w};
            float bv[8] = {b0.x,b0.y,b0.z,b0.w,b1.x,b1.y,b1.z,b1.w};
#pragma unroll
            for (int r=0;r<8;r++)
#pragma unroll
              for (int c=0;c<8;c++) acc[r][c] += av[r]*bv[c];
        }
        const int colbase = t*128 + colg;
#pragma unroll
        for (int c=0;c<8;c++){
            bool ok = (colbase + c) < cols;
#pragma unroll
            for (int r=0;r<8;r++){
                float v = ok ? acc[r][c] : NEGINF;
                ins3(v, t0[r], t1[r], t2[r]);
            }
        }
        if (t+1 < ntiles) CP_WAIT0();
        __syncthreads();
    }

    float* M = sm;
#pragma unroll
    for (int r=0;r<8;r++){
        int row = rowg + r;
        M[(row*16+txc)*3+0] = t0[r];
        M[(row*16+txc)*3+1] = t1[r];
        M[(row*16+txc)*3+2] = t2[r];
    }
    __syncthreads();
    if (tid < 128){
        float u0=NEGINF, u1=NEGINF, u2=NEGINF;
        const float* m = M + (size_t)tid*48;
        for (int j=0;j<48;j++) ins3(m[j], u0, u1, u2);
        int row = row0 + tid;
        if (row < nrows)
            g_rowsum[(size_t)cls*QPAD + row] = u0+u1+u2;
    }
}

// ---------- stage2: mma.sync bf16 + register-resident top-3 epilogue ----------
// grid (QPAD/128, KCLS), block 256 (8 warps), dyn smem 3*18432 = 55296B
__global__ void __launch_bounds__(256) mma_topk_kernel()
{
    extern __shared__ char smc[];
    char* As = smc;                 // [128 rows][144B]
    char* Bs = smc + 18432;         // [2][128 cols][144B]
    const int tid = threadIdx.x;
    const int wid = tid >> 5, lane = tid & 31;
    const int g = lane >> 2, tg = lane & 3;
    const int cls = blockIdx.y;
    const int row0 = blockIdx.x*128;

    uint32_t sA = (uint32_t)__cvta_generic_to_shared(As);
    uint32_t sB = (uint32_t)__cvta_generic_to_shared(Bs);

    const char* aG = (const char*)g_qbf + (size_t)row0*128;
    for (int c = tid; c < 1024; c += 256){
        int col = c >> 3, part = c & 7;
        cpasync16(sA + (uint32_t)(col*BROW + part*16), aG + (size_t)col*128 + part*16);
    }
    const char* bG = (const char*)g_bankbf + (size_t)cls*BCOLS*128;
    for (int c = tid; c < 1024; c += 256){
        int col = c >> 3, part = c & 7;
        cpasync16(sB + (uint32_t)(col*BROW + part*16), bG + (size_t)col*128 + part*16);
    }
    CP_COMMIT(); CP_WAIT0();
    __syncthreads();

    // A fragments (16 regs), loaded once: rows wid*16 + {g, g+8}
    uint32_t a[4][4];
    {
        const char* ar = As + (wid*16 + g)*BROW + tg*4;
#pragma unroll
        for (int kk=0; kk<4; kk++){
            a[kk][0] = *(const uint32_t*)(ar + kk*32);
            a[kk][1] = *(const uint32_t*)(ar + 8*BROW + kk*32);
            a[kk][2] = *(const uint32_t*)(ar + kk*32 + 16);
            a[kk][3] = *(const uint32_t*)(ar + 8*BROW + kk*32 + 16);
        }
    }

    float tA0=NEGINF, tA1=NEGINF, tA2=NEGINF;   // row g
    float tB0=NEGINF, tB1=NEGINF, tB2=NEGINF;   // row g+8

    for (int t = 0; t < CTILES2; ++t){
        if (t+1 < CTILES2){
            const char* bN = bG + (size_t)(t+1)*CT2*128;
            uint32_t bb = sB + (uint32_t)(((t+1)&1)*18432);
            for (int c = tid; c < 1024; c += 256){
                int col = c >> 3, part = c & 7;
                cpasync16(bb + (uint32_t)(col*BROW + part*16), bN + (size_t)col*128 + part*16);
            }
            CP_COMMIT();
        }
        const char* Bp = Bs + (t&1)*18432;
#pragma unroll 4
        for (int ns = 0; ns < 16; ++ns){
            const char* br = Bp + (ns*8 + g)*BROW + tg*4;
            float c0=0.f, c1=0.f, c2=0.f, c3=0.f;
#pragma unroll
            for (int kk=0; kk<4; kk++){
                uint32_t b0 = *(const uint32_t*)(br + kk*32);
                uint32_t b1 = *(const uint32_t*)(br + kk*32 + 16);
                asm volatile(
                    "mma.sync.aligned.m16n8k16.row.col.f32.bf16.bf16.f32 "
                    "{%0,%1,%2,%3}, {%4,%5,%6,%7}, {%8,%9}, {%0,%1,%2,%3};"
                    : "+f"(c0), "+f"(c1), "+f"(c2), "+f"(c3)
                    : "r"(a[kk][0]), "r"(a[kk][1]), "r"(a[kk][2]), "r"(a[kk][3]),
                      "r"(b0), "r"(b1));
            }
            const int colBase = t*CT2 + ns*8;
            if (colBase + 8 > MAUG){              // only the single partial n-step
                if (colBase + 2*tg     >= MAUG){ c0 = NEGINF; c2 = NEGINF; }
                if (colBase + 2*tg + 1 >= MAUG){ c1 = NEGINF; c3 = NEGINF; }
            }
            ins3(c0, tA0, tA1, tA2); ins3(c1, tA0, tA1, tA2);
            ins3(c2, tB0, tB1, tB2); ins3(c3, tB0, tB1, tB2);
        }
        if (t+1 < CTILES2) CP_WAIT0();
        __syncthreads();
    }

    // merge top-3 across the 4 lanes of each quad (tg 0..3)
#pragma unroll
    for (int off = 1; off <= 2; off <<= 1){
        float r0 = __shfl_xor_sync(0xffffffffu, tA0, off);
        float r1 = __shfl_xor_sync(0xffffffffu, tA1, off);
        float r2 = __shfl_xor_sync(0xffffffffu, tA2, off);
        ins3(r0, tA0, tA1, tA2); ins3(r1, tA0, tA1, tA2); ins3(r2, tA0, tA1, tA2);
        float s0 = __shfl_xor_sync(0xffffffffu, tB0, off);
        float s1 = __shfl_xor_sync(0xffffffffu, tB1, off);
        float s2 = __shfl_xor_sync(0xffffffffu, tB2, off);
        ins3(s0, tB0, tB1, tB2); ins3(s1, tB0, tB1, tB2); ins3(s2, tB0, tB1, tB2);
    }
    if (tg == 0){
        int row = row0 + wid*16 + g;
        g_rowsum[(size_t)cls*QPAD + row]     = tA0 + tA1 + tA2;
        g_rowsum[(size_t)cls*QPAD + row + 8] = tB0 + tB1 + tB2;
    }
}

// ---------- per-image deterministic sum ----------
__global__ void imgsum_kernel(float* __restrict__ outp, int useOut)
{
    __shared__ float s[128];
    const int img = blockIdx.x, cls = blockIdx.y;
    const int tid = threadIdx.x;
    const float* src = g_rowsum + (size_t)cls*QPAD + (size_t)img*PP;
    float v = 0.f;
    for (int i = tid; i < PP; i += 128) v += src[i];
    s[tid] = v; __syncthreads();
    for (int st=64; st>0; st>>=1){
        if (tid < st) s[tid] += s[tid+st];
        __syncthreads();
    }
    if (tid==0){
        float* dst = useOut ? outp : g_simu;
        dst[img*KCLS + cls] = s[0];
    }
}

// ---------- softmax + per-class top-10 (lowest-index ties) ----------
__global__ void select_kernel()
{
    __shared__ float pm[NU*KCLS];
    int tid = threadIdx.x;
    if (tid < NU){
        float v[KCLS]; float mx = NEGINF;
#pragma unroll
        for (int j=0;j<KCLS;j++){ v[j] = g_simu[tid*KCLS+j]; mx = fmaxf(mx, v[j]); }
        float s = 0.f;
#pragma unroll
        for (int j=0;j<KCLS;j++){ v[j] = expf(v[j]-mx); s += v[j]; }
#pragma unroll
        for (int j=0;j<KCLS;j++) pm[tid*KCLS+j] = v[j]/s;
    }
    __syncthreads();
    if (tid < KCLS){
        unsigned long long taken = 0ull;
        for (int i=0;i<SELN;i++){
            float best = NEGINF; int bi = 0;
            for (int b=0;b<NU;b++){
                if (taken & (1ull<<b)) continue;
                float val = pm[b*KCLS+tid];
                if (val > best){ best = val; bi = b; }
            }
            taken |= (1ull<<bi);
            g_selidx[tid*SELN+i] = bi;
        }
    }
}

extern "C" void kernel_launch(void* const* d_in, const int* in_sizes, int n_in,
                              void* d_out, int out_size)
{
    (void)in_sizes; (void)n_in; (void)out_size;
    // dict order: input1..3, w1, w2, w3, w4, g1, b1, g2, b2, g3, b3, g4, b4
    const float* in1 = (const float*)d_in[0];
    const float* in2 = (const float*)d_in[1];
    const float* in3 = (const float*)d_in[2];
    const float* w1  = (const float*)d_in[3];
    const float* w2  = (const float*)d_in[4];
    const float* w3  = (const float*)d_in[5];
    const float* w4  = (const float*)d_in[6];
    const float* gg1 = (const float*)d_in[7];
    const float* bb1 = (const float*)d_in[8];
    const float* gg2 = (const float*)d_in[9];
    const float* bb2 = (const float*)d_in[10];
    const float* gg3 = (const float*)d_in[11];
    const float* bb3 = (const float*)d_in[12];
    const float* gg4 = (const float*)d_in[13];
    const float* bb4 = (const float*)d_in[14];
    float* out = (float*)d_out;

    const int SM3 = (36864 + 16*(50*18))*4;
    const int SM2 = (36864 + 16*(34*18))*4;
    const int SMG = (8192 + 16384)*4;   // 96KB  (stage1)
    const int SMM = 3*18432;            // 55296B (stage2 mma)
    cudaFuncSetAttribute(conv64_kernel<3>, cudaFuncAttributeMaxDynamicSharedMemorySize, SM3);
    cudaFuncSetAttribute(conv64_kernel<2>, cudaFuncAttributeMaxDynamicSharedMemorySize, SM2);
    cudaFuncSetAttribute(topk_gemm_kernel,  cudaFuncAttributeMaxDynamicSharedMemorySize, SMG);
    cudaFuncSetAttribute(mma_topk_kernel,   cudaFuncAttributeMaxDynamicSharedMemorySize, SMM);

    dim3 blk(16,16);
    conv1_kernel<<<dim3(6,6,NALL), blk>>>(in1, in2, in3, w1);
    bn_stats_kernel<<<dim3(64,3), 256>>>(0, H1*H1);
    bn_pool_kernel<<<2048, 256>>>(0, 1, gg1, bb1, H1, H1, 1);
    conv64_kernel<3><<<dim3(3,1,NALL), blk, SM3>>>(1, 2, w2, H2, H2);
    bn_stats_kernel<<<dim3(64,3), 256>>>(2, H2*H2);
    bn_pool_kernel<<<2048, 256>>>(2, 3, gg2, bb2, H2, H2, 1);
    conv64_kernel<2><<<dim3(2,1,NALL), blk, SM2>>>(3, 4, w3, H3, H3);
    bn_stats_kernel<<<dim3(64,3), 256>>>(4, H3*H3);
    bn_pool_kernel<<<2048, 256>>>(4, 3, gg3, bb3, H3, H3, 0);
    conv64_kernel<2><<<dim3(2,1,NALL), blk, SM2>>>(3, 4, w4, H3, H3);
    bn_stats_kernel<<<dim3(64,3), 256>>>(4, H3*H3);
    bn_pool_kernel<<<2048, 256>>>(4, 3, gg4, bb4, H3, H3, 0);   // final feats in D

    norm_kernel<<<NALL, 256>>>();
    flatT_kernel<<<2048, 256>>>();
    fillT_support_kernel<<<2048, 256>>>();
    fillbf_q_kernel<<<2048, 256>>>();
    fillbf_support_kernel<<<2048, 256>>>();

    // stage 1: unlabeled rows vs support banks (fp32, exact selection)
    topk_gemm_kernel<<<dim3(UPAD/128, KCLS), 256, SMG>>>(UPAD, UROWS, MSUP);
    imgsum_kernel<<<dim3(NU, KCLS), 128>>>(nullptr, 0);
    select_kernel<<<1, 64>>>();
    fillbf_aug_kernel<<<2048, 256>>>();

    // stage 2: query rows vs augmented banks via mma.sync bf16 -> out [75,5]
    mma_topk_kernel<<<dim3(QPAD/128, KCLS), 256, SMM>>>();
    imgsum_kernel<<<dim3(NQ, KCLS), 128>>>(out, 1);
}

// round 10
// speedup vs baseline: 3.7748x; 1.6584x over previous
#include <cuda_runtime.h>
#include <cuda_bf16.h>
#include <math.h>
#include <stdint.h>

#define NQ 75
#define NS 25
#define NU 64
#define NALL 164
#define H1 84
#define H2 42
#define H3 21
#define PP 441
#define KCLS 5
#define SHOT 5
#define MSUP (SHOT*PP)          // 2205
#define MAUG (MSUP + 10*PP)     // 6615
#define BCOLS 6656              // 52*128
#define QROWS (NQ*PP)           // 33075
#define QPAD  33152             // 259*128
#define UROWS (NU*PP)           // 28224
#define UPAD  28288             // 221*128
#define SELN 10
#define NEGINF -3.4e38f
#define CT2 128
#define BROW 144                // padded smem row bytes (conflict-free)

__device__ float g_bufA[(size_t)NALL*64*H1*H1];
__device__ float g_bufC[(size_t)NALL*64*H2*H2];
__device__ float g_bufD[(size_t)NALL*64*H3*H3];
__device__ float g_bufE[(size_t)NALL*64*H3*H3];
__device__ float g_bufB[(size_t)NALL*64*H2*H2];
__device__ float g_rinv[(size_t)NALL*PP];
__device__ __nv_bfloat16 g_qbf[(size_t)QPAD*64];         // [row][k] bf16 queries
__device__ __nv_bfloat16 g_ubf[(size_t)UPAD*64];         // [row][k] bf16 unlabeled
__device__ __nv_bfloat16 g_bankbf[(size_t)KCLS*BCOLS*64];// [cls][col][k] bf16 banks
__device__ float g_rowsum[(size_t)KCLS*QPAD];
__device__ float g_stats[3*64*2];
__device__ float g_simu[NU*KCLS];
__device__ int   g_selidx[KCLS*SELN];

__device__ __forceinline__ float* bufPtr(int s){
    switch(s){
        case 0: return g_bufA; case 1: return g_bufB; case 2: return g_bufC;
        case 3: return g_bufD; default: return g_bufE;
    }
}
__device__ __forceinline__ int groupOf(int n){ return (n < NQ) ? 0 : ((n < NQ+NS) ? 1 : 2); }

__device__ __forceinline__ void cpasync16(uint32_t dst, const void* src){
    asm volatile("cp.async.cg.shared.global [%0], [%1], 16;\n" :: "r"(dst), "l"(src));
}
#define CP_COMMIT() asm volatile("cp.async.commit_group;\n" ::: "memory")
#define CP_WAIT0()  asm volatile("cp.async.wait_group 0;\n" ::: "memory")

__device__ __forceinline__ void ins3(float v, float& t0, float& t1, float& t2){
    if (v > t2){
        if (v > t0){ t2 = t1; t1 = t0; t0 = v; }
        else if (v > t1){ t2 = t1; t1 = v; }
        else t2 = v;
    }
}

// ---------- conv1: 3->64, 84x84 SAME ----------
__global__ void conv1_kernel(const float* __restrict__ in1, const float* __restrict__ in2,
                             const float* __restrict__ in3, const float* __restrict__ w)
{
    __shared__ float sW[64*27];
    __shared__ float sIn[3*18*18];
    const int n = blockIdx.z;
    const int gx0 = blockIdx.x*16, gy0 = blockIdx.y*16;
    const int tx = threadIdx.x, ty = threadIdx.y;
    const int tid = ty*16 + tx;
    const float* img = (n < NQ)    ? (in1 + (size_t)n*3*H1*H1)
                     : (n < NQ+NS) ? (in2 + (size_t)(n-NQ)*3*H1*H1)
                                   : (in3 + (size_t)(n-NQ-NS)*3*H1*H1);
    for (int i = tid; i < 64*27; i += 256) sW[i] = w[i];
    for (int i = tid; i < 3*18*18; i += 256) {
        int c = i / 324, rem = i % 324, r = rem/18, cc = rem%18;
        int gy = gy0 - 1 + r, gx = gx0 - 1 + cc;
        sIn[i] = (gy>=0 && gy<H1 && gx>=0 && gx<H1) ? img[((size_t)c*H1+gy)*H1+gx] : 0.f;
    }
    __syncthreads();
    int ox = gx0+tx, oy = gy0+ty;
    if (ox >= H1 || oy >= H1) return;
    float v[27];
#pragma unroll
    for (int c=0;c<3;c++)
#pragma unroll
      for (int dy=0;dy<3;dy++)
#pragma unroll
        for (int dx=0;dx<3;dx++)
          v[c*9+dy*3+dx] = sIn[c*324 + (ty+dy)*18 + (tx+dx)];
#pragma unroll 4
    for (int oc=0; oc<64; oc++){
        float acc = 0.f;
        const float* wp = sW + oc*27;
#pragma unroll
        for (int j=0;j<27;j++) acc += wp[j]*v[j];
        g_bufA[(((size_t)n*64+oc)*H1+oy)*H1+ox] = acc;
    }
}

// ---------- conv 64->64 3x3 SAME ; grid.z = n*4 + ocg ----------
template<int RPT>
__global__ void conv64_kernel(int inSel, int outSel, const float* __restrict__ wt, int H, int W)
{
    extern __shared__ float sm[];
    float* sW  = sm;              // 16*64*9 = 9216 floats
    float* sIn = sm + 9216;
    constexpr int TH   = 16*RPT;
    constexpr int HALO = (TH+2)*18;
    const int z   = blockIdx.z;
    const int n   = z >> 2;
    const int ocg = z & 3;
    const int gx0 = blockIdx.x*16;
    const int gy0 = blockIdx.y*TH;
    const int tx = threadIdx.x, ty = threadIdx.y;
    const int tid = ty*16 + tx;
    for (int i = tid; i < 16*64*9; i += 256) sW[i] = wt[(size_t)(ocg*16)*576 + i];
    const int oyb = gy0 + ty*RPT;
    const int ox  = gx0 + tx;
    const bool anyValid = (ox < W) && (oyb < H);
    const float* inN  = bufPtr(inSel)  + (size_t)n*64*H*W;
    float*       outN = bufPtr(outSel) + (size_t)n*64*H*W;

    float acc[16][RPT];
#pragma unroll
    for (int o=0;o<16;o++)
#pragma unroll
      for (int r=0;r<RPT;r++) acc[o][r]=0.f;

    for (int cc = 0; cc < 4; ++cc) {
        __syncthreads();
        for (int i = tid; i < 16*HALO; i += 256) {
            int c = i / HALO, rem = i % HALO, r = rem/18, col = rem%18;
            int gy = gy0-1+r, gx = gx0-1+col;
            float v = 0.f;
            if (gy>=0 && gy<H && gx>=0 && gx<W)
                v = inN[((size_t)(cc*16+c)*H+gy)*W+gx];
            sIn[i] = v;
        }
        __syncthreads();
        if (anyValid) {
            for (int ic=0; ic<16; ++ic) {
                float v[RPT+2][3];
                const float* sp = sIn + ic*HALO + (ty*RPT)*18 + tx;
#pragma unroll
                for (int r=0;r<RPT+2;r++)
#pragma unroll
                  for (int d=0;d<3;d++) v[r][d] = sp[r*18+d];
                const float* wp = sW + (cc*16+ic)*9;
#pragma unroll
                for (int o=0;o<16;o++){
                    const float* wo = wp + o*576;
                    float w0=wo[0],w1=wo[1],w2=wo[2],w3=wo[3],w4=wo[4];
                    float w5=wo[5],w6=wo[6],w7=wo[7],w8=wo[8];
#pragma unroll
                    for (int r=0;r<RPT;r++){
                        float a = acc[o][r];
                        a += w0*v[r  ][0]; a += w1*v[r  ][1]; a += w2*v[r  ][2];
                        a += w3*v[r+1][0]; a += w4*v[r+1][1]; a += w5*v[r+1][2];
                        a += w6*v[r+2][0]; a += w7*v[r+2][1]; a += w8*v[r+2][2];
                        acc[o][r] = a;
                    }
                }
            }
        }
    }
    if (anyValid) {
#pragma unroll
        for (int o=0;o<16;o++){
            int oc = ocg*16+o;
#pragma unroll
            for (int r=0;r<RPT;r++){
                int oy = oyb + r;
                if (oy < H) outN[((size_t)oc*H+oy)*W+ox] = acc[o][r];
            }
        }
    }
}

// ---------- BN stats ----------
__global__ void bn_stats_kernel(int sel, int HW)
{
    __shared__ double ssum[256], ssum2[256];
    const int ch = blockIdx.x, g = blockIdx.y;
    const int n0 = (g==0)?0:((g==1)?NQ:(NQ+NS));
    const int n1 = (g==0)?NQ:((g==1)?(NQ+NS):NALL);
    const int tid = threadIdx.x;
    const float* buf = bufPtr(sel);
    double s=0.0, s2=0.0;
    for (int n=n0; n<n1; ++n) {
        const float* p = buf + ((size_t)n*64+ch)*HW;
        for (int i=tid;i<HW;i+=256){ double x = (double)p[i]; s+=x; s2+=x*x; }
    }
    ssum[tid]=s; ssum2[tid]=s2; __syncthreads();
    for (int st=128; st>0; st>>=1){
        if (tid<st){ ssum[tid]+=ssum[tid+st]; ssum2[tid]+=ssum2[tid+st]; }
        __syncthreads();
    }
    if (tid==0){
        double cnt = (double)(n1-n0)*HW;
        double mean = ssum[0]/cnt;
        double var  = ssum2[0]/cnt - mean*mean;
        g_stats[(g*64+ch)*2+0] = (float)mean;
        g_stats[(g*64+ch)*2+1] = (float)(1.0/sqrt(var + 1e-5));
    }
}

// ---------- BN + LeakyReLU (+pool) ----------
__global__ void bn_pool_kernel(int inSel, int outSel, const float* __restrict__ gamma,
                               const float* __restrict__ beta, int H, int W, int doPool)
{
    const int oH = doPool ? H/2 : H, oW = doPool ? W/2 : W;
    const size_t total = (size_t)NALL*64*oH*oW;
    const float* in = bufPtr(inSel);
    float* out = bufPtr(outSel);
    for (size_t idx = (size_t)blockIdx.x*blockDim.x + threadIdx.x; idx < total;
         idx += (size_t)gridDim.x*blockDim.x) {
        int ox = (int)(idx % oW); size_t t = idx / oW;
        int oy = (int)(t % oH);   t /= oH;
        int c  = (int)(t % 64);   int n = (int)(t / 64);
        int g = groupOf(n);
        float mean = g_stats[(g*64+c)*2+0], rsig = g_stats[(g*64+c)*2+1];
        float sc = gamma[c]*rsig;
        float sh = beta[c] - mean*sc;
        const float* p = in + ((size_t)n*64+c)*H*W;
        float r;
        if (doPool){
            float x0 = p[(size_t)(2*oy)*W + 2*ox  ]*sc+sh;
            float x1 = p[(size_t)(2*oy)*W + 2*ox+1]*sc+sh;
            float x2 = p[(size_t)(2*oy+1)*W + 2*ox  ]*sc+sh;
            float x3 = p[(size_t)(2*oy+1)*W + 2*ox+1]*sc+sh;
            x0 = x0>=0.f?x0:0.2f*x0; x1 = x1>=0.f?x1:0.2f*x1;
            x2 = x2>=0.f?x2:0.2f*x2; x3 = x3>=0.f?x3:0.2f*x3;
            r = fmaxf(fmaxf(x0,x1), fmaxf(x2,x3));
        } else {
            float x = p[(size_t)oy*W+ox]*sc+sh;
            r = x>=0.f?x:0.2f*x;
        }
        out[idx] = r;
    }
}

// ---------- descriptor inverse norms ----------
__global__ void norm_kernel()
{
    int img = blockIdx.x;
    for (int p = threadIdx.x; p < PP; p += blockDim.x){
        float ss = 0.f;
        const float* f = g_bufD + (size_t)img*64*PP + p;
#pragma unroll
        for (int c=0;c<64;c++){ float x = f[(size_t)c*PP]; ss += x*x; }
        g_rinv[(size_t)img*PP + p] = rsqrtf(ss);
    }
}

// ---------- bf16 descriptor buffers: mode 0 = queries, 1 = unlabeled ----------
__global__ void fillbf_desc_kernel(int mode)
{
    const int pad = mode ? UPAD : QPAD;
    const int nrows = mode ? UROWS : QROWS;
    const int imgBase = mode ? (NQ+NS) : 0;
    __nv_bfloat16* dst = mode ? g_ubf : g_qbf;
    const size_t total = (size_t)pad*64;
    for (size_t i = (size_t)blockIdx.x*blockDim.x + threadIdx.x; i < total;
         i += (size_t)gridDim.x*blockDim.x) {
        int k = (int)(i & 63); int row = (int)(i >> 6);
        float v = 0.f;
        if (row < nrows){
            int img = imgBase + row / PP, p = row % PP;
            v = g_bufD[((size_t)img*64+k)*PP + p] * g_rinv[(size_t)img*PP + p];
        }
        dst[i] = __float2bfloat16(v);
    }
}
__global__ void fillbf_support_kernel()
{
    const size_t total = (size_t)KCLS*BCOLS*64;
    for (size_t i = (size_t)blockIdx.x*blockDim.x + threadIdx.x; i < total;
         i += (size_t)gridDim.x*blockDim.x) {
        int k = (int)(i & 63); size_t t = i >> 6;
        int col = (int)(t % BCOLS); int j = (int)(t / BCOLS);
        if (col < MSUP){
            int s = col / PP, p = col % PP;
            int img = NQ + j*SHOT + s;
            g_bankbf[i] = __float2bfloat16(
                g_bufD[((size_t)img*64+k)*PP + p] * g_rinv[(size_t)img*PP + p]);
        } else if (col >= MAUG){
            g_bankbf[i] = __float2bfloat16(0.f);
        }
    }
}
__global__ void fillbf_aug_kernel()
{
    const size_t total = (size_t)KCLS*(SELN*PP)*64;
    for (size_t i = (size_t)blockIdx.x*blockDim.x + threadIdx.x; i < total;
         i += (size_t)gridDim.x*blockDim.x) {
        int k = (int)(i & 63); size_t t = i >> 6;
        int a = (int)(t % (SELN*PP)); int j = (int)(t / (SELN*PP));
        int sel = a / PP, p = a % PP;
        int img = NQ + NS + g_selidx[j*SELN + sel];
        g_bankbf[(((size_t)j*BCOLS) + MSUP + a)*64 + k] = __float2bfloat16(
            g_bufD[((size_t)img*64+k)*PP + p] * g_rinv[(size_t)img*PP + p]);
    }
}

// ---------- unified mma.sync bf16 + register-resident top-3 ----------
// grid (rowtiles, KCLS), block 256 (8 warps), dyn smem 3*18432 = 55296B
// aSel: 0 = unlabeled (stage1), 1 = queries (stage2). cols = valid bank cols.
__global__ void __launch_bounds__(256) mma_topk_kernel(int aSel, int cols)
{
    extern __shared__ char smc[];
    char* As = smc;                 // [128 rows][144B]
    char* Bs = smc + 18432;         // [2][128 cols][144B]
    const int tid = threadIdx.x;
    const int wid = tid >> 5, lane = tid & 31;
    const int g = lane >> 2, tg = lane & 3;
    const int cls = blockIdx.y;
    const int row0 = blockIdx.x*128;
    const int ntiles = (cols + CT2 - 1)/CT2;

    uint32_t sA = (uint32_t)__cvta_generic_to_shared(As);
    uint32_t sB = (uint32_t)__cvta_generic_to_shared(Bs);

    const char* aG = (const char*)(aSel ? g_qbf : g_ubf) + (size_t)row0*128;
    for (int c = tid; c < 1024; c += 256){
        int col = c >> 3, part = c & 7;
        cpasync16(sA + (uint32_t)(col*BROW + part*16), aG + (size_t)col*128 + part*16);
    }
    const char* bG = (const char*)g_bankbf + (size_t)cls*BCOLS*128;
    for (int c = tid; c < 1024; c += 256){
        int col = c >> 3, part = c & 7;
        cpasync16(sB + (uint32_t)(col*BROW + part*16), bG + (size_t)col*128 + part*16);
    }
    CP_COMMIT(); CP_WAIT0();
    __syncthreads();

    // A fragments (16 regs), loaded once: rows wid*16 + {g, g+8}
    uint32_t a[4][4];
    {
        const char* ar = As + (wid*16 + g)*BROW + tg*4;
#pragma unroll
        for (int kk=0; kk<4; kk++){
            a[kk][0] = *(const uint32_t*)(ar + kk*32);
            a[kk][1] = *(const uint32_t*)(ar + 8*BROW + kk*32);
            a[kk][2] = *(const uint32_t*)(ar + kk*32 + 16);
            a[kk][3] = *(const uint32_t*)(ar + 8*BROW + kk*32 + 16);
        }
    }

    float tA0=NEGINF, tA1=NEGINF, tA2=NEGINF;   // row g
    float tB0=NEGINF, tB1=NEGINF, tB2=NEGINF;   // row g+8

    for (int t = 0; t < ntiles; ++t){
        if (t+1 < ntiles){
            const char* bN = bG + (size_t)(t+1)*CT2*128;
            uint32_t bb = sB + (uint32_t)(((t+1)&1)*18432);
            for (int c = tid; c < 1024; c += 256){
                int col = c >> 3, part = c & 7;
                cpasync16(bb + (uint32_t)(col*BROW + part*16), bN + (size_t)col*128 + part*16);
            }
            CP_COMMIT();
        }
        const char* Bp = Bs + (t&1)*18432;
#pragma unroll 4
        for (int ns = 0; ns < 16; ++ns){
            const char* br = Bp + (ns*8 + g)*BROW + tg*4;
            float c0=0.f, c1=0.f, c2=0.f, c3=0.f;
#pragma unroll
            for (int kk=0; kk<4; kk++){
                uint32_t b0 = *(const uint32_t*)(br + kk*32);
                uint32_t b1 = *(const uint32_t*)(br + kk*32 + 16);
                asm volatile(
                    "mma.sync.aligned.m16n8k16.row.col.f32.bf16.bf16.f32 "
                    "{%0,%1,%2,%3}, {%4,%5,%6,%7}, {%8,%9}, {%0,%1,%2,%3};"
                    : "+f"(c0), "+f"(c1), "+f"(c2), "+f"(c3)
                    : "r"(a[kk][0]), "r"(a[kk][1]), "r"(a[kk][2]), "r"(a[kk][3]),
                      "r"(b0), "r"(b1));
            }
            const int colBase = t*CT2 + ns*8;
            if (colBase + 8 > cols){              // partial / fully-out n-steps
                if (colBase + 2*tg     >= cols){ c0 = NEGINF; c2 = NEGINF; }
                if (colBase + 2*tg + 1 >= cols){ c1 = NEGINF; c3 = NEGINF; }
            }
            ins3(c0, tA0, tA1, tA2); ins3(c1, tA0, tA1, tA2);
            ins3(c2, tB0, tB1, tB2); ins3(c3, tB0, tB1, tB2);
        }
        if (t+1 < ntiles) CP_WAIT0();
        __syncthreads();
    }

    // merge top-3 across the 4 lanes of each quad
#pragma unroll
    for (int off = 1; off <= 2; off <<= 1){
        float r0 = __shfl_xor_sync(0xffffffffu, tA0, off);
        float r1 = __shfl_xor_sync(0xffffffffu, tA1, off);
        float r2 = __shfl_xor_sync(0xffffffffu, tA2, off);
        ins3(r0, tA0, tA1, tA2); ins3(r1, tA0, tA1, tA2); ins3(r2, tA0, tA1, tA2);
        float s0 = __shfl_xor_sync(0xffffffffu, tB0, off);
        float s1 = __shfl_xor_sync(0xffffffffu, tB1, off);
        float s2 = __shfl_xor_sync(0xffffffffu, tB2, off);
        ins3(s0, tB0, tB1, tB2); ins3(s1, tB0, tB1, tB2); ins3(s2, tB0, tB1, tB2);
    }
    if (tg == 0){
        int row = row0 + wid*16 + g;
        g_rowsum[(size_t)cls*QPAD + row]     = tA0 + tA1 + tA2;
        g_rowsum[(size_t)cls*QPAD + row + 8] = tB0 + tB1 + tB2;
    }
}

// ---------- per-image deterministic sum ----------
__global__ void imgsum_kernel(float* __restrict__ outp, int useOut)
{
    __shared__ float s[128];
    const int img = blockIdx.x, cls = blockIdx.y;
    const int tid = threadIdx.x;
    const float* src = g_rowsum + (size_t)cls*QPAD + (size_t)img*PP;
    float v = 0.f;
    for (int i = tid; i < PP; i += 128) v += src[i];
    s[tid] = v; __syncthreads();
    for (int st=64; st>0; st>>=1){
        if (tid < st) s[tid] += s[tid+st];
        __syncthreads();
    }
    if (tid==0){
        float* dst = useOut ? outp : g_simu;
        dst[img*KCLS + cls] = s[0];
    }
}

// ---------- softmax + per-class top-10 (lowest-index ties) ----------
__global__ void select_kernel()
{
    __shared__ float pm[NU*KCLS];
    int tid = threadIdx.x;
    if (tid < NU){
        float v[KCLS]; float mx = NEGINF;
#pragma unroll
        for (int j=0;j<KCLS;j++){ v[j] = g_simu[tid*KCLS+j]; mx = fmaxf(mx, v[j]); }
        float s = 0.f;
#pragma unroll
        for (int j=0;j<KCLS;j++){ v[j] = expf(v[j]-mx); s += v[j]; }
#pragma unroll
        for (int j=0;j<KCLS;j++) pm[tid*KCLS+j] = v[j]/s;
    }
    __syncthreads();
    if (tid < KCLS){
        unsigned long long taken = 0ull;
        for (int i=0;i<SELN;i++){
            float best = NEGINF; int bi = 0;
            for (int b=0;b<NU;b++){
                if (taken & (1ull<<b)) continue;
                float val = pm[b*KCLS+tid];
                if (val > best){ best = val; bi = b; }
            }
            taken |= (1ull<<bi);
            g_selidx[tid*SELN+i] = bi;
        }
    }
}

extern "C" void kernel_launch(void* const* d_in, const int* in_sizes, int n_in,
                              void* d_out, int out_size)
{
    (void)in_sizes; (void)n_in; (void)out_size;
    // dict order: input1..3, w1, w2, w3, w4, g1, b1, g2, b2, g3, b3, g4, b4
    const float* in1 = (const float*)d_in[0];
    const float* in2 = (const float*)d_in[1];
    const float* in3 = (const float*)d_in[2];
    const float* w1  = (const float*)d_in[3];
    const float* w2  = (const float*)d_in[4];
    const float* w3  = (const float*)d_in[5];
    const float* w4  = (const float*)d_in[6];
    const float* gg1 = (const float*)d_in[7];
    const float* bb1 = (const float*)d_in[8];
    const float* gg2 = (const float*)d_in[9];
    const float* bb2 = (const float*)d_in[10];
    const float* gg3 = (const float*)d_in[11];
    const float* bb3 = (const float*)d_in[12];
    const float* gg4 = (const float*)d_in[13];
    const float* bb4 = (const float*)d_in[14];
    float* out = (float*)d_out;

    const int SM3 = (9216 + 16*(50*18))*4;   // 94464B
    const int SM2 = (9216 + 16*(34*18))*4;   // 76032B
    const int SMM = 3*18432;                 // 55296B
    cudaFuncSetAttribute(conv64_kernel<3>, cudaFuncAttributeMaxDynamicSharedMemorySize, SM3);
    cudaFuncSetAttribute(conv64_kernel<2>, cudaFuncAttributeMaxDynamicSharedMemorySize, SM2);
    cudaFuncSetAttribute(mma_topk_kernel,  cudaFuncAttributeMaxDynamicSharedMemorySize, SMM);

    dim3 blk(16,16);
    conv1_kernel<<<dim3(6,6,NALL), blk>>>(in1, in2, in3, w1);
    bn_stats_kernel<<<dim3(64,3), 256>>>(0, H1*H1);
    bn_pool_kernel<<<2048, 256>>>(0, 1, gg1, bb1, H1, H1, 1);
    conv64_kernel<3><<<dim3(3,1,NALL*4), blk, SM3>>>(1, 2, w2, H2, H2);
    bn_stats_kernel<<<dim3(64,3), 256>>>(2, H2*H2);
    bn_pool_kernel<<<2048, 256>>>(2, 3, gg2, bb2, H2, H2, 1);
    conv64_kernel<2><<<dim3(2,1,NALL*4), blk, SM2>>>(3, 4, w3, H3, H3);
    bn_stats_kernel<<<dim3(64,3), 256>>>(4, H3*H3);
    bn_pool_kernel<<<2048, 256>>>(4, 3, gg3, bb3, H3, H3, 0);
    conv64_kernel<2><<<dim3(2,1,NALL*4), blk, SM2>>>(3, 4, w4, H3, H3);
    bn_stats_kernel<<<dim3(64,3), 256>>>(4, H3*H3);
    bn_pool_kernel<<<2048, 256>>>(4, 3, gg4, bb4, H3, H3, 0);   // final feats in D

    norm_kernel<<<NALL, 256>>>();
    fillbf_desc_kernel<<<2048, 256>>>(0);   // queries
    fillbf_desc_kernel<<<2048, 256>>>(1);   // unlabeled
    fillbf_support_kernel<<<2048, 256>>>();

    // stage 1: unlabeled rows vs support banks (bf16 mma, cols = MSUP)
    mma_topk_kernel<<<dim3(UPAD/128, KCLS), 256, SMM>>>(0, MSUP);
    imgsum_kernel<<<dim3(NU, KCLS), 128>>>(nullptr, 0);
    select_kernel<<<1, 64>>>();
    fillbf_aug_kernel<<<2048, 256>>>();

    // stage 2: query rows vs augmented banks (bf16 mma, cols = MAUG)
    mma_topk_kernel<<<dim3(QPAD/128, KCLS), 256, SMM>>>(1, MAUG);
    imgsum_kernel<<<dim3(NQ, KCLS), 128>>>(out, 1);
}

// round 11
// speedup vs baseline: 3.9613x; 1.0494x over previous
#include <cuda_runtime.h>
#include <cuda_bf16.h>
#include <math.h>
#include <stdint.h>

#define NQ 75
#define NS 25
#define NU 64
#define NALL 164
#define H1 84
#define H2 42
#define H3 21
#define PP 441
#define KCLS 5
#define SHOT 5
#define MSUP (SHOT*PP)          // 2205
#define MAUG (MSUP + 10*PP)     // 6615
#define BCOLS 6656              // 52*128
#define QROWS (NQ*PP)           // 33075
#define QPAD  33152             // 259*128
#define UROWS (NU*PP)           // 28224
#define UPAD  28288             // 221*128
#define SELN 10
#define NEGINF -3.4e38f
#define CT2 128
#define BROW 144                // padded smem row bytes (conflict-free)

__device__ float g_bufA[(size_t)NALL*64*H1*H1];
__device__ float g_bufC[(size_t)NALL*64*H2*H2];
__device__ float g_bufD[(size_t)NALL*64*H3*H3];
__device__ float g_bufE[(size_t)NALL*64*H3*H3];
__device__ float g_bufB[(size_t)NALL*64*H2*H2];
__device__ float g_rinv[(size_t)NALL*PP];
__device__ __nv_bfloat16 g_qbf[(size_t)QPAD*64];         // [row][k] bf16 queries
__device__ __nv_bfloat16 g_ubf[(size_t)UPAD*64];         // [row][k] bf16 unlabeled
__device__ __nv_bfloat16 g_bankbf[(size_t)KCLS*BCOLS*64];// [cls][col][k] bf16 banks
__device__ float g_rowsum[(size_t)KCLS*QPAD];
__device__ float g_stats[3*64*2];
__device__ float g_simu[NU*KCLS];
__device__ int   g_selidx[KCLS*SELN];

__device__ __forceinline__ float* bufPtr(int s){
    switch(s){
        case 0: return g_bufA; case 1: return g_bufB; case 2: return g_bufC;
        case 3: return g_bufD; default: return g_bufE;
    }
}
__device__ __forceinline__ int groupOf(int n){ return (n < NQ) ? 0 : ((n < NQ+NS) ? 1 : 2); }

__device__ __forceinline__ void cpasync16(uint32_t dst, const void* src){
    asm volatile("cp.async.cg.shared.global [%0], [%1], 16;\n" :: "r"(dst), "l"(src));
}
#define CP_COMMIT() asm volatile("cp.async.commit_group;\n" ::: "memory")
#define CP_WAIT0()  asm volatile("cp.async.wait_group 0;\n" ::: "memory")

__device__ __forceinline__ void ins3(float v, float& t0, float& t1, float& t2){
    if (v > t2){
        if (v > t0){ t2 = t1; t1 = t0; t0 = v; }
        else if (v > t1){ t2 = t1; t1 = v; }
        else t2 = v;
    }
}

// ---------- conv1: 3->64, 84x84 SAME ----------
__global__ void conv1_kernel(const float* __restrict__ in1, const float* __restrict__ in2,
                             const float* __restrict__ in3, const float* __restrict__ w)
{
    __shared__ float sW[64*27];
    __shared__ float sIn[3*18*18];
    const int n = blockIdx.z;
    const int gx0 = blockIdx.x*16, gy0 = blockIdx.y*16;
    const int tx = threadIdx.x, ty = threadIdx.y;
    const int tid = ty*16 + tx;
    const float* img = (n < NQ)    ? (in1 + (size_t)n*3*H1*H1)
                     : (n < NQ+NS) ? (in2 + (size_t)(n-NQ)*3*H1*H1)
                                   : (in3 + (size_t)(n-NQ-NS)*3*H1*H1);
    for (int i = tid; i < 64*27; i += 256) sW[i] = w[i];
    for (int i = tid; i < 3*18*18; i += 256) {
        int c = i / 324, rem = i % 324, r = rem/18, cc = rem%18;
        int gy = gy0 - 1 + r, gx = gx0 - 1 + cc;
        sIn[i] = (gy>=0 && gy<H1 && gx>=0 && gx<H1) ? img[((size_t)c*H1+gy)*H1+gx] : 0.f;
    }
    __syncthreads();
    int ox = gx0+tx, oy = gy0+ty;
    if (ox >= H1 || oy >= H1) return;
    float v[27];
#pragma unroll
    for (int c=0;c<3;c++)
#pragma unroll
      for (int dy=0;dy<3;dy++)
#pragma unroll
        for (int dx=0;dx<3;dx++)
          v[c*9+dy*3+dx] = sIn[c*324 + (ty+dy)*18 + (tx+dx)];
#pragma unroll 4
    for (int oc=0; oc<64; oc++){
        float acc = 0.f;
        const float* wp = sW + oc*27;
#pragma unroll
        for (int j=0;j<27;j++) acc += wp[j]*v[j];
        g_bufA[(((size_t)n*64+oc)*H1+oy)*H1+ox] = acc;
    }
}

// ---------- conv 64->64 3x3 SAME ; grid.z = n*4 + ocg ; ic chunked by 8 ----------
template<int RPT>
__global__ void conv64_kernel(int inSel, int outSel, const float* __restrict__ wt, int H, int W)
{
    extern __shared__ float sm[];
    float* sW  = sm;              // [16 oc][8 ic][9] = 1152 floats
    float* sIn = sm + 1152;       // [8 ic][HALO]
    constexpr int TH   = 16*RPT;
    constexpr int HALO = (TH+2)*18;
    const int z   = blockIdx.z;
    const int n   = z >> 2;
    const int ocg = z & 3;
    const int gx0 = blockIdx.x*16;
    const int gy0 = blockIdx.y*TH;
    const int tx = threadIdx.x, ty = threadIdx.y;
    const int tid = ty*16 + tx;
    const int oyb = gy0 + ty*RPT;
    const int ox  = gx0 + tx;
    const bool anyValid = (ox < W) && (oyb < H);
    const float* inN  = bufPtr(inSel)  + (size_t)n*64*H*W;
    float*       outN = bufPtr(outSel) + (size_t)n*64*H*W;

    float acc[16][RPT];
#pragma unroll
    for (int o=0;o<16;o++)
#pragma unroll
      for (int r=0;r<RPT;r++) acc[o][r]=0.f;

    for (int cc = 0; cc < 8; ++cc) {
        __syncthreads();
        // weights for this chunk: [o][ic8][9]
        for (int i = tid; i < 1152; i += 256) {
            int o = i / 72, rem = i % 72;
            sW[i] = wt[(size_t)(ocg*16+o)*576 + cc*72 + rem];
        }
        // input halo for 8 ics
        for (int i = tid; i < 8*HALO; i += 256) {
            int c = i / HALO, rem = i % HALO, r = rem/18, col = rem%18;
            int gy = gy0-1+r, gx = gx0-1+col;
            float v = 0.f;
            if (gy>=0 && gy<H && gx>=0 && gx<W)
                v = inN[((size_t)(cc*8+c)*H+gy)*W+gx];
            sIn[i] = v;
        }
        __syncthreads();
        if (anyValid) {
            for (int ic=0; ic<8; ++ic) {
                float v[RPT+2][3];
                const float* sp = sIn + ic*HALO + (ty*RPT)*18 + tx;
#pragma unroll
                for (int r=0;r<RPT+2;r++)
#pragma unroll
                  for (int d=0;d<3;d++) v[r][d] = sp[r*18+d];
                const float* wp = sW + ic*9;
#pragma unroll
                for (int o=0;o<16;o++){
                    const float* wo = wp + o*72;
                    float w0=wo[0],w1=wo[1],w2=wo[2],w3=wo[3],w4=wo[4];
                    float w5=wo[5],w6=wo[6],w7=wo[7],w8=wo[8];
#pragma unroll
                    for (int r=0;r<RPT;r++){
                        float a = acc[o][r];
                        a += w0*v[r  ][0]; a += w1*v[r  ][1]; a += w2*v[r  ][2];
                        a += w3*v[r+1][0]; a += w4*v[r+1][1]; a += w5*v[r+1][2];
                        a += w6*v[r+2][0]; a += w7*v[r+2][1]; a += w8*v[r+2][2];
                        acc[o][r] = a;
                    }
                }
            }
        }
    }
    if (anyValid) {
#pragma unroll
        for (int o=0;o<16;o++){
            int oc = ocg*16+o;
#pragma unroll
            for (int r=0;r<RPT;r++){
                int oy = oyb + r;
                if (oy < H) outN[((size_t)oc*H+oy)*W+ox] = acc[o][r];
            }
        }
    }
}

// ---------- BN stats ----------
__global__ void bn_stats_kernel(int sel, int HW)
{
    __shared__ double ssum[256], ssum2[256];
    const int ch = blockIdx.x, g = blockIdx.y;
    const int n0 = (g==0)?0:((g==1)?NQ:(NQ+NS));
    const int n1 = (g==0)?NQ:((g==1)?(NQ+NS):NALL);
    const int tid = threadIdx.x;
    const float* buf = bufPtr(sel);
    double s=0.0, s2=0.0;
    for (int n=n0; n<n1; ++n) {
        const float* p = buf + ((size_t)n*64+ch)*HW;
        for (int i=tid;i<HW;i+=256){ double x = (double)p[i]; s+=x; s2+=x*x; }
    }
    ssum[tid]=s; ssum2[tid]=s2; __syncthreads();
    for (int st=128; st>0; st>>=1){
        if (tid<st){ ssum[tid]+=ssum[tid+st]; ssum2[tid]+=ssum2[tid+st]; }
        __syncthreads();
    }
    if (tid==0){
        double cnt = (double)(n1-n0)*HW;
        double mean = ssum[0]/cnt;
        double var  = ssum2[0]/cnt - mean*mean;
        g_stats[(g*64+ch)*2+0] = (float)mean;
        g_stats[(g*64+ch)*2+1] = (float)(1.0/sqrt(var + 1e-5));
    }
}

// ---------- BN + LeakyReLU (+pool) ----------
__global__ void bn_pool_kernel(int inSel, int outSel, const float* __restrict__ gamma,
                               const float* __restrict__ beta, int H, int W, int doPool)
{
    const int oH = doPool ? H/2 : H, oW = doPool ? W/2 : W;
    const size_t total = (size_t)NALL*64*oH*oW;
    const float* in = bufPtr(inSel);
    float* out = bufPtr(outSel);
    for (size_t idx = (size_t)blockIdx.x*blockDim.x + threadIdx.x; idx < total;
         idx += (size_t)gridDim.x*blockDim.x) {
        int ox = (int)(idx % oW); size_t t = idx / oW;
        int oy = (int)(t % oH);   t /= oH;
        int c  = (int)(t % 64);   int n = (int)(t / 64);
        int g = groupOf(n);
        float mean = g_stats[(g*64+c)*2+0], rsig = g_stats[(g*64+c)*2+1];
        float sc = gamma[c]*rsig;
        float sh = beta[c] - mean*sc;
        const float* p = in + ((size_t)n*64+c)*H*W;
        float r;
        if (doPool){
            float x0 = p[(size_t)(2*oy)*W + 2*ox  ]*sc+sh;
            float x1 = p[(size_t)(2*oy)*W + 2*ox+1]*sc+sh;
            float x2 = p[(size_t)(2*oy+1)*W + 2*ox  ]*sc+sh;
            float x3 = p[(size_t)(2*oy+1)*W + 2*ox+1]*sc+sh;
            x0 = x0>=0.f?x0:0.2f*x0; x1 = x1>=0.f?x1:0.2f*x1;
            x2 = x2>=0.f?x2:0.2f*x2; x3 = x3>=0.f?x3:0.2f*x3;
            r = fmaxf(fmaxf(x0,x1), fmaxf(x2,x3));
        } else {
            float x = p[(size_t)oy*W+ox]*sc+sh;
            r = x>=0.f?x:0.2f*x;
        }
        out[idx] = r;
    }
}

// ---------- descriptor inverse norms ----------
__global__ void norm_kernel()
{
    int img = blockIdx.x;
    for (int p = threadIdx.x; p < PP; p += blockDim.x){
        float ss = 0.f;
        const float* f = g_bufD + (size_t)img*64*PP + p;
#pragma unroll
        for (int c=0;c<64;c++){ float x = f[(size_t)c*PP]; ss += x*x; }
        g_rinv[(size_t)img*PP + p] = rsqrtf(ss);
    }
}

// ---------- bf16 descriptor buffers: mode 0 = queries, 1 = unlabeled ----------
__global__ void fillbf_desc_kernel(int mode)
{
    const int pad = mode ? UPAD : QPAD;
    const int nrows = mode ? UROWS : QROWS;
    const int imgBase = mode ? (NQ+NS) : 0;
    __nv_bfloat16* dst = mode ? g_ubf : g_qbf;
    const size_t total = (size_t)pad*64;
    for (size_t i = (size_t)blockIdx.x*blockDim.x + threadIdx.x; i < total;
         i += (size_t)gridDim.x*blockDim.x) {
        int k = (int)(i & 63); int row = (int)(i >> 6);
        float v = 0.f;
        if (row < nrows){
            int img = imgBase + row / PP, p = row % PP;
            v = g_bufD[((size_t)img*64+k)*PP + p] * g_rinv[(size_t)img*PP + p];
        }
        dst[i] = __float2bfloat16(v);
    }
}
__global__ void fillbf_support_kernel()
{
    const size_t total = (size_t)KCLS*BCOLS*64;
    for (size_t i = (size_t)blockIdx.x*blockDim.x + threadIdx.x; i < total;
         i += (size_t)gridDim.x*blockDim.x) {
        int k = (int)(i & 63); size_t t = i >> 6;
        int col = (int)(t % BCOLS); int j = (int)(t / BCOLS);
        if (col < MSUP){
            int s = col / PP, p = col % PP;
            int img = NQ + j*SHOT + s;
            g_bankbf[i] = __float2bfloat16(
                g_bufD[((size_t)img*64+k)*PP + p] * g_rinv[(size_t)img*PP + p]);
        } else if (col >= MAUG){
            g_bankbf[i] = __float2bfloat16(0.f);
        }
    }
}
__global__ void fillbf_aug_kernel()
{
    const size_t total = (size_t)KCLS*(SELN*PP)*64;
    for (size_t i = (size_t)blockIdx.x*blockDim.x + threadIdx.x; i < total;
         i += (size_t)gridDim.x*blockDim.x) {
        int k = (int)(i & 63); size_t t = i >> 6;
        int a = (int)(t % (SELN*PP)); int j = (int)(t / (SELN*PP));
        int sel = a / PP, p = a % PP;
        int img = NQ + NS + g_selidx[j*SELN + sel];
        g_bankbf[(((size_t)j*BCOLS) + MSUP + a)*64 + k] = __float2bfloat16(
            g_bufD[((size_t)img*64+k)*PP + p] * g_rinv[(size_t)img*PP + p]);
    }
}

// ---------- unified mma.sync bf16 + register-resident top-3 ----------
// grid (rowtiles, KCLS), block 256 (8 warps), dyn smem 3*18432 = 55296B
__global__ void __launch_bounds__(256) mma_topk_kernel(int aSel, int cols)
{
    extern __shared__ char smc[];
    char* As = smc;                 // [128 rows][144B]
    char* Bs = smc + 18432;         // [2][128 cols][144B]
    const int tid = threadIdx.x;
    const int wid = tid >> 5, lane = tid & 31;
    const int g = lane >> 2, tg = lane & 3;
    const int cls = blockIdx.y;
    const int row0 = blockIdx.x*128;
    const int ntiles = (cols + CT2 - 1)/CT2;

    uint32_t sA = (uint32_t)__cvta_generic_to_shared(As);
    uint32_t sB = (uint32_t)__cvta_generic_to_shared(Bs);

    const char* aG = (const char*)(aSel ? g_qbf : g_ubf) + (size_t)row0*128;
    for (int c = tid; c < 1024; c += 256){
        int col = c >> 3, part = c & 7;
        cpasync16(sA + (uint32_t)(col*BROW + part*16), aG + (size_t)col*128 + part*16);
    }
    const char* bG = (const char*)g_bankbf + (size_t)cls*BCOLS*128;
    for (int c = tid; c < 1024; c += 256){
        int col = c >> 3, part = c & 7;
        cpasync16(sB + (uint32_t)(col*BROW + part*16), bG + (size_t)col*128 + part*16);
    }
    CP_COMMIT(); CP_WAIT0();
    __syncthreads();

    uint32_t a[4][4];
    {
        const char* ar = As + (wid*16 + g)*BROW + tg*4;
#pragma unroll
        for (int kk=0; kk<4; kk++){
            a[kk][0] = *(const uint32_t*)(ar + kk*32);
            a[kk][1] = *(const uint32_t*)(ar + 8*BROW + kk*32);
            a[kk][2] = *(const uint32_t*)(ar + kk*32 + 16);
            a[kk][3] = *(const uint32_t*)(ar + 8*BROW + kk*32 + 16);
        }
    }

    float tA0=NEGINF, tA1=NEGINF, tA2=NEGINF;   // row g
    float tB0=NEGINF, tB1=NEGINF, tB2=NEGINF;   // row g+8

    for (int t = 0; t < ntiles; ++t){
        if (t+1 < ntiles){
            const char* bN = bG + (size_t)(t+1)*CT2*128;
            uint32_t bb = sB + (uint32_t)(((t+1)&1)*18432);
            for (int c = tid; c < 1024; c += 256){
                int col = c >> 3, part = c & 7;
                cpasync16(bb + (uint32_t)(col*BROW + part*16), bN + (size_t)col*128 + part*16);
            }
            CP_COMMIT();
        }
        const char* Bp = Bs + (t&1)*18432;
#pragma unroll 4
        for (int ns = 0; ns < 16; ++ns){
            const char* br = Bp + (ns*8 + g)*BROW + tg*4;
            float c0=0.f, c1=0.f, c2=0.f, c3=0.f;
#pragma unroll
            for (int kk=0; kk<4; kk++){
                uint32_t b0 = *(const uint32_t*)(br + kk*32);
                uint32_t b1 = *(const uint32_t*)(br + kk*32 + 16);
                asm volatile(
                    "mma.sync.aligned.m16n8k16.row.col.f32.bf16.bf16.f32 "
                    "{%0,%1,%2,%3}, {%4,%5,%6,%7}, {%8,%9}, {%0,%1,%2,%3};"
                    : "+f"(c0), "+f"(c1), "+f"(c2), "+f"(c3)
                    : "r"(a[kk][0]), "r"(a[kk][1]), "r"(a[kk][2]), "r"(a[kk][3]),
                      "r"(b0), "r"(b1));
            }
            const int colBase = t*CT2 + ns*8;
            if (colBase + 8 > cols){
                if (colBase + 2*tg     >= cols){ c0 = NEGINF; c2 = NEGINF; }
                if (colBase + 2*tg + 1 >= cols){ c1 = NEGINF; c3 = NEGINF; }
            }
            ins3(c0, tA0, tA1, tA2); ins3(c1, tA0, tA1, tA2);
            ins3(c2, tB0, tB1, tB2); ins3(c3, tB0, tB1, tB2);
        }
        if (t+1 < ntiles) CP_WAIT0();
        __syncthreads();
    }

#pragma unroll
    for (int off = 1; off <= 2; off <<= 1){
        float r0 = __shfl_xor_sync(0xffffffffu, tA0, off);
        float r1 = __shfl_xor_sync(0xffffffffu, tA1, off);
        float r2 = __shfl_xor_sync(0xffffffffu, tA2, off);
        ins3(r0, tA0, tA1, tA2); ins3(r1, tA0, tA1, tA2); ins3(r2, tA0, tA1, tA2);
        float s0 = __shfl_xor_sync(0xffffffffu, tB0, off);
        float s1 = __shfl_xor_sync(0xffffffffu, tB1, off);
        float s2 = __shfl_xor_sync(0xffffffffu, tB2, off);
        ins3(s0, tB0, tB1, tB2); ins3(s1, tB0, tB1, tB2); ins3(s2, tB0, tB1, tB2);
    }
    if (tg == 0){
        int row = row0 + wid*16 + g;
        g_rowsum[(size_t)cls*QPAD + row]     = tA0 + tA1 + tA2;
        g_rowsum[(size_t)cls*QPAD + row + 8] = tB0 + tB1 + tB2;
    }
}

// ---------- per-image deterministic sum ----------
__global__ void imgsum_kernel(float* __restrict__ outp, int useOut)
{
    __shared__ float s[128];
    const int img = blockIdx.x, cls = blockIdx.y;
    const int tid = threadIdx.x;
    const float* src = g_rowsum + (size_t)cls*QPAD + (size_t)img*PP;
    float v = 0.f;
    for (int i = tid; i < PP; i += 128) v += src[i];
    s[tid] = v; __syncthreads();
    for (int st=64; st>0; st>>=1){
        if (tid < st) s[tid] += s[tid+st];
        __syncthreads();
    }
    if (tid==0){
        float* dst = useOut ? outp : g_simu;
        dst[img*KCLS + cls] = s[0];
    }
}

// ---------- softmax + per-class top-10 (lowest-index ties) ----------
__global__ void select_kernel()
{
    __shared__ float pm[NU*KCLS];
    int tid = threadIdx.x;
    if (tid < NU){
        float v[KCLS]; float mx = NEGINF;
#pragma unroll
        for (int j=0;j<KCLS;j++){ v[j] = g_simu[tid*KCLS+j]; mx = fmaxf(mx, v[j]); }
        float s = 0.f;
#pragma unroll
        for (int j=0;j<KCLS;j++){ v[j] = expf(v[j]-mx); s += v[j]; }
#pragma unroll
        for (int j=0;j<KCLS;j++) pm[tid*KCLS+j] = v[j]/s;
    }
    __syncthreads();
    if (tid < KCLS){
        unsigned long long taken = 0ull;
        for (int i=0;i<SELN;i++){
            float best = NEGINF; int bi = 0;
            for (int b=0;b<NU;b++){
                if (taken & (1ull<<b)) continue;
                float val = pm[b*KCLS+tid];
                if (val > best){ best = val; bi = b; }
            }
            taken |= (1ull<<bi);
            g_selidx[tid*SELN+i] = bi;
        }
    }
}

extern "C" void kernel_launch(void* const* d_in, const int* in_sizes, int n_in,
                              void* d_out, int out_size)
{
    (void)in_sizes; (void)n_in; (void)out_size;
    // dict order: input1..3, w1, w2, w3, w4, g1, b1, g2, b2, g3, b3, g4, b4
    const float* in1 = (const float*)d_in[0];
    const float* in2 = (const float*)d_in[1];
    const float* in3 = (const float*)d_in[2];
    const float* w1  = (const float*)d_in[3];
    const float* w2  = (const float*)d_in[4];
    const float* w3  = (const float*)d_in[5];
    const float* w4  = (const float*)d_in[6];
    const float* gg1 = (const float*)d_in[7];
    const float* bb1 = (const float*)d_in[8];
    const float* gg2 = (const float*)d_in[9];
    const float* bb2 = (const float*)d_in[10];
    const float* gg3 = (const float*)d_in[11];
    const float* bb3 = (const float*)d_in[12];
    const float* gg4 = (const float*)d_in[13];
    const float* bb4 = (const float*)d_in[14];
    float* out = (float*)d_out;

    const int SM3 = (1152 + 8*(50*18))*4;    // 33408B
    const int SM2 = (1152 + 8*(34*18))*4;    // 24192B
    const int SMM = 3*18432;                 // 55296B
    cudaFuncSetAttribute(conv64_kernel<3>, cudaFuncAttributeMaxDynamicSharedMemorySize, SM3);
    cudaFuncSetAttribute(conv64_kernel<2>, cudaFuncAttributeMaxDynamicSharedMemorySize, SM2);
    cudaFuncSetAttribute(mma_topk_kernel,  cudaFuncAttributeMaxDynamicSharedMemorySize, SMM);

    dim3 blk(16,16);
    conv1_kernel<<<dim3(6,6,NALL), blk>>>(in1, in2, in3, w1);
    bn_stats_kernel<<<dim3(64,3), 256>>>(0, H1*H1);
    bn_pool_kernel<<<2048, 256>>>(0, 1, gg1, bb1, H1, H1, 1);
    conv64_kernel<3><<<dim3(3,1,NALL*4), blk, SM3>>>(1, 2, w2, H2, H2);
    bn_stats_kernel<<<dim3(64,3), 256>>>(2, H2*H2);
    bn_pool_kernel<<<2048, 256>>>(2, 3, gg2, bb2, H2, H2, 1);
    conv64_kernel<2><<<dim3(2,1,NALL*4), blk, SM2>>>(3, 4, w3, H3, H3);
    bn_stats_kernel<<<dim3(64,3), 256>>>(4, H3*H3);
    bn_pool_kernel<<<2048, 256>>>(4, 3, gg3, bb3, H3, H3, 0);
    conv64_kernel<2><<<dim3(2,1,NALL*4), blk, SM2>>>(3, 4, w4, H3, H3);
    bn_stats_kernel<<<dim3(64,3), 256>>>(4, H3*H3);
    bn_pool_kernel<<<2048, 256>>>(4, 3, gg4, bb4, H3, H3, 0);   // final feats in D

    norm_kernel<<<NALL, 256>>>();
    fillbf_desc_kernel<<<2048, 256>>>(0);   // queries
    fillbf_desc_kernel<<<2048, 256>>>(1);   // unlabeled
    fillbf_support_kernel<<<2048, 256>>>();

    // stage 1: unlabeled rows vs support banks (bf16 mma, cols = MSUP)
    mma_topk_kernel<<<dim3(UPAD/128, KCLS), 256, SMM>>>(0, MSUP);
    imgsum_kernel<<<dim3(NU, KCLS), 128>>>(nullptr, 0);
    select_kernel<<<1, 64>>>();
    fillbf_aug_kernel<<<2048, 256>>>();

    // stage 2: query rows vs augmented banks (bf16 mma, cols = MAUG)
    mma_topk_kernel<<<dim3(QPAD/128, KCLS), 256, SMM>>>(1, MAUG);
    imgsum_kernel<<<dim3(NQ, KCLS), 128>>>(out, 1);
}

// round 12
// speedup vs baseline: 4.2908x; 1.0832x over previous
#include <cuda_runtime.h>
#include <cuda_bf16.h>
#include <math.h>
#include <stdint.h>

#define NQ 75
#define NS 25
#define NU 64
#define NALL 164
#define H1 84
#define H2 42
#define H3 21
#define PP 441
#define KCLS 5
#define SHOT 5
#define MSUP (SHOT*PP)          // 2205
#define MAUG (MSUP + 10*PP)     // 6615
#define BCOLS 6656              // 52*128
#define QROWS (NQ*PP)           // 33075
#define QPAD  33152             // 259*128
#define UROWS (NU*PP)           // 28224
#define UPAD  28288             // 221*128
#define SELN 10
#define NEGINF -3.4e38f
#define CT2 128
#define BROW 144                // padded smem row bytes (conflict-free)

__device__ float g_bufA[(size_t)NALL*64*H1*H1];
__device__ float g_bufC[(size_t)NALL*64*H2*H2];
__device__ float g_bufD[(size_t)NALL*64*H3*H3];
__device__ float g_bufE[(size_t)NALL*64*H3*H3];
__device__ float g_bufB[(size_t)NALL*64*H2*H2];
__device__ float g_rinv[(size_t)NALL*PP];
__device__ __nv_bfloat16 g_qbf[(size_t)QPAD*64];         // [row][k] bf16 queries
__device__ __nv_bfloat16 g_ubf[(size_t)UPAD*64];         // [row][k] bf16 unlabeled
__device__ __nv_bfloat16 g_bankbf[(size_t)KCLS*BCOLS*64];// [cls][col][k] bf16 banks
__device__ float g_rowsum[(size_t)KCLS*QPAD];
__device__ float g_stats[3*64*2];
__device__ float g_simu[NU*KCLS];
__device__ int   g_selidx[KCLS*SELN];

__device__ __forceinline__ float* bufPtr(int s){
    switch(s){
        case 0: return g_bufA; case 1: return g_bufB; case 2: return g_bufC;
        case 3: return g_bufD; default: return g_bufE;
    }
}
__device__ __forceinline__ int groupOf(int n){ return (n < NQ) ? 0 : ((n < NQ+NS) ? 1 : 2); }

__device__ __forceinline__ void cpasync16(uint32_t dst, const void* src){
    asm volatile("cp.async.cg.shared.global [%0], [%1], 16;\n" :: "r"(dst), "l"(src));
}
#define CP_COMMIT() asm volatile("cp.async.commit_group;\n" ::: "memory")
#define CP_WAIT0()  asm volatile("cp.async.wait_group 0;\n" ::: "memory")

__device__ __forceinline__ void ins3(float v, float& t0, float& t1, float& t2){
    if (v > t2){
        if (v > t0){ t2 = t1; t1 = t0; t0 = v; }
        else if (v > t1){ t2 = t1; t1 = v; }
        else t2 = v;
    }
}

// ---------- conv1: 3->64, 84x84 SAME ----------
__global__ void conv1_kernel(const float* __restrict__ in1, const float* __restrict__ in2,
                             const float* __restrict__ in3, const float* __restrict__ w)
{
    __shared__ float sW[64*27];
    __shared__ float sIn[3*18*18];
    const int n = blockIdx.z;
    const int gx0 = blockIdx.x*16, gy0 = blockIdx.y*16;
    const int tx = threadIdx.x, ty = threadIdx.y;
    const int tid = ty*16 + tx;
    const float* img = (n < NQ)    ? (in1 + (size_t)n*3*H1*H1)
                     : (n < NQ+NS) ? (in2 + (size_t)(n-NQ)*3*H1*H1)
                                   : (in3 + (size_t)(n-NQ-NS)*3*H1*H1);
    for (int i = tid; i < 64*27; i += 256) sW[i] = w[i];
    for (int i = tid; i < 3*18*18; i += 256) {
        int c = i / 324, rem = i % 324, r = rem/18, cc = rem%18;
        int gy = gy0 - 1 + r, gx = gx0 - 1 + cc;
        sIn[i] = (gy>=0 && gy<H1 && gx>=0 && gx<H1) ? img[((size_t)c*H1+gy)*H1+gx] : 0.f;
    }
    __syncthreads();
    int ox = gx0+tx, oy = gy0+ty;
    if (ox >= H1 || oy >= H1) return;
    float v[27];
#pragma unroll
    for (int c=0;c<3;c++)
#pragma unroll
      for (int dy=0;dy<3;dy++)
#pragma unroll
        for (int dx=0;dx<3;dx++)
          v[c*9+dy*3+dx] = sIn[c*324 + (ty+dy)*18 + (tx+dx)];
#pragma unroll 4
    for (int oc=0; oc<64; oc++){
        float acc = 0.f;
        const float* wp = sW + oc*27;
#pragma unroll
        for (int j=0;j<27;j++) acc += wp[j]*v[j];
        g_bufA[(((size_t)n*64+oc)*H1+oy)*H1+ox] = acc;
    }
}

// ---------- conv 64->64 3x3 SAME v4 ----------
// grid.z = n*4 + ocg ; block (16,16); ty half selects 8-oc subgroup,
// 8 row-groups of RPT rows. ic chunked by 8. Bit-identical accumulation order.
template<int RPT>
__global__ void conv64_kernel(int inSel, int outSel, const float* __restrict__ wt, int H, int W)
{
    extern __shared__ float sm[];
    float* sW  = sm;              // [16 oc][8 ic][9] = 1152 floats
    float* sIn = sm + 1152;       // [8 ic][HALO]
    constexpr int TH   = 8*RPT;
    constexpr int HALO = (TH+2)*18;
    const int z   = blockIdx.z;
    const int n   = z >> 2;
    const int ocg = z & 3;
    const int gx0 = blockIdx.x*16;
    const int gy0 = blockIdx.y*TH;
    const int tx = threadIdx.x, ty = threadIdx.y;
    const int tid = ty*16 + tx;
    const int half = ty >> 3;           // 0: oc 0-7, 1: oc 8-15
    const int tyr  = ty & 7;            // row group
    const int oyb = gy0 + tyr*RPT;
    const int ox  = gx0 + tx;
    const bool anyValid = (ox < W) && (oyb < H);
    const float* inN  = bufPtr(inSel)  + (size_t)n*64*H*W;
    float*       outN = bufPtr(outSel) + (size_t)n*64*H*W;

    float acc[8][RPT];
#pragma unroll
    for (int o=0;o<8;o++)
#pragma unroll
      for (int r=0;r<RPT;r++) acc[o][r]=0.f;

    for (int cc = 0; cc < 8; ++cc) {
        __syncthreads();
        for (int i = tid; i < 1152; i += 256) {
            int o = i / 72, rem = i % 72;
            sW[i] = wt[(size_t)(ocg*16+o)*576 + cc*72 + rem];
        }
        for (int i = tid; i < 8*HALO; i += 256) {
            int c = i / HALO, rem = i % HALO, r = rem/18, col = rem%18;
            int gy = gy0-1+r, gx = gx0-1+col;
            float v = 0.f;
            if (gy>=0 && gy<H && gx>=0 && gx<W)
                v = inN[((size_t)(cc*8+c)*H+gy)*W+gx];
            sIn[i] = v;
        }
        __syncthreads();
        if (anyValid) {
            for (int ic=0; ic<8; ++ic) {
                float v[RPT+2][3];
                const float* sp = sIn + ic*HALO + (tyr*RPT)*18 + tx;
#pragma unroll
                for (int r=0;r<RPT+2;r++)
#pragma unroll
                  for (int d=0;d<3;d++) v[r][d] = sp[r*18+d];
                const float* wp = sW + (half*8)*72 + ic*9;
#pragma unroll
                for (int o=0;o<8;o++){
                    const float* wo = wp + o*72;
                    float w0=wo[0],w1=wo[1],w2=wo[2],w3=wo[3],w4=wo[4];
                    float w5=wo[5],w6=wo[6],w7=wo[7],w8=wo[8];
#pragma unroll
                    for (int r=0;r<RPT;r++){
                        float a = acc[o][r];
                        a += w0*v[r  ][0]; a += w1*v[r  ][1]; a += w2*v[r  ][2];
                        a += w3*v[r+1][0]; a += w4*v[r+1][1]; a += w5*v[r+1][2];
                        a += w6*v[r+2][0]; a += w7*v[r+2][1]; a += w8*v[r+2][2];
                        acc[o][r] = a;
                    }
                }
            }
        }
    }
    if (anyValid) {
#pragma unroll
        for (int o=0;o<8;o++){
            int oc = ocg*16 + half*8 + o;
#pragma unroll
            for (int r=0;r<RPT;r++){
                int oy = oyb + r;
                if (oy < H) outN[((size_t)oc*H+oy)*W+ox] = acc[o][r];
            }
        }
    }
}

// ---------- BN stats ----------
__global__ void bn_stats_kernel(int sel, int HW)
{
    __shared__ double ssum[256], ssum2[256];
    const int ch = blockIdx.x, g = blockIdx.y;
    const int n0 = (g==0)?0:((g==1)?NQ:(NQ+NS));
    const int n1 = (g==0)?NQ:((g==1)?(NQ+NS):NALL);
    const int tid = threadIdx.x;
    const float* buf = bufPtr(sel);
    double s=0.0, s2=0.0;
    for (int n=n0; n<n1; ++n) {
        const float* p = buf + ((size_t)n*64+ch)*HW;
        for (int i=tid;i<HW;i+=256){ double x = (double)p[i]; s+=x; s2+=x*x; }
    }
    ssum[tid]=s; ssum2[tid]=s2; __syncthreads();
    for (int st=128; st>0; st>>=1){
        if (tid<st){ ssum[tid]+=ssum[tid+st]; ssum2[tid]+=ssum2[tid+st]; }
        __syncthreads();
    }
    if (tid==0){
        double cnt = (double)(n1-n0)*HW;
        double mean = ssum[0]/cnt;
        double var  = ssum2[0]/cnt - mean*mean;
        g_stats[(g*64+ch)*2+0] = (float)mean;
        g_stats[(g*64+ch)*2+1] = (float)(1.0/sqrt(var + 1e-5));
    }
}

// ---------- BN + LeakyReLU (+pool) ----------
__global__ void bn_pool_kernel(int inSel, int outSel, const float* __restrict__ gamma,
                               const float* __restrict__ beta, int H, int W, int doPool)
{
    const int oH = doPool ? H/2 : H, oW = doPool ? W/2 : W;
    const size_t total = (size_t)NALL*64*oH*oW;
    const float* in = bufPtr(inSel);
    float* out = bufPtr(outSel);
    for (size_t idx = (size_t)blockIdx.x*blockDim.x + threadIdx.x; idx < total;
         idx += (size_t)gridDim.x*blockDim.x) {
        int ox = (int)(idx % oW); size_t t = idx / oW;
        int oy = (int)(t % oH);   t /= oH;
        int c  = (int)(t % 64);   int n = (int)(t / 64);
        int g = groupOf(n);
        float mean = g_stats[(g*64+c)*2+0], rsig = g_stats[(g*64+c)*2+1];
        float sc = gamma[c]*rsig;
        float sh = beta[c] - mean*sc;
        const float* p = in + ((size_t)n*64+c)*H*W;
        float r;
        if (doPool){
            float x0 = p[(size_t)(2*oy)*W + 2*ox  ]*sc+sh;
            float x1 = p[(size_t)(2*oy)*W + 2*ox+1]*sc+sh;
            float x2 = p[(size_t)(2*oy+1)*W + 2*ox  ]*sc+sh;
            float x3 = p[(size_t)(2*oy+1)*W + 2*ox+1]*sc+sh;
            x0 = x0>=0.f?x0:0.2f*x0; x1 = x1>=0.f?x1:0.2f*x1;
            x2 = x2>=0.f?x2:0.2f*x2; x3 = x3>=0.f?x3:0.2f*x3;
            r = fmaxf(fmaxf(x0,x1), fmaxf(x2,x3));
        } else {
            float x = p[(size_t)oy*W+ox]*sc+sh;
            r = x>=0.f?x:0.2f*x;
        }
        out[idx] = r;
    }
}

// ---------- descriptor inverse norms ----------
__global__ void norm_kernel()
{
    int img = blockIdx.x;
    for (int p = threadIdx.x; p < PP; p += blockDim.x){
        float ss = 0.f;
        const float* f = g_bufD + (size_t)img*64*PP + p;
#pragma unroll
        for (int c=0;c<64;c++){ float x = f[(size_t)c*PP]; ss += x*x; }
        g_rinv[(size_t)img*PP + p] = rsqrtf(ss);
    }
}

// ---------- bf16 descriptor buffers: mode 0 = queries, 1 = unlabeled ----------
__global__ void fillbf_desc_kernel(int mode)
{
    const int pad = mode ? UPAD : QPAD;
    const int nrows = mode ? UROWS : QROWS;
    const int imgBase = mode ? (NQ+NS) : 0;
    __nv_bfloat16* dst = mode ? g_ubf : g_qbf;
    const size_t total = (size_t)pad*64;
    for (size_t i = (size_t)blockIdx.x*blockDim.x + threadIdx.x; i < total;
         i += (size_t)gridDim.x*blockDim.x) {
        int k = (int)(i & 63); int row = (int)(i >> 6);
        float v = 0.f;
        if (row < nrows){
            int img = imgBase + row / PP, p = row % PP;
            v = g_bufD[((size_t)img*64+k)*PP + p] * g_rinv[(size_t)img*PP + p];
        }
        dst[i] = __float2bfloat16(v);
    }
}
__global__ void fillbf_support_kernel()
{
    const size_t total = (size_t)KCLS*BCOLS*64;
    for (size_t i = (size_t)blockIdx.x*blockDim.x + threadIdx.x; i < total;
         i += (size_t)gridDim.x*blockDim.x) {
        int k = (int)(i & 63); size_t t = i >> 6;
        int col = (int)(t % BCOLS); int j = (int)(t / BCOLS);
        if (col < MSUP){
            int s = col / PP, p = col % PP;
            int img = NQ + j*SHOT + s;
            g_bankbf[i] = __float2bfloat16(
                g_bufD[((size_t)img*64+k)*PP + p] * g_rinv[(size_t)img*PP + p]);
        } else if (col >= MAUG){
            g_bankbf[i] = __float2bfloat16(0.f);
        }
    }
}
__global__ void fillbf_aug_kernel()
{
    const size_t total = (size_t)KCLS*(SELN*PP)*64;
    for (size_t i = (size_t)blockIdx.x*blockDim.x + threadIdx.x; i < total;
         i += (size_t)gridDim.x*blockDim.x) {
        int k = (int)(i & 63); size_t t = i >> 6;
        int a = (int)(t % (SELN*PP)); int j = (int)(t / (SELN*PP));
        int sel = a / PP, p = a % PP;
        int img = NQ + NS + g_selidx[j*SELN + sel];
        g_bankbf[(((size_t)j*BCOLS) + MSUP + a)*64 + k] = __float2bfloat16(
            g_bufD[((size_t)img*64+k)*PP + p] * g_rinv[(size_t)img*PP + p]);
    }
}

// ---------- unified mma.sync bf16 + register-resident top-3 ----------
__global__ void __launch_bounds__(256) mma_topk_kernel(int aSel, int cols)
{
    extern __shared__ char smc[];
    char* As = smc;                 // [128 rows][144B]
    char* Bs = smc + 18432;         // [2][128 cols][144B]
    const int tid = threadIdx.x;
    const int wid = tid >> 5, lane = tid & 31;
    const int g = lane >> 2, tg = lane & 3;
    const int cls = blockIdx.y;
    const int row0 = blockIdx.x*128;
    const int ntiles = (cols + CT2 - 1)/CT2;

    uint32_t sA = (uint32_t)__cvta_generic_to_shared(As);
    uint32_t sB = (uint32_t)__cvta_generic_to_shared(Bs);

    const char* aG = (const char*)(aSel ? g_qbf : g_ubf) + (size_t)row0*128;
    for (int c = tid; c < 1024; c += 256){
        int col = c >> 3, part = c & 7;
        cpasync16(sA + (uint32_t)(col*BROW + part*16), aG + (size_t)col*128 + part*16);
    }
    const char* bG = (const char*)g_bankbf + (size_t)cls*BCOLS*128;
    for (int c = tid; c < 1024; c += 256){
        int col = c >> 3, part = c & 7;
        cpasync16(sB + (uint32_t)(col*BROW + part*16), bG + (size_t)col*128 + part*16);
    }
    CP_COMMIT(); CP_WAIT0();
    __syncthreads();

    uint32_t a[4][4];
    {
        const char* ar = As + (wid*16 + g)*BROW + tg*4;
#pragma unroll
        for (int kk=0; kk<4; kk++){
            a[kk][0] = *(const uint32_t*)(ar + kk*32);
            a[kk][1] = *(const uint32_t*)(ar + 8*BROW + kk*32);
            a[kk][2] = *(const uint32_t*)(ar + kk*32 + 16);
            a[kk][3] = *(const uint32_t*)(ar + 8*BROW + kk*32 + 16);
        }
    }

    float tA0=NEGINF, tA1=NEGINF, tA2=NEGINF;
    float tB0=NEGINF, tB1=NEGINF, tB2=NEGINF;

    for (int t = 0; t < ntiles; ++t){
        if (t+1 < ntiles){
            const char* bN = bG + (size_t)(t+1)*CT2*128;
            uint32_t bb = sB + (uint32_t)(((t+1)&1)*18432);
            for (int c = tid; c < 1024; c += 256){
                int col = c >> 3, part = c & 7;
                cpasync16(bb + (uint32_t)(col*BROW + part*16), bN + (size_t)col*128 + part*16);
            }
            CP_COMMIT();
        }
        const char* Bp = Bs + (t&1)*18432;
#pragma unroll 4
        for (int ns = 0; ns < 16; ++ns){
            const char* br = Bp + (ns*8 + g)*BROW + tg*4;
            float c0=0.f, c1=0.f, c2=0.f, c3=0.f;
#pragma unroll
            for (int kk=0; kk<4; kk++){
                uint32_t b0 = *(const uint32_t*)(br + kk*32);
                uint32_t b1 = *(const uint32_t*)(br + kk*32 + 16);
                asm volatile(
                    "mma.sync.aligned.m16n8k16.row.col.f32.bf16.bf16.f32 "
                    "{%0,%1,%2,%3}, {%4,%5,%6,%7}, {%8,%9}, {%0,%1,%2,%3};"
                    : "+f"(c0), "+f"(c1), "+f"(c2), "+f"(c3)
                    : "r"(a[kk][0]), "r"(a[kk][1]), "r"(a[kk][2]), "r"(a[kk][3]),
                      "r"(b0), "r"(b1));
            }
            const int colBase = t*CT2 + ns*8;
            if (colBase + 8 > cols){
                if (colBase + 2*tg     >= cols){ c0 = NEGINF; c2 = NEGINF; }
                if (colBase + 2*tg + 1 >= cols){ c1 = NEGINF; c3 = NEGINF; }
            }
            ins3(c0, tA0, tA1, tA2); ins3(c1, tA0, tA1, tA2);
            ins3(c2, tB0, tB1, tB2); ins3(c3, tB0, tB1, tB2);
        }
        if (t+1 < ntiles) CP_WAIT0();
        __syncthreads();
    }

#pragma unroll
    for (int off = 1; off <= 2; off <<= 1){
        float r0 = __shfl_xor_sync(0xffffffffu, tA0, off);
        float r1 = __shfl_xor_sync(0xffffffffu, tA1, off);
        float r2 = __shfl_xor_sync(0xffffffffu, tA2, off);
        ins3(r0, tA0, tA1, tA2); ins3(r1, tA0, tA1, tA2); ins3(r2, tA0, tA1, tA2);
        float s0 = __shfl_xor_sync(0xffffffffu, tB0, off);
        float s1 = __shfl_xor_sync(0xffffffffu, tB1, off);
        float s2 = __shfl_xor_sync(0xffffffffu, tB2, off);
        ins3(s0, tB0, tB1, tB2); ins3(s1, tB0, tB1, tB2); ins3(s2, tB0, tB1, tB2);
    }
    if (tg == 0){
        int row = row0 + wid*16 + g;
        g_rowsum[(size_t)cls*QPAD + row]     = tA0 + tA1 + tA2;
        g_rowsum[(size_t)cls*QPAD + row + 8] = tB0 + tB1 + tB2;
    }
}

// ---------- per-image deterministic sum ----------
__global__ void imgsum_kernel(float* __restrict__ outp, int useOut)
{
    __shared__ float s[128];
    const int img = blockIdx.x, cls = blockIdx.y;
    const int tid = threadIdx.x;
    const float* src = g_rowsum + (size_t)cls*QPAD + (size_t)img*PP;
    float v = 0.f;
    for (int i = tid; i < PP; i += 128) v += src[i];
    s[tid] = v; __syncthreads();
    for (int st=64; st>0; st>>=1){
        if (tid < st) s[tid] += s[tid+st];
        __syncthreads();
    }
    if (tid==0){
        float* dst = useOut ? outp : g_simu;
        dst[img*KCLS + cls] = s[0];
    }
}

// ---------- softmax + per-class top-10 (lowest-index ties) ----------
__global__ void select_kernel()
{
    __shared__ float pm[NU*KCLS];
    int tid = threadIdx.x;
    if (tid < NU){
        float v[KCLS]; float mx = NEGINF;
#pragma unroll
        for (int j=0;j<KCLS;j++){ v[j] = g_simu[tid*KCLS+j]; mx = fmaxf(mx, v[j]); }
        float s = 0.f;
#pragma unroll
        for (int j=0;j<KCLS;j++){ v[j] = expf(v[j]-mx); s += v[j]; }
#pragma unroll
        for (int j=0;j<KCLS;j++) pm[tid*KCLS+j] = v[j]/s;
    }
    __syncthreads();
    if (tid < KCLS){
        unsigned long long taken = 0ull;
        for (int i=0;i<SELN;i++){
            float best = NEGINF; int bi = 0;
            for (int b=0;b<NU;b++){
                if (taken & (1ull<<b)) continue;
                float val = pm[b*KCLS+tid];
                if (val > best){ best = val; bi = b; }
            }
            taken |= (1ull<<bi);
            g_selidx[tid*SELN+i] = bi;
        }
    }
}

extern "C" void kernel_launch(void* const* d_in, const int* in_sizes, int n_in,
                              void* d_out, int out_size)
{
    (void)in_sizes; (void)n_in; (void)out_size;
    // dict order: input1..3, w1, w2, w3, w4, g1, b1, g2, b2, g3, b3, g4, b4
    const float* in1 = (const float*)d_in[0];
    const float* in2 = (const float*)d_in[1];
    const float* in3 = (const float*)d_in[2];
    const float* w1  = (const float*)d_in[3];
    const float* w2  = (const float*)d_in[4];
    const float* w3  = (const float*)d_in[5];
    const float* w4  = (const float*)d_in[6];
    const float* gg1 = (const float*)d_in[7];
    const float* bb1 = (const float*)d_in[8];
    const float* gg2 = (const float*)d_in[9];
    const float* bb2 = (const float*)d_in[10];
    const float* gg3 = (const float*)d_in[11];
    const float* bb3 = (const float*)d_in[12];
    const float* gg4 = (const float*)d_in[13];
    const float* bb4 = (const float*)d_in[14];
    float* out = (float*)d_out;

    const int SM3 = (1152 + 8*(50*18))*4;    // conv64<6>: 33408B  (TH=48)
    const int SM2 = (1152 + 8*(26*18))*4;    // conv64<3>: 19584B  (TH=24)
    const int SMM = 3*18432;                 // 55296B
    cudaFuncSetAttribute(conv64_kernel<6>, cudaFuncAttributeMaxDynamicSharedMemorySize, SM3);
    cudaFuncSetAttribute(conv64_kernel<3>, cudaFuncAttributeMaxDynamicSharedMemorySize, SM2);
    cudaFuncSetAttribute(mma_topk_kernel,  cudaFuncAttributeMaxDynamicSharedMemorySize, SMM);

    dim3 blk(16,16);
    conv1_kernel<<<dim3(6,6,NALL), blk>>>(in1, in2, in3, w1);
    bn_stats_kernel<<<dim3(64,3), 256>>>(0, H1*H1);
    bn_pool_kernel<<<2048, 256>>>(0, 1, gg1, bb1, H1, H1, 1);
    conv64_kernel<6><<<dim3(3,1,NALL*4), blk, SM3>>>(1, 2, w2, H2, H2);   // 42x42, TH=48
    bn_stats_kernel<<<dim3(64,3), 256>>>(2, H2*H2);
    bn_pool_kernel<<<2048, 256>>>(2, 3, gg2, bb2, H2, H2, 1);
    conv64_kernel<3><<<dim3(2,1,NALL*4), blk, SM2>>>(3, 4, w3, H3, H3);   // 21x21, TH=24
    bn_stats_kernel<<<dim3(64,3), 256>>>(4, H3*H3);
    bn_pool_kernel<<<2048, 256>>>(4, 3, gg3, bb3, H3, H3, 0);
    conv64_kernel<3><<<dim3(2,1,NALL*4), blk, SM2>>>(3, 4, w4, H3, H3);
    bn_stats_kernel<<<dim3(64,3), 256>>>(4, H3*H3);
    bn_pool_kernel<<<2048, 256>>>(4, 3, gg4, bb4, H3, H3, 0);   // final feats in D

    norm_kernel<<<NALL, 256>>>();
    fillbf_desc_kernel<<<2048, 256>>>(0);   // queries
    fillbf_desc_kernel<<<2048, 256>>>(1);   // unlabeled
    fillbf_support_kernel<<<2048, 256>>>();

    // stage 1: unlabeled rows vs support banks (bf16 mma, cols = MSUP)
    mma_topk_kernel<<<dim3(UPAD/128, KCLS), 256, SMM>>>(0, MSUP);
    imgsum_kernel<<<dim3(NU, KCLS), 128>>>(nullptr, 0);
    select_kernel<<<1, 64>>>();
    fillbf_aug_kernel<<<2048, 256>>>();

    // stage 2: query rows vs augmented banks (bf16 mma, cols = MAUG)
    mma_topk_kernel<<<dim3(QPAD/128, KCLS), 256, SMM>>>(1, MAUG);
    imgsum_kernel<<<dim3(NQ, KCLS), 128>>>(out, 1);
}

// round 14
// speedup vs baseline: 4.3993x; 1.0253x over previous
#include <cuda_runtime.h>
#include <cuda_bf16.h>
#include <math.h>
#include <stdint.h>

#define NQ 75
#define NS 25
#define NU 64
#define NALL 164
#define H1 84
#define H2 42
#define H3 21
#define PP 441
#define KCLS 5
#define SHOT 5
#define MSUP (SHOT*PP)          // 2205
#define MAUG (MSUP + 10*PP)     // 6615
#define BCOLS 6656              // 52*128
#define QROWS (NQ*PP)           // 33075
#define QPAD  33152             // 259*128
#define UROWS (NU*PP)           // 28224
#define UPAD  28288             // 221*128
#define SELN 10
#define NEGINF -3.4e38f
#define CT2 128
#define BROW 144

__device__ float g_bufA[(size_t)NALL*64*H1*H1];
__device__ float g_bufC[(size_t)NALL*64*H2*H2];
__device__ float g_bufD[(size_t)NALL*64*H3*H3];
__device__ float g_bufE[(size_t)NALL*64*H3*H3];
__device__ float g_bufB[(size_t)NALL*64*H2*H2];
__device__ float g_rinv[(size_t)NALL*PP];
__device__ __nv_bfloat16 g_qbf[(size_t)QPAD*64];
__device__ __nv_bfloat16 g_ubf[(size_t)UPAD*64];
__device__ __nv_bfloat16 g_bankbf[(size_t)KCLS*BCOLS*64];
__device__ float g_rowsum[(size_t)KCLS*QPAD];
__device__ float g_stats[3*64*2];
__device__ float g_simu[NU*KCLS];
__device__ int   g_selidx[KCLS*SELN];

__device__ __forceinline__ float* bufPtr(int s){
    switch(s){
        case 0: return g_bufA; case 1: return g_bufB; case 2: return g_bufC;
        case 3: return g_bufD; default: return g_bufE;
    }
}
__device__ __forceinline__ int groupOf(int n){ return (n < NQ) ? 0 : ((n < NQ+NS) ? 1 : 2); }

__device__ __forceinline__ void cpasync16(uint32_t dst, const void* src){
    asm volatile("cp.async.cg.shared.global [%0], [%1], 16;\n" :: "r"(dst), "l"(src));
}
#define CP_COMMIT() asm volatile("cp.async.commit_group;\n" ::: "memory")
#define CP_WAIT0()  asm volatile("cp.async.wait_group 0;\n" ::: "memory")

__device__ __forceinline__ void ins3(float v, float& t0, float& t1, float& t2){
    if (v > t2){
        if (v > t0){ t2 = t1; t1 = t0; t0 = v; }
        else if (v > t1){ t2 = t1; t1 = v; }
        else t2 = v;
    }
}

// ---------- conv1: 3->64, 84x84 SAME ; weights padded to 28, float4 reads ----------
__global__ void conv1_kernel(const float* __restrict__ in1, const float* __restrict__ in2,
                             const float* __restrict__ in3, const float* __restrict__ w)
{
    __shared__ float sW[64*28];
    __shared__ float sIn[3*18*18];
    const int n = blockIdx.z;
    const int gx0 = blockIdx.x*16, gy0 = blockIdx.y*16;
    const int tx = threadIdx.x, ty = threadIdx.y;
    const int tid = ty*16 + tx;
    const float* img = (n < NQ)    ? (in1 + (size_t)n*3*H1*H1)
                     : (n < NQ+NS) ? (in2 + (size_t)(n-NQ)*3*H1*H1)
                                   : (in3 + (size_t)(n-NQ-NS)*3*H1*H1);
    for (int i = tid; i < 64*27; i += 256){
        int oc = i / 27, j = i % 27;
        sW[oc*28 + j] = w[i];
    }
    for (int i = tid; i < 3*18*18; i += 256) {
        int c = i / 324, rem = i % 324, r = rem/18, cc = rem%18;
        int gy = gy0 - 1 + r, gx = gx0 - 1 + cc;
        sIn[i] = (gy>=0 && gy<H1 && gx>=0 && gx<H1) ? img[((size_t)c*H1+gy)*H1+gx] : 0.f;
    }
    __syncthreads();
    int ox = gx0+tx, oy = gy0+ty;
    if (ox >= H1 || oy >= H1) return;
    float v[27];
#pragma unroll
    for (int c=0;c<3;c++)
#pragma unroll
      for (int dy=0;dy<3;dy++)
#pragma unroll
        for (int dx=0;dx<3;dx++)
          v[c*9+dy*3+dx] = sIn[c*324 + (ty+dy)*18 + (tx+dx)];
#pragma unroll 2
    for (int oc=0; oc<64; oc++){
        const float* wp = sW + oc*28;
        float4 q0 = *(const float4*)(wp);
        float4 q1 = *(const float4*)(wp+4);
        float4 q2 = *(const float4*)(wp+8);
        float4 q3 = *(const float4*)(wp+12);
        float4 q4 = *(const float4*)(wp+16);
        float4 q5 = *(const float4*)(wp+20);
        float  w24 = wp[24], w25 = wp[25], w26 = wp[26];
        float acc = 0.f;
        acc += q0.x*v[0];  acc += q0.y*v[1];  acc += q0.z*v[2];  acc += q0.w*v[3];
        acc += q1.x*v[4];  acc += q1.y*v[5];  acc += q1.z*v[6];  acc += q1.w*v[7];
        acc += q2.x*v[8];  acc += q2.y*v[9];  acc += q2.z*v[10]; acc += q2.w*v[11];
        acc += q3.x*v[12]; acc += q3.y*v[13]; acc += q3.z*v[14]; acc += q3.w*v[15];
        acc += q4.x*v[16]; acc += q4.y*v[17]; acc += q4.z*v[18]; acc += q4.w*v[19];
        acc += q5.x*v[20]; acc += q5.y*v[21]; acc += q5.z*v[22]; acc += q5.w*v[23];
        acc += w24*v[24];  acc += w25*v[25];  acc += w26*v[26];
        g_bufA[(((size_t)n*64+oc)*H1+oy)*H1+ox] = acc;
    }
}

// ---------- conv 64->64 3x3 SAME v5 ----------
// grid.z = n*4 + ocg ; block (16,16); ty half = 8-oc subgroup; ic chunked by 8.
// Weight rows padded to 12 floats for float4 reads. Bit-identical accumulation.
template<int RPT>
__global__ void conv64_kernel(int inSel, int outSel, const float* __restrict__ wt, int H, int W)
{
    extern __shared__ float sm[];
    float* sW  = sm;              // [16 oc][8 ic][12] = 1536 floats
    float* sIn = sm + 1536;       // [8 ic][HALO]
    constexpr int TH   = 8*RPT;
    constexpr int HALO = (TH+2)*18;
    const int z   = blockIdx.z;
    const int n   = z >> 2;
    const int ocg = z & 3;
    const int gx0 = blockIdx.x*16;
    const int gy0 = blockIdx.y*TH;
    const int tx = threadIdx.x, ty = threadIdx.y;
    const int tid = ty*16 + tx;
    const int half = ty >> 3;
    const int tyr  = ty & 7;
    const int oyb = gy0 + tyr*RPT;
    const int ox  = gx0 + tx;
    const bool anyValid = (ox < W) && (oyb < H);
    const float* inN  = bufPtr(inSel)  + (size_t)n*64*H*W;
    float*       outN = bufPtr(outSel) + (size_t)n*64*H*W;

    float acc[8][RPT];
#pragma unroll
    for (int o=0;o<8;o++)
#pragma unroll
      for (int r=0;r<RPT;r++) acc[o][r]=0.f;

    for (int cc = 0; cc < 8; ++cc) {
        __syncthreads();
        // weights: [o][ic8][12] padded rows
        for (int i = tid; i < 1152; i += 256) {
            int o = i / 72, rem = i % 72;
            int ic = rem / 9, j = rem % 9;
            sW[o*96 + ic*12 + j] = wt[(size_t)(ocg*16+o)*576 + cc*72 + rem];
        }
        for (int i = tid; i < 8*HALO; i += 256) {
            int c = i / HALO, rem = i % HALO, r = rem/18, col = rem%18;
            int gy = gy0-1+r, gx = gx0-1+col;
            float v = 0.f;
            if (gy>=0 && gy<H && gx>=0 && gx<W)
                v = inN[((size_t)(cc*8+c)*H+gy)*W+gx];
            sIn[i] = v;
        }
        __syncthreads();
        if (anyValid) {
            for (int ic=0; ic<8; ++ic) {
                float v[RPT+2][3];
                const float* sp = sIn + ic*HALO + (tyr*RPT)*18 + tx;
#pragma unroll
                for (int r=0;r<RPT+2;r++)
#pragma unroll
                  for (int d=0;d<3;d++) v[r][d] = sp[r*18+d];
                const float* wpB = sW + (half*8)*96 + ic*12;
#pragma unroll
                for (int o=0;o<8;o++){
                    const float* wo = wpB + o*96;
                    float4 qa = *(const float4*)(wo);
                    float4 qb = *(const float4*)(wo+4);
                    float  w8 = wo[8];
                    float w0=qa.x,w1=qa.y,w2=qa.z,w3=qa.w;
                    float w4=qb.x,w5=qb.y,w6=qb.z,w7=qb.w;
#pragma unroll
                    for (int r=0;r<RPT;r++){
                        float a = acc[o][r];
                        a += w0*v[r  ][0]; a += w1*v[r  ][1]; a += w2*v[r  ][2];
                        a += w3*v[r+1][0]; a += w4*v[r+1][1]; a += w5*v[r+1][2];
                        a += w6*v[r+2][0]; a += w7*v[r+2][1]; a += w8*v[r+2][2];
                        acc[o][r] = a;
                    }
                }
            }
        }
    }
    if (anyValid) {
#pragma unroll
        for (int o=0;o<8;o++){
            int oc = ocg*16 + half*8 + o;
#pragma unroll
            for (int r=0;r<RPT;r++){
                int oy = oyb + r;
                if (oy < H) outN[((size_t)oc*H+oy)*W+ox] = acc[o][r];
            }
        }
    }
}

// ---------- BN stats ----------
__global__ void bn_stats_kernel(int sel, int HW)
{
    __shared__ double ssum[256], ssum2[256];
    const int ch = blockIdx.x, g = blockIdx.y;
    const int n0 = (g==0)?0:((g==1)?NQ:(NQ+NS));
    const int n1 = (g==0)?NQ:((g==1)?(NQ+NS):NALL);
    const int tid = threadIdx.x;
    const float* buf = bufPtr(sel);
    double s=0.0, s2=0.0;
    for (int n=n0; n<n1; ++n) {
        const float* p = buf + ((size_t)n*64+ch)*HW;
        for (int i=tid;i<HW;i+=256){ double x = (double)p[i]; s+=x; s2+=x*x; }
    }
    ssum[tid]=s; ssum2[tid]=s2; __syncthreads();
    for (int st=128; st>0; st>>=1){
        if (tid<st){ ssum[tid]+=ssum[tid+st]; ssum2[tid]+=ssum2[tid+st]; }
        __syncthreads();
    }
    if (tid==0){
        double cnt = (double)(n1-n0)*HW;
        double mean = ssum[0]/cnt;
        double var  = ssum2[0]/cnt - mean*mean;
        g_stats[(g*64+ch)*2+0] = (float)mean;
        g_stats[(g*64+ch)*2+1] = (float)(1.0/sqrt(var + 1e-5));
    }
}

// ---------- BN + LeakyReLU (+pool) ----------
__global__ void bn_pool_kernel(int inSel, int outSel, const float* __restrict__ gamma,
                               const float* __restrict__ beta, int H, int W, int doPool)
{
    const int oH = doPool ? H/2 : H, oW = doPool ? W/2 : W;
    const size_t total = (size_t)NALL*64*oH*oW;
    const float* in = bufPtr(inSel);
    float* out = bufPtr(outSel);
    for (size_t idx = (size_t)blockIdx.x*blockDim.x + threadIdx.x; idx < total;
         idx += (size_t)gridDim.x*blockDim.x) {
        int ox = (int)(idx % oW); size_t t = idx / oW;
        int oy = (int)(t % oH);   t /= oH;
        int c  = (int)(t % 64);   int n = (int)(t / 64);
        int g = groupOf(n);
        float mean = g_stats[(g*64+c)*2+0], rsig = g_stats[(g*64+c)*2+1];
        float sc = gamma[c]*rsig;
        float sh = beta[c] - mean*sc;
        const float* p = in + ((size_t)n*64+c)*H*W;
        float r;
        if (doPool){
            float x0 = p[(size_t)(2*oy)*W + 2*ox  ]*sc+sh;
            float x1 = p[(size_t)(2*oy)*W + 2*ox+1]*sc+sh;
            float x2 = p[(size_t)(2*oy+1)*W + 2*ox  ]*sc+sh;
            float x3 = p[(size_t)(2*oy+1)*W + 2*ox+1]*sc+sh;
            x0 = x0>=0.f?x0:0.2f*x0; x1 = x1>=0.f?x1:0.2f*x1;
            x2 = x2>=0.f?x2:0.2f*x2; x3 = x3>=0.f?x3:0.2f*x3;
            r = fmaxf(fmaxf(x0,x1), fmaxf(x2,x3));
        } else {
            float x = p[(size_t)oy*W+ox]*sc+sh;
            r = x>=0.f?x:0.2f*x;
        }
        out[idx] = r;
    }
}

// ---------- descriptor inverse norms ----------
__global__ void norm_kernel()
{
    int img = blockIdx.x;
    for (int p = threadIdx.x; p < PP; p += blockDim.x){
        float ss = 0.f;
        const float* f = g_bufD + (size_t)img*64*PP + p;
#pragma unroll
        for (int c=0;c<64;c++){ float x = f[(size_t)c*PP]; ss += x*x; }
        g_rinv[(size_t)img*PP + p] = rsqrtf(ss);
    }
}

// ---------- bf16 descriptor buffers ----------
__global__ void fillbf_desc_kernel(int mode)
{
    const int pad = mode ? UPAD : QPAD;
    const int nrows = mode ? UROWS : QROWS;
    const int imgBase = mode ? (NQ+NS) : 0;
    __nv_bfloat16* dst = mode ? g_ubf : g_qbf;
    const size_t total = (size_t)pad*64;
    for (size_t i = (size_t)blockIdx.x*blockDim.x + threadIdx.x; i < total;
         i += (size_t)gridDim.x*blockDim.x) {
        int k = (int)(i & 63); int row = (int)(i >> 6);
        float v = 0.f;
        if (row < nrows){
            int img = imgBase + row / PP, p = row % PP;
            v = g_bufD[((size_t)img*64+k)*PP + p] * g_rinv[(size_t)img*PP + p];
        }
        dst[i] = __float2bfloat16(v);
    }
}
__global__ void fillbf_support_kernel()
{
    const size_t total = (size_t)KCLS*BCOLS*64;
    for (size_t i = (size_t)blockIdx.x*blockDim.x + threadIdx.x; i < total;
         i += (size_t)gridDim.x*blockDim.x) {
        int k = (int)(i & 63); size_t t = i >> 6;
        int col = (int)(t % BCOLS); int j = (int)(t / BCOLS);
        if (col < MSUP){
            int s = col / PP, p = col % PP;
            int img = NQ + j*SHOT + s;
            g_bankbf[i] = __float2bfloat16(
                g_bufD[((size_t)img*64+k)*PP + p] * g_rinv[(size_t)img*PP + p]);
        } else if (col >= MAUG){
            g_bankbf[i] = __float2bfloat16(0.f);
        }
    }
}
__global__ void fillbf_aug_kernel()
{
    const size_t total = (size_t)KCLS*(SELN*PP)*64;
    for (size_t i = (size_t)blockIdx.x*blockDim.x + threadIdx.x; i < total;
         i += (size_t)gridDim.x*blockDim.x) {
        int k = (int)(i & 63); size_t t = i >> 6;
        int a = (int)(t % (SELN*PP)); int j = (int)(t / (SELN*PP));
        int sel = a / PP, p = a % PP;
        int img = NQ + NS + g_selidx[j*SELN + sel];
        g_bankbf[(((size_t)j*BCOLS) + MSUP + a)*64 + k] = __float2bfloat16(
            g_bufD[((size_t)img*64+k)*PP + p] * g_rinv[(size_t)img*PP + p]);
    }
}

// ---------- unified mma.sync bf16 + register-resident top-3 ----------
__global__ void __launch_bounds__(256) mma_topk_kernel(int aSel, int cols)
{
    extern __shared__ char smc[];
    char* As = smc;
    char* Bs = smc + 18432;
    const int tid = threadIdx.x;
    const int wid = tid >> 5, lane = tid & 31;
    const int g = lane >> 2, tg = lane & 3;
    const int cls = blockIdx.y;
    const int row0 = blockIdx.x*128;
    const int ntiles = (cols + CT2 - 1)/CT2;

    uint32_t sA = (uint32_t)__cvta_generic_to_shared(As);
    uint32_t sB = (uint32_t)__cvta_generic_to_shared(Bs);

    const char* aG = (const char*)(aSel ? g_qbf : g_ubf) + (size_t)row0*128;
    for (int c = tid; c < 1024; c += 256){
        int col = c >> 3, part = c & 7;
        cpasync16(sA + (uint32_t)(col*BROW + part*16), aG + (size_t)col*128 + part*16);
    }
    const char* bG = (const char*)g_bankbf + (size_t)cls*BCOLS*128;
    for (int c = tid; c < 1024; c += 256){
        int col = c >> 3, part = c & 7;
        cpasync16(sB + (uint32_t)(col*BROW + part*16), bG + (size_t)col*128 + part*16);
    }
    CP_COMMIT(); CP_WAIT0();
    __syncthreads();

    uint32_t a[4][4];
    {
        const char* ar = As + (wid*16 + g)*BROW + tg*4;
#pragma unroll
        for (int kk=0; kk<4; kk++){
            a[kk][0] = *(const uint32_t*)(ar + kk*32);
            a[kk][1] = *(const uint32_t*)(ar + 8*BROW + kk*32);
            a[kk][2] = *(const uint32_t*)(ar + kk*32 + 16);
            a[kk][3] = *(const uint32_t*)(ar + 8*BROW + kk*32 + 16);
        }
    }

    float tA0=NEGINF, tA1=NEGINF, tA2=NEGINF;
    float tB0=NEGINF, tB1=NEGINF, tB2=NEGINF;

    for (int t = 0; t < ntiles; ++t){
        if (t+1 < ntiles){
            const char* bN = bG + (size_t)(t+1)*CT2*128;
            uint32_t bb = sB + (uint32_t)(((t+1)&1)*18432);
            for (int c = tid; c < 1024; c += 256){
                int col = c >> 3, part = c & 7;
                cpasync16(bb + (uint32_t)(col*BROW + part*16), bN + (size_t)col*128 + part*16);
            }
            CP_COMMIT();
        }
        const char* Bp = Bs + (t&1)*18432;
#pragma unroll 4
        for (int ns = 0; ns < 16; ++ns){
            const char* br = Bp + (ns*8 + g)*BROW + tg*4;
            float c0=0.f, c1=0.f, c2=0.f, c3=0.f;
#pragma unroll
            for (int kk=0; kk<4; kk++){
                uint32_t b0 = *(const uint32_t*)(br + kk*32);
                uint32_t b1 = *(const uint32_t*)(br + kk*32 + 16);
                asm volatile(
                    "mma.sync.aligned.m16n8k16.row.col.f32.bf16.bf16.f32 "
                    "{%0,%1,%2,%3}, {%4,%5,%6,%7}, {%8,%9}, {%0,%1,%2,%3};"
                    : "+f"(c0), "+f"(c1), "+f"(c2), "+f"(c3)
                    : "r"(a[kk][0]), "r"(a[kk][1]), "r"(a[kk][2]), "r"(a[kk][3]),
                      "r"(b0), "r"(b1));
            }
            const int colBase = t*CT2 + ns*8;
            if (colBase + 8 > cols){
                if (colBase + 2*tg     >= cols){ c0 = NEGINF; c2 = NEGINF; }
                if (colBase + 2*tg + 1 >= cols){ c1 = NEGINF; c3 = NEGINF; }
            }
            ins3(c0, tA0, tA1, tA2); ins3(c1, tA0, tA1, tA2);
            ins3(c2, tB0, tB1, tB2); ins3(c3, tB0, tB1, tB2);
        }
        if (t+1 < ntiles) CP_WAIT0();
        __syncthreads();
    }

#pragma unroll
    for (int off = 1; off <= 2; off <<= 1){
        float r0 = __shfl_xor_sync(0xffffffffu, tA0, off);
        float r1 = __shfl_xor_sync(0xffffffffu, tA1, off);
        float r2 = __shfl_xor_sync(0xffffffffu, tA2, off);
        ins3(r0, tA0, tA1, tA2); ins3(r1, tA0, tA1, tA2); ins3(r2, tA0, tA1, tA2);
        float s0 = __shfl_xor_sync(0xffffffffu, tB0, off);
        float s1 = __shfl_xor_sync(0xffffffffu, tB1, off);
        float s2 = __shfl_xor_sync(0xffffffffu, tB2, off);
        ins3(s0, tB0, tB1, tB2); ins3(s1, tB0, tB1, tB2); ins3(s2, tB0, tB1, tB2);
    }
    if (tg == 0){
        int row = row0 + wid*16 + g;
        g_rowsum[(size_t)cls*QPAD + row]     = tA0 + tA1 + tA2;
        g_rowsum[(size_t)cls*QPAD + row + 8] = tB0 + tB1 + tB2;
    }
}

// ---------- per-image deterministic sum ----------
__global__ void imgsum_kernel(float* __restrict__ outp, int useOut)
{
    __shared__ float s[128];
    const int img = blockIdx.x, cls = blockIdx.y;
    const int tid = threadIdx.x;
    const float* src = g_rowsum + (size_t)cls*QPAD + (size_t)img*PP;
    float v = 0.f;
    for (int i = tid; i < PP; i += 128) v += src[i];
    s[tid] = v; __syncthreads();
    for (int st=64; st>0; st>>=1){
        if (tid < st) s[tid] += s[tid+st];
        __syncthreads();
    }
    if (tid==0){
        float* dst = useOut ? outp : g_simu;
        dst[img*KCLS + cls] = s[0];
    }
}

// ---------- softmax + per-class top-10 (lowest-index ties) ----------
__global__ void select_kernel()
{
    __shared__ float pm[NU*KCLS];
    int tid = threadIdx.x;
    if (tid < NU){
        float v[KCLS]; float mx = NEGINF;
#pragma unroll
        for (int j=0;j<KCLS;j++){ v[j] = g_simu[tid*KCLS+j]; mx = fmaxf(mx, v[j]); }
        float s = 0.f;
#pragma unroll
        for (int j=0;j<KCLS;j++){ v[j] = expf(v[j]-mx); s += v[j]; }
#pragma unroll
        for (int j=0;j<KCLS;j++) pm[tid*KCLS+j] = v[j]/s;
    }
    __syncthreads();
    if (tid < KCLS){
        unsigned long long taken = 0ull;
        for (int i=0;i<SELN;i++){
            float best = NEGINF; int bi = 0;
            for (int b=0;b<NU;b++){
                if (taken & (1ull<<b)) continue;
                float val = pm[b*KCLS+tid];
                if (val > best){ best = val; bi = b; }
            }
            taken |= (1ull<<bi);
            g_selidx[tid*SELN+i] = bi;
        }
    }
}

extern "C" void kernel_launch(void* const* d_in, const int* in_sizes, int n_in,
                              void* d_out, int out_size)
{
    (void)in_sizes; (void)n_in; (void)out_size;
    // dict order: input1..3, w1, w2, w3, w4, g1, b1, g2, b2, g3, b3, g4, b4
    const float* in1 = (const float*)d_in[0];
    const float* in2 = (const float*)d_in[1];
    const float* in3 = (const float*)d_in[2];
    const float* w1  = (const float*)d_in[3];
    const float* w2  = (const float*)d_in[4];
    const float* w3  = (const float*)d_in[5];
    const float* w4  = (const float*)d_in[6];
    const float* gg1 = (const float*)d_in[7];
    const float* bb1 = (const float*)d_in[8];
    const float* gg2 = (const float*)d_in[9];
    const float* bb2 = (const float*)d_in[10];
    const float* gg3 = (const float*)d_in[11];
    const float* bb3 = (const float*)d_in[12];
    const float* gg4 = (const float*)d_in[13];
    const float* bb4 = (const float*)d_in[14];
    float* out = (float*)d_out;

    const int SM3 = (1536 + 8*(50*18))*4;    // conv64<6>: 34944B  (TH=48)
    const int SM2 = (1536 + 8*(26*18))*4;    // conv64<3>: 21120B  (TH=24)
    const int SMM = 3*18432;                 // 55296B
    cudaFuncSetAttribute(conv64_kernel<6>, cudaFuncAttributeMaxDynamicSharedMemorySize, SM3);
    cudaFuncSetAttribute(conv64_kernel<3>, cudaFuncAttributeMaxDynamicSharedMemorySize, SM2);
    cudaFuncSetAttribute(mma_topk_kernel,  cudaFuncAttributeMaxDynamicSharedMemorySize, SMM);

    dim3 blk(16,16);
    conv1_kernel<<<dim3(6,6,NALL), blk>>>(in1, in2, in3, w1);
    bn_stats_kernel<<<dim3(64,3), 256>>>(0, H1*H1);
    bn_pool_kernel<<<2048, 256>>>(0, 1, gg1, bb1, H1, H1, 1);
    conv64_kernel<6><<<dim3(3,1,NALL*4), blk, SM3>>>(1, 2, w2, H2, H2);   // 42x42, TH=48
    bn_stats_kernel<<<dim3(64,3), 256>>>(2, H2*H2);
    bn_pool_kernel<<<2048, 256>>>(2, 3, gg2, bb2, H2, H2, 1);
    conv64_kernel<3><<<dim3(2,1,NALL*4), blk, SM2>>>(3, 4, w3, H3, H3);   // 21x21, TH=24
    bn_stats_kernel<<<dim3(64,3), 256>>>(4, H3*H3);
    bn_pool_kernel<<<2048, 256>>>(4, 3, gg3, bb3, H3, H3, 0);
    conv64_kernel<3><<<dim3(2,1,NALL*4), blk, SM2>>>(3, 4, w4, H3, H3);
    bn_stats_kernel<<<dim3(64,3), 256>>>(4, H3*H3);
    bn_pool_kernel<<<2048, 256>>>(4, 3, gg4, bb4, H3, H3, 0);   // final feats in D

    norm_kernel<<<NALL, 256>>>();
    fillbf_desc_kernel<<<2048, 256>>>(0);   // queries
    fillbf_desc_kernel<<<2048, 256>>>(1);   // unlabeled
    fillbf_support_kernel<<<2048, 256>>>();

    // stage 1: unlabeled rows vs support banks (bf16 mma, cols = MSUP)
    mma_topk_kernel<<<dim3(UPAD/128, KCLS), 256, SMM>>>(0, MSUP);
    imgsum_kernel<<<dim3(NU, KCLS), 128>>>(nullptr, 0);
    select_kernel<<<1, 64>>>();
    fillbf_aug_kernel<<<2048, 256>>>();

    // stage 2: query rows vs augmented banks (bf16 mma, cols = MAUG)
    mma_topk_kernel<<<dim3(QPAD/128, KCLS), 256, SMM>>>(1, MAUG);
    imgsum_kernel<<<dim3(NQ, KCLS), 128>>>(out, 1);
}

// round 16
// speedup vs baseline: 5.8953x; 1.3401x over previous
#include <cuda_runtime.h>
#include <cuda_bf16.h>
#include <math.h>
#include <stdint.h>

#define NQ 75
#define NS 25
#define NU 64
#define NALL 164
#define H1 84
#define H2 42
#define H3 21
#define PP 441
#define KCLS 5
#define SHOT 5
#define MSUP (SHOT*PP)          // 2205
#define MAUG (MSUP + 10*PP)     // 6615
#define BCOLS 6656              // 52*128
#define QROWS (NQ*PP)           // 33075
#define QPAD  33152             // 259*128
#define UROWS (NU*PP)           // 28224
#define UPAD  28288             // 221*128
#define SELN 10
#define NEGINF -3.4e38f
#define CT2 128
#define BROW 144

__device__ float g_bufA[(size_t)NALL*64*H1*H1];
__device__ float g_bufC[(size_t)NALL*64*H2*H2];
__device__ float g_bufD[(size_t)NALL*64*H3*H3];
__device__ float g_bufE[(size_t)NALL*64*H3*H3];
__device__ float g_bufB[(size_t)NALL*64*H2*H2];
__device__ float g_rinv[(size_t)NALL*PP];
__device__ __nv_bfloat16 g_qbf[(size_t)QPAD*64];
__device__ __nv_bfloat16 g_ubf[(size_t)UPAD*64];
__device__ __nv_bfloat16 g_bankbf[(size_t)KCLS*BCOLS*64];
__device__ float g_rowsum[(size_t)KCLS*QPAD];
__device__ float g_stats[3*64*2];
__device__ float g_simu[NU*KCLS];
__device__ int   g_selidx[KCLS*SELN];

__device__ __forceinline__ float* bufPtr(int s){
    switch(s){
        case 0: return g_bufA; case 1: return g_bufB; case 2: return g_bufC;
        case 3: return g_bufD; default: return g_bufE;
    }
}
__device__ __forceinline__ int groupOf(int n){ return (n < NQ) ? 0 : ((n < NQ+NS) ? 1 : 2); }

__device__ __forceinline__ void cpasync16(uint32_t dst, const void* src){
    asm volatile("cp.async.cg.shared.global [%0], [%1], 16;\n" :: "r"(dst), "l"(src));
}
#define CP_COMMIT() asm volatile("cp.async.commit_group;\n" ::: "memory")
#define CP_WAIT0()  asm volatile("cp.async.wait_group 0;\n" ::: "memory")

__device__ __forceinline__ void ins3(float v, float& t0, float& t1, float& t2){
    if (v > t2){
        if (v > t0){ t2 = t1; t1 = t0; t0 = v; }
        else if (v > t1){ t2 = t1; t1 = v; }
        else t2 = v;
    }
}

// ---------- conv1: 3->64, 84x84 SAME ; weights padded to 28, float4 reads ----------
__global__ void conv1_kernel(const float* __restrict__ in1, const float* __restrict__ in2,
                             const float* __restrict__ in3, const float* __restrict__ w)
{
    __shared__ float sW[64*28];
    __shared__ float sIn[3*18*18];
    const int n = blockIdx.z;
    const int gx0 = blockIdx.x*16, gy0 = blockIdx.y*16;
    const int tx = threadIdx.x, ty = threadIdx.y;
    const int tid = ty*16 + tx;
    const float* img = (n < NQ)    ? (in1 + (size_t)n*3*H1*H1)
                     : (n < NQ+NS) ? (in2 + (size_t)(n-NQ)*3*H1*H1)
                                   : (in3 + (size_t)(n-NQ-NS)*3*H1*H1);
    for (int i = tid; i < 64*27; i += 256){
        int oc = i / 27, j = i % 27;
        sW[oc*28 + j] = w[i];
    }
    for (int i = tid; i < 3*18*18; i += 256) {
        int c = i / 324, rem = i % 324, r = rem/18, cc = rem%18;
        int gy = gy0 - 1 + r, gx = gx0 - 1 + cc;
        sIn[i] = (gy>=0 && gy<H1 && gx>=0 && gx<H1) ? img[((size_t)c*H1+gy)*H1+gx] : 0.f;
    }
    __syncthreads();
    int ox = gx0+tx, oy = gy0+ty;
    if (ox >= H1 || oy >= H1) return;
    float v[27];
#pragma unroll
    for (int c=0;c<3;c++)
#pragma unroll
      for (int dy=0;dy<3;dy++)
#pragma unroll
        for (int dx=0;dx<3;dx++)
          v[c*9+dy*3+dx] = sIn[c*324 + (ty+dy)*18 + (tx+dx)];
#pragma unroll 2
    for (int oc=0; oc<64; oc++){
        const float* wp = sW + oc*28;
        float4 q0 = *(const float4*)(wp);
        float4 q1 = *(const float4*)(wp+4);
        float4 q2 = *(const float4*)(wp+8);
        float4 q3 = *(const float4*)(wp+12);
        float4 q4 = *(const float4*)(wp+16);
        float4 q5 = *(const float4*)(wp+20);
        float  w24 = wp[24], w25 = wp[25], w26 = wp[26];
        float acc = 0.f;
        acc += q0.x*v[0];  acc += q0.y*v[1];  acc += q0.z*v[2];  acc += q0.w*v[3];
        acc += q1.x*v[4];  acc += q1.y*v[5];  acc += q1.z*v[6];  acc += q1.w*v[7];
        acc += q2.x*v[8];  acc += q2.y*v[9];  acc += q2.z*v[10]; acc += q2.w*v[11];
        acc += q3.x*v[12]; acc += q3.y*v[13]; acc += q3.z*v[14]; acc += q3.w*v[15];
        acc += q4.x*v[16]; acc += q4.y*v[17]; acc += q4.z*v[18]; acc += q4.w*v[19];
        acc += q5.x*v[20]; acc += q5.y*v[21]; acc += q5.z*v[22]; acc += q5.w*v[23];
        acc += w24*v[24];  acc += w25*v[25];  acc += w26*v[26];
        g_bufA[(((size_t)n*64+oc)*H1+oy)*H1+ox] = acc;
    }
}

// ---------- conv 64->64 3x3 SAME (16-wide tiles, conv2 @42) ----------
template<int RPT>
__global__ void conv64_kernel(int inSel, int outSel, const float* __restrict__ wt, int H, int W)
{
    extern __shared__ float sm[];
    float* sW  = sm;              // [16 oc][8 ic][12] = 1536
    float* sIn = sm + 1536;
    constexpr int TH   = 8*RPT;
    constexpr int HALO = (TH+2)*18;
    const int z   = blockIdx.z;
    const int n   = z >> 2;
    const int ocg = z & 3;
    const int gx0 = blockIdx.x*16;
    const int gy0 = blockIdx.y*TH;
    const int tx = threadIdx.x, ty = threadIdx.y;
    const int tid = ty*16 + tx;
    const int half = ty >> 3;
    const int tyr  = ty & 7;
    const int oyb = gy0 + tyr*RPT;
    const int ox  = gx0 + tx;
    const bool anyValid = (ox < W) && (oyb < H);
    const float* inN  = bufPtr(inSel)  + (size_t)n*64*H*W;
    float*       outN = bufPtr(outSel) + (size_t)n*64*H*W;

    float acc[8][RPT];
#pragma unroll
    for (int o=0;o<8;o++)
#pragma unroll
      for (int r=0;r<RPT;r++) acc[o][r]=0.f;

    for (int cc = 0; cc < 8; ++cc) {
        __syncthreads();
        for (int i = tid; i < 1152; i += 256) {
            int o = i / 72, rem = i % 72;
            int ic = rem / 9, j = rem % 9;
            sW[o*96 + ic*12 + j] = wt[(size_t)(ocg*16+o)*576 + cc*72 + rem];
        }
        for (int i = tid; i < 8*HALO; i += 256) {
            int c = i / HALO, rem = i % HALO, r = rem/18, col = rem%18;
            int gy = gy0-1+r, gx = gx0-1+col;
            float v = 0.f;
            if (gy>=0 && gy<H && gx>=0 && gx<W)
                v = inN[((size_t)(cc*8+c)*H+gy)*W+gx];
            sIn[i] = v;
        }
        __syncthreads();
        if (anyValid) {
            for (int ic=0; ic<8; ++ic) {
                float v[RPT+2][3];
                const float* sp = sIn + ic*HALO + (tyr*RPT)*18 + tx;
#pragma unroll
                for (int r=0;r<RPT+2;r++)
#pragma unroll
                  for (int d=0;d<3;d++) v[r][d] = sp[r*18+d];
                const float* wpB = sW + (half*8)*96 + ic*12;
#pragma unroll
                for (int o=0;o<8;o++){
                    const float* wo = wpB + o*96;
                    float4 qa = *(const float4*)(wo);
                    float4 qb = *(const float4*)(wo+4);
                    float  w8 = wo[8];
                    float w0=qa.x,w1=qa.y,w2=qa.z,w3=qa.w;
                    float w4=qb.x,w5=qb.y,w6=qb.z,w7=qb.w;
#pragma unroll
                    for (int r=0;r<RPT;r++){
                        float a = acc[o][r];
                        a += w0*v[r  ][0]; a += w1*v[r  ][1]; a += w2*v[r  ][2];
                        a += w3*v[r+1][0]; a += w4*v[r+1][1]; a += w5*v[r+1][2];
                        a += w6*v[r+2][0]; a += w7*v[r+2][1]; a += w8*v[r+2][2];
                        acc[o][r] = a;
                    }
                }
            }
        }
    }
    if (anyValid) {
#pragma unroll
        for (int o=0;o<8;o++){
            int oc = ocg*16 + half*8 + o;
#pragma unroll
            for (int r=0;r<RPT;r++){
                int oy = oyb + r;
                if (oy < H) outN[((size_t)oc*H+oy)*W+ox] = acc[o][r];
            }
        }
    }
}

// ---------- conv 64->64 3x3 SAME specialized for 21x21 (conv3/conv4) ----------
__global__ void conv64_21_kernel(int inSel, int outSel, const float* __restrict__ wt)
{
    extern __shared__ float sm[];
    float* sW  = sm;              // [16 oc][8 ic][12] = 1536
    float* sIn = sm + 1536;       // [8 ic][26*23]
    const int HALO = 26*23;       // 598
    const int z = blockIdx.x;
    const int n = z >> 2, ocg = z & 3;
    const int tx = threadIdx.x;   // 0..20
    const int ty = threadIdx.y;   // 0..11
    const int tid = ty*21 + tx;   // 0..251
    const int half = ty / 6;
    const int tyr  = ty % 6;
    const int oyb = tyr*4;
    const float* inN  = bufPtr(inSel)  + (size_t)n*64*H3*H3;
    float*       outN = bufPtr(outSel) + (size_t)n*64*H3*H3;

    float acc[8][4];
#pragma unroll
    for (int o=0;o<8;o++)
#pragma unroll
      for (int r=0;r<4;r++) acc[o][r]=0.f;

    for (int cc = 0; cc < 8; ++cc) {
        __syncthreads();
        for (int i = tid; i < 1152; i += 252) {
            int o = i / 72, rem = i % 72;
            int ic = rem / 9, j = rem % 9;
            sW[o*96 + ic*12 + j] = wt[(size_t)(ocg*16+o)*576 + cc*72 + rem];
        }
        for (int i = tid; i < 8*HALO; i += 252) {
            int c = i / HALO, rem = i % HALO, r = rem/23, col = rem%23;
            int gy = r-1, gx = col-1;
            float v = 0.f;
            if (gy>=0 && gy<H3 && gx>=0 && gx<H3)
                v = inN[((size_t)(cc*8+c)*H3+gy)*H3+gx];
            sIn[i] = v;
        }
        __syncthreads();
        for (int ic=0; ic<8; ++ic) {
            float v[6][3];
            const float* sp = sIn + ic*HALO + oyb*23 + tx;
#pragma unroll
            for (int r=0;r<6;r++)
#pragma unroll
              for (int d=0;d<3;d++) v[r][d] = sp[r*23+d];
            const float* wpB = sW + (half*8)*96 + ic*12;
#pragma unroll
            for (int o=0;o<8;o++){
                const float* wo = wpB + o*96;
                float4 qa = *(const float4*)(wo);
                float4 qb = *(const float4*)(wo+4);
                float  w8 = wo[8];
                float w0=qa.x,w1=qa.y,w2=qa.z,w3=qa.w;
                float w4=qb.x,w5=qb.y,w6=qb.z,w7=qb.w;
#pragma unroll
                for (int r=0;r<4;r++){
                    float a = acc[o][r];
                    a += w0*v[r  ][0]; a += w1*v[r  ][1]; a += w2*v[r  ][2];
                    a += w3*v[r+1][0]; a += w4*v[r+1][1]; a += w5*v[r+1][2];
                    a += w6*v[r+2][0]; a += w7*v[r+2][1]; a += w8*v[r+2][2];
                    acc[o][r] = a;
                }
            }
        }
    }
#pragma unroll
    for (int o=0;o<8;o++){
        int oc = ocg*16 + half*8 + o;
#pragma unroll
        for (int r=0;r<4;r++){
            int oy = oyb + r;
            if (oy < H3) outN[((size_t)oc*H3+oy)*H3+tx] = acc[o][r];
        }
    }
}

// ---------- BN stats v2b: fp32 per-plane partials; float4 only when aligned ----------
__global__ void bn_stats_kernel(int sel, int HW)
{
    __shared__ double ssum[256], ssum2[256];
    const int ch = blockIdx.x, g = blockIdx.y;
    const int n0 = (g==0)?0:((g==1)?NQ:(NQ+NS));
    const int n1 = (g==0)?NQ:((g==1)?(NQ+NS):NALL);
    const int tid = threadIdx.x;
    const float* buf = bufPtr(sel);
    const bool vec = (HW & 3) == 0;     // plane bases stay 16B-aligned only then
    double ds=0.0, ds2=0.0;
    for (int n=n0; n<n1; ++n) {
        const float* p = buf + ((size_t)n*64+ch)*HW;
        float s=0.f, s2=0.f;
        if (vec){
            const float4* p4 = (const float4*)p;
            const int HW4 = HW >> 2;
            for (int i=tid;i<HW4;i+=256){
                float4 x = p4[i];
                s  += x.x + x.y + x.z + x.w;
                s2 += x.x*x.x + x.y*x.y + x.z*x.z + x.w*x.w;
            }
        } else {
            for (int i=tid;i<HW;i+=256){
                float x = p[i]; s += x; s2 += x*x;
            }
        }
        ds += (double)s; ds2 += (double)s2;
    }
    ssum[tid]=ds; ssum2[tid]=ds2; __syncthreads();
    for (int st=128; st>0; st>>=1){
        if (tid<st){ ssum[tid]+=ssum[tid+st]; ssum2[tid]+=ssum2[tid+st]; }
        __syncthreads();
    }
    if (tid==0){
        double cnt = (double)(n1-n0)*HW;
        double mean = ssum[0]/cnt;
        double var  = ssum2[0]/cnt - mean*mean;
        g_stats[(g*64+ch)*2+0] = (float)mean;
        g_stats[(g*64+ch)*2+1] = (float)(1.0/sqrt(var + 1e-5));
    }
}

// ---------- BN + LeakyReLU (+pool) ----------
__global__ void bn_pool_kernel(int inSel, int outSel, const float* __restrict__ gamma,
                               const float* __restrict__ beta, int H, int W, int doPool)
{
    const int oH = doPool ? H/2 : H, oW = doPool ? W/2 : W;
    const size_t total = (size_t)NALL*64*oH*oW;
    const float* in = bufPtr(inSel);
    float* out = bufPtr(outSel);
    for (size_t idx = (size_t)blockIdx.x*blockDim.x + threadIdx.x; idx < total;
         idx += (size_t)gridDim.x*blockDim.x) {
        int ox = (int)(idx % oW); size_t t = idx / oW;
        int oy = (int)(t % oH);   t /= oH;
        int c  = (int)(t % 64);   int n = (int)(t / 64);
        int g = groupOf(n);
        float mean = g_stats[(g*64+c)*2+0], rsig = g_stats[(g*64+c)*2+1];
        float sc = gamma[c]*rsig;
        float sh = beta[c] - mean*sc;
        const float* p = in + ((size_t)n*64+c)*H*W;
        float r;
        if (doPool){
            float x0 = p[(size_t)(2*oy)*W + 2*ox  ]*sc+sh;
            float x1 = p[(size_t)(2*oy)*W + 2*ox+1]*sc+sh;
            float x2 = p[(size_t)(2*oy+1)*W + 2*ox  ]*sc+sh;
            float x3 = p[(size_t)(2*oy+1)*W + 2*ox+1]*sc+sh;
            x0 = x0>=0.f?x0:0.2f*x0; x1 = x1>=0.f?x1:0.2f*x1;
            x2 = x2>=0.f?x2:0.2f*x2; x3 = x3>=0.f?x3:0.2f*x3;
            r = fmaxf(fmaxf(x0,x1), fmaxf(x2,x3));
        } else {
            float x = p[(size_t)oy*W+ox]*sc+sh;
            r = x>=0.f?x:0.2f*x;
        }
        out[idx] = r;
    }
}

// ---------- descriptor inverse norms ----------
__global__ void norm_kernel()
{
    int img = blockIdx.x;
    for (int p = threadIdx.x; p < PP; p += blockDim.x){
        float ss = 0.f;
        const float* f = g_bufD + (size_t)img*64*PP + p;
#pragma unroll
        for (int c=0;c<64;c++){ float x = f[(size_t)c*PP]; ss += x*x; }
        g_rinv[(size_t)img*PP + p] = rsqrtf(ss);
    }
}

// ---------- bf16 descriptor buffers ----------
__global__ void fillbf_desc_kernel(int mode)
{
    const int pad = mode ? UPAD : QPAD;
    const int nrows = mode ? UROWS : QROWS;
    const int imgBase = mode ? (NQ+NS) : 0;
    __nv_bfloat16* dst = mode ? g_ubf : g_qbf;
    const size_t total = (size_t)pad*64;
    for (size_t i = (size_t)blockIdx.x*blockDim.x + threadIdx.x; i < total;
         i += (size_t)gridDim.x*blockDim.x) {
        int k = (int)(i & 63); int row = (int)(i >> 6);
        float v = 0.f;
        if (row < nrows){
            int img = imgBase + row / PP, p = row % PP;
            v = g_bufD[((size_t)img*64+k)*PP + p] * g_rinv[(size_t)img*PP + p];
        }
        dst[i] = __float2bfloat16(v);
    }
}
__global__ void fillbf_support_kernel()
{
    const size_t total = (size_t)KCLS*BCOLS*64;
    for (size_t i = (size_t)blockIdx.x*blockDim.x + threadIdx.x; i < total;
         i += (size_t)gridDim.x*blockDim.x) {
        int k = (int)(i & 63); size_t t = i >> 6;
        int col = (int)(t % BCOLS); int j = (int)(t / BCOLS);
        if (col < MSUP){
            int s = col / PP, p = col % PP;
            int img = NQ + j*SHOT + s;
            g_bankbf[i] = __float2bfloat16(
                g_bufD[((size_t)img*64+k)*PP + p] * g_rinv[(size_t)img*PP + p]);
        } else if (col >= MAUG){
            g_bankbf[i] = __float2bfloat16(0.f);
        }
    }
}
__global__ void fillbf_aug_kernel()
{
    const size_t total = (size_t)KCLS*(SELN*PP)*64;
    for (size_t i = (size_t)blockIdx.x*blockDim.x + threadIdx.x; i < total;
         i += (size_t)gridDim.x*blockDim.x) {
        int k = (int)(i & 63); size_t t = i >> 6;
        int a = (int)(t % (SELN*PP)); int j = (int)(t / (SELN*PP));
        int sel = a / PP, p = a % PP;
        int img = NQ + NS + g_selidx[j*SELN + sel];
        g_bankbf[(((size_t)j*BCOLS) + MSUP + a)*64 + k] = __float2bfloat16(
            g_bufD[((size_t)img*64+k)*PP + p] * g_rinv[(size_t)img*PP + p]);
    }
}

// ---------- unified mma.sync bf16 + register-resident top-3 ----------
__global__ void __launch_bounds__(256) mma_topk_kernel(int aSel, int cols)
{
    extern __shared__ char smc[];
    char* As = smc;
    char* Bs = smc + 18432;
    const int tid = threadIdx.x;
    const int wid = tid >> 5, lane = tid & 31;
    const int g = lane >> 2, tg = lane & 3;
    const int cls = blockIdx.y;
    const int row0 = blockIdx.x*128;
    const int ntiles = (cols + CT2 - 1)/CT2;

    uint32_t sA = (uint32_t)__cvta_generic_to_shared(As);
    uint32_t sB = (uint32_t)__cvta_generic_to_shared(Bs);

    const char* aG = (const char*)(aSel ? g_qbf : g_ubf) + (size_t)row0*128;
    for (int c = tid; c < 1024; c += 256){
        int col = c >> 3, part = c & 7;
        cpasync16(sA + (uint32_t)(col*BROW + part*16), aG + (size_t)col*128 + part*16);
    }
    const char* bG = (const char*)g_bankbf + (size_t)cls*BCOLS*128;
    for (int c = tid; c < 1024; c += 256){
        int col = c >> 3, part = c & 7;
        cpasync16(sB + (uint32_t)(col*BROW + part*16), bG + (size_t)col*128 + part*16);
    }
    CP_COMMIT(); CP_WAIT0();
    __syncthreads();

    uint32_t a[4][4];
    {
        const char* ar = As + (wid*16 + g)*BROW + tg*4;
#pragma unroll
        for (int kk=0; kk<4; kk++){
            a[kk][0] = *(const uint32_t*)(ar + kk*32);
            a[kk][1] = *(const uint32_t*)(ar + 8*BROW + kk*32);
            a[kk][2] = *(const uint32_t*)(ar + kk*32 + 16);
            a[kk][3] = *(const uint32_t*)(ar + 8*BROW + kk*32 + 16);
        }
    }

    float tA0=NEGINF, tA1=NEGINF, tA2=NEGINF;
    float tB0=NEGINF, tB1=NEGINF, tB2=NEGINF;

    for (int t = 0; t < ntiles; ++t){
        if (t+1 < ntiles){
            const char* bN = bG + (size_t)(t+1)*CT2*128;
            uint32_t bb = sB + (uint32_t)(((t+1)&1)*18432);
            for (int c = tid; c < 1024; c += 256){
                int col = c >> 3, part = c & 7;
                cpasync16(bb + (uint32_t)(col*BROW + part*16), bN + (size_t)col*128 + part*16);
            }
            CP_COMMIT();
        }
        const char* Bp = Bs + (t&1)*18432;
#pragma unroll 4
        for (int ns = 0; ns < 16; ++ns){
            const char* br = Bp + (ns*8 + g)*BROW + tg*4;
            float c0=0.f, c1=0.f, c2=0.f, c3=0.f;
#pragma unroll
            for (int kk=0; kk<4; kk++){
                uint32_t b0 = *(const uint32_t*)(br + kk*32);
                uint32_t b1 = *(const uint32_t*)(br + kk*32 + 16);
                asm volatile(
                    "mma.sync.aligned.m16n8k16.row.col.f32.bf16.bf16.f32 "
                    "{%0,%1,%2,%3}, {%4,%5,%6,%7}, {%8,%9}, {%0,%1,%2,%3};"
                    : "+f"(c0), "+f"(c1), "+f"(c2), "+f"(c3)
                    : "r"(a[kk][0]), "r"(a[kk][1]), "r"(a[kk][2]), "r"(a[kk][3]),
                      "r"(b0), "r"(b1));
            }
            const int colBase = t*CT2 + ns*8;
            if (colBase + 8 > cols){
                if (colBase + 2*tg     >= cols){ c0 = NEGINF; c2 = NEGINF; }
                if (colBase + 2*tg + 1 >= cols){ c1 = NEGINF; c3 = NEGINF; }
            }
            ins3(c0, tA0, tA1, tA2); ins3(c1, tA0, tA1, tA2);
            ins3(c2, tB0, tB1, tB2); ins3(c3, tB0, tB1, tB2);
        }
        if (t+1 < ntiles) CP_WAIT0();
        __syncthreads();
    }

#pragma unroll
    for (int off = 1; off <= 2; off <<= 1){
        float r0 = __shfl_xor_sync(0xffffffffu, tA0, off);
        float r1 = __shfl_xor_sync(0xffffffffu, tA1, off);
        float r2 = __shfl_xor_sync(0xffffffffu, tA2, off);
        ins3(r0, tA0, tA1, tA2); ins3(r1, tA0, tA1, tA2); ins3(r2, tA0, tA1, tA2);
        float s0 = __shfl_xor_sync(0xffffffffu, tB0, off);
        float s1 = __shfl_xor_sync(0xffffffffu, tB1, off);
        float s2 = __shfl_xor_sync(0xffffffffu, tB2, off);
        ins3(s0, tB0, tB1, tB2); ins3(s1, tB0, tB1, tB2); ins3(s2, tB0, tB1, tB2);
    }
    if (tg == 0){
        int row = row0 + wid*16 + g;
        g_rowsum[(size_t)cls*QPAD + row]     = tA0 + tA1 + tA2;
        g_rowsum[(size_t)cls*QPAD + row + 8] = tB0 + tB1 + tB2;
    }
}

// ---------- per-image deterministic sum ----------
__global__ void imgsum_kernel(float* __restrict__ outp, int useOut)
{
    __shared__ float s[128];
    const int img = blockIdx.x, cls = blockIdx.y;
    const int tid = threadIdx.x;
    const float* src = g_rowsum + (size_t)cls*QPAD + (size_t)img*PP;
    float v = 0.f;
    for (int i = tid; i < PP; i += 128) v += src[i];
    s[tid] = v; __syncthreads();
    for (int st=64; st>0; st>>=1){
        if (tid < st) s[tid] += s[tid+st];
        __syncthreads();
    }
    if (tid==0){
        float* dst = useOut ? outp : g_simu;
        dst[img*KCLS + cls] = s[0];
    }
}

// ---------- softmax + per-class top-10 (lowest-index ties) ----------
__global__ void select_kernel()
{
    __shared__ float pm[NU*KCLS];
    int tid = threadIdx.x;
    if (tid < NU){
        float v[KCLS]; float mx = NEGINF;
#pragma unroll
        for (int j=0;j<KCLS;j++){ v[j] = g_simu[tid*KCLS+j]; mx = fmaxf(mx, v[j]); }
        float s = 0.f;
#pragma unroll
        for (int j=0;j<KCLS;j++){ v[j] = expf(v[j]-mx); s += v[j]; }
#pragma unroll
        for (int j=0;j<KCLS;j++) pm[tid*KCLS+j] = v[j]/s;
    }
    __syncthreads();
    if (tid < KCLS){
        unsigned long long taken = 0ull;
        for (int i=0;i<SELN;i++){
            float best = NEGINF; int bi = 0;
            for (int b=0;b<NU;b++){
                if (taken & (1ull<<b)) continue;
                float val = pm[b*KCLS+tid];
                if (val > best){ best = val; bi = b; }
            }
            taken |= (1ull<<bi);
            g_selidx[tid*SELN+i] = bi;
        }
    }
}

extern "C" void kernel_launch(void* const* d_in, const int* in_sizes, int n_in,
                              void* d_out, int out_size)
{
    (void)in_sizes; (void)n_in; (void)out_size;
    // dict order: input1..3, w1, w2, w3, w4, g1, b1, g2, b2, g3, b3, g4, b4
    const float* in1 = (const float*)d_in[0];
    const float* in2 = (const float*)d_in[1];
    const float* in3 = (const float*)d_in[2];
    const float* w1  = (const float*)d_in[3];
    const float* w2  = (const float*)d_in[4];
    const float* w3  = (const float*)d_in[5];
    const float* w4  = (const float*)d_in[6];
    const float* gg1 = (const float*)d_in[7];
    const float* bb1 = (const float*)d_in[8];
    const float* gg2 = (const float*)d_in[9];
    const float* bb2 = (const float*)d_in[10];
    const float* gg3 = (const float*)d_in[11];
    const float* bb3 = (const float*)d_in[12];
    const float* gg4 = (const float*)d_in[13];
    const float* bb4 = (const float*)d_in[14];
    float* out = (float*)d_out;

    const int SM3  = (1536 + 8*(50*18))*4;   // conv64<6>: 34944B (TH=48)
    const int SM21 = (1536 + 8*598)*4;       // conv64_21: 25280B
    const int SMM  = 3*18432;                // 55296B
    cudaFuncSetAttribute(conv64_kernel<6>,  cudaFuncAttributeMaxDynamicSharedMemorySize, SM3);
    cudaFuncSetAttribute(conv64_21_kernel,  cudaFuncAttributeMaxDynamicSharedMemorySize, SM21);
    cudaFuncSetAttribute(mma_topk_kernel,   cudaFuncAttributeMaxDynamicSharedMemorySize, SMM);

    dim3 blk(16,16);
    dim3 blk21(21,12);
    conv1_kernel<<<dim3(6,6,NALL), blk>>>(in1, in2, in3, w1);
    bn_stats_kernel<<<dim3(64,3), 256>>>(0, H1*H1);
    bn_pool_kernel<<<2048, 256>>>(0, 1, gg1, bb1, H1, H1, 1);
    conv64_kernel<6><<<dim3(3,1,NALL*4), blk, SM3>>>(1, 2, w2, H2, H2);
    bn_stats_kernel<<<dim3(64,3), 256>>>(2, H2*H2);
    bn_pool_kernel<<<2048, 256>>>(2, 3, gg2, bb2, H2, H2, 1);
    conv64_21_kernel<<<NALL*4, blk21, SM21>>>(3, 4, w3);
    bn_stats_kernel<<<dim3(64,3), 256>>>(4, H3*H3);
    bn_pool_kernel<<<2048, 256>>>(4, 3, gg3, bb3, H3, H3, 0);
    conv64_21_kernel<<<NALL*4, blk21, SM21>>>(3, 4, w4);
    bn_stats_kernel<<<dim3(64,3), 256>>>(4, H3*H3);
    bn_pool_kernel<<<2048, 256>>>(4, 3, gg4, bb4, H3, H3, 0);   // final feats in D

    norm_kernel<<<NALL, 256>>>();
    fillbf_desc_kernel<<<2048, 256>>>(0);
    fillbf_desc_kernel<<<2048, 256>>>(1);
    fillbf_support_kernel<<<2048, 256>>>();

    mma_topk_kernel<<<dim3(UPAD/128, KCLS), 256, SMM>>>(0, MSUP);
    imgsum_kernel<<<dim3(NU, KCLS), 128>>>(nullptr, 0);
    select_kernel<<<1, 64>>>();
    fillbf_aug_kernel<<<2048, 256>>>();

    mma_topk_kernel<<<dim3(QPAD/128, KCLS), 256, SMM>>>(1, MAUG);
    imgsum_kernel<<<dim3(NQ, KCLS), 128>>>(out, 1);
}